// round 5
// baseline (speedup 1.0000x reference)
#include <cuda_runtime.h>
#include <math_constants.h>

#define B_SZ 2
#define L_SEQ 2048
#define D_MODEL 1024
#define NH 16
#define DK 64
#define M_TOT (B_SZ * L_SEQ)
#define NEG (-1e10f)

// Scratch (device globals — no cudaMalloc allowed). All tf32 bit patterns.
__device__ unsigned g_Qh[B_SZ * NH * L_SEQ * DK];   // [b][h][i][d] scaled tf32
__device__ unsigned g_Kh[B_SZ * NH * L_SEQ * DK];   // [b][h][o][d] tf32
__device__ unsigned g_Vt[B_SZ * NH * DK * L_SEQ];   // [b][h][d][o] tf32
__device__ unsigned g_Mha[M_TOT * D_MODEL];         // [b*L+i][d*16+h] tf32
__device__ unsigned g_mbits[B_SZ * L_SEQ * L_SEQ / 32];
__device__ unsigned g_Qtf[M_TOT * D_MODEL];         // inputs converted to tf32
__device__ unsigned g_Ktf[M_TOT * D_MODEL];
__device__ unsigned g_Vtf[M_TOT * D_MODEL];
__device__ unsigned g_Wtf[4][D_MODEL * D_MODEL];

__device__ __forceinline__ unsigned f2tf32(float v) {
  unsigned r;
  asm("cvt.rna.tf32.f32 %0, %1;" : "=r"(r) : "f"(v));
  return r;
}
__device__ __forceinline__ void cpa16(unsigned d, const void* s) {
  asm volatile("cp.async.cg.shared.global [%0], [%1], 16;" :: "r"(d), "l"(s));
}
__device__ __forceinline__ void cpcommit() {
  asm volatile("cp.async.commit_group;");
}
__device__ __forceinline__ void cpwait0() {
  asm volatile("cp.async.wait_group 0;");
}

// ---------------------------------------------------------------------------
// fp32 -> tf32 bit conversion, vectorized
// ---------------------------------------------------------------------------
__global__ __launch_bounds__(256) void cvt_tf32_kernel(
    const float4* __restrict__ in, uint4* __restrict__ out) {
  int i = blockIdx.x * 256 + threadIdx.x;
  float4 v = in[i];
  out[i] = make_uint4(f2tf32(v.x), f2tf32(v.y), f2tf32(v.z), f2tf32(v.w));
}

// ---------------------------------------------------------------------------
// Mask: 4-byte bool elements -> bit-packed (bit set == masked)
// ---------------------------------------------------------------------------
__global__ __launch_bounds__(256) void mask_bits_kernel(
    const int* __restrict__ m4, unsigned* __restrict__ out) {
  int w = blockIdx.x * 256 + threadIdx.x;
  const int4* p = (const int4*)m4 + (size_t)w * 8;
  unsigned bits = 0;
#pragma unroll
  for (int j = 0; j < 8; j++) {
    int4 v = p[j];
    bits |= (unsigned)(v.x != 0) << (4 * j + 0);
    bits |= (unsigned)(v.y != 0) << (4 * j + 1);
    bits |= (unsigned)(v.z != 0) << (4 * j + 2);
    bits |= (unsigned)(v.w != 0) << (4 * j + 3);
  }
  out[w] = bits;
}

// ---------------------------------------------------------------------------
// TF32 GEMM, cp.async double-buffered. C[m,n] = sum_k A[m,k] * W[n,k].
// A, W are tf32 bit arrays. 128x128 CTA tile, KC=32, 8 warps x (64x32).
// MODE 0: fp32 C[m*1024+n]
// MODE 1: Q -> tf32 scaled 0.125, [b,h,i,d]
// MODE 2: K -> tf32, [b,h,i,d]
// MODE 3: V -> tf32, [b,h,d,i] (transposed)
// ---------------------------------------------------------------------------
#define ASTR 36
#define GTILE (128 * ASTR)
template <int MODE>
__global__ __launch_bounds__(256, 2) void gemm_tf32_kernel(
    const unsigned* __restrict__ A, const unsigned* __restrict__ W,
    void* __restrict__ Cv) {
  const int K = D_MODEL;
  extern __shared__ unsigned gsm[];
  unsigned* As = gsm;              // [2][GTILE]
  unsigned* Bs = gsm + 2 * GTILE;  // [2][GTILE]
  unsigned sA = (unsigned)__cvta_generic_to_shared(As);
  unsigned sB = (unsigned)__cvta_generic_to_shared(Bs);

  int tid = threadIdx.x;
  int m0 = blockIdx.y * 128;
  int n0 = blockIdx.x * 128;
  int wid = tid >> 5;
  int lane = tid & 31;
  int warp_m = (wid & 1) * 64;
  int warp_n = (wid >> 1) * 32;
  int grp = lane >> 2;
  int thr = lane & 3;
  int lr = tid >> 3;
  int lc = (tid & 7) * 4;

  const unsigned* Ap = A + (size_t)(m0 + lr) * K + lc;
  const unsigned* Wp = W + (size_t)(n0 + lr) * K + lc;

  float acc[4][4][4];
#pragma unroll
  for (int i = 0; i < 4; i++)
#pragma unroll
    for (int j = 0; j < 4; j++)
#pragma unroll
      for (int r = 0; r < 4; r++) acc[i][j][r] = 0.f;

#define G_ISSUE(k0, buf)                                              \
  {                                                                   \
    _Pragma("unroll") for (int s = 0; s < 4; s++) {                   \
      int r = lr + s * 32;                                            \
      cpa16(sA + ((buf)*GTILE + r * ASTR + lc) * 4,                   \
            Ap + (size_t)s * 32 * K + (k0));                          \
      cpa16(sB + ((buf)*GTILE + r * ASTR + lc) * 4,                   \
            Wp + (size_t)s * 32 * K + (k0));                          \
    }                                                                 \
    cpcommit();                                                       \
  }

  G_ISSUE(0, 0);
  const int T = K / 32;
  for (int t = 0; t < T; t++) {
    int cur = t & 1;
    cpwait0();
    __syncthreads();
    if (t + 1 < T) G_ISSUE((t + 1) * 32, cur ^ 1);
    const unsigned* Ac = As + cur * GTILE;
    const unsigned* Bc = Bs + cur * GTILE;
#pragma unroll
    for (int kk = 0; kk < 32; kk += 8) {
      unsigned af[4][4], bf[4][2];
#pragma unroll
      for (int mt = 0; mt < 4; mt++) {
        int rb = warp_m + mt * 16;
        af[mt][0] = Ac[(rb + grp) * ASTR + kk + thr];
        af[mt][1] = Ac[(rb + grp + 8) * ASTR + kk + thr];
        af[mt][2] = Ac[(rb + grp) * ASTR + kk + thr + 4];
        af[mt][3] = Ac[(rb + grp + 8) * ASTR + kk + thr + 4];
      }
#pragma unroll
      for (int nt = 0; nt < 4; nt++) {
        int nb = warp_n + nt * 8;
        bf[nt][0] = Bc[(nb + grp) * ASTR + kk + thr];
        bf[nt][1] = Bc[(nb + grp) * ASTR + kk + thr + 4];
      }
#pragma unroll
      for (int mt = 0; mt < 4; mt++)
#pragma unroll
        for (int nt = 0; nt < 4; nt++) {
          float* c = acc[mt][nt];
          asm volatile(
              "mma.sync.aligned.m16n8k8.row.col.f32.tf32.tf32.f32 "
              "{%0,%1,%2,%3}, {%4,%5,%6,%7}, {%8,%9}, {%0,%1,%2,%3};"
              : "+f"(c[0]), "+f"(c[1]), "+f"(c[2]), "+f"(c[3])
              : "r"(af[mt][0]), "r"(af[mt][1]), "r"(af[mt][2]), "r"(af[mt][3]),
                "r"(bf[nt][0]), "r"(bf[nt][1]));
        }
    }
  }

#pragma unroll
  for (int mt = 0; mt < 4; mt++) {
#pragma unroll
    for (int nt = 0; nt < 4; nt++) {
      int row = m0 + warp_m + mt * 16 + grp;
      int col = n0 + warp_n + nt * 8 + thr * 2;
      float* c = acc[mt][nt];
      if (MODE == 0) {
        float* C = (float*)Cv;
        *(float2*)&C[(size_t)row * D_MODEL + col] = make_float2(c[0], c[1]);
        *(float2*)&C[(size_t)(row + 8) * D_MODEL + col] = make_float2(c[2], c[3]);
      } else {
        unsigned* C = (unsigned*)Cv;
#pragma unroll
        for (int e = 0; e < 4; e++) {
          int r = row + (e >> 1) * 8;
          int n = col + (e & 1);
          int b = r >> 11;
          int ii = r & (L_SEQ - 1);
          int h = n & 15;
          int d = n >> 4;
          unsigned u = f2tf32(MODE == 1 ? c[e] * 0.125f : c[e]);
          if (MODE == 3)
            C[((((size_t)b * NH + h) * DK) + d) * L_SEQ + ii] = u;
          else
            C[((((size_t)b * NH + h) * L_SEQ) + ii) * DK + d] = u;
        }
      }
    }
  }
}

// ---------------------------------------------------------------------------
// TF32 flash attention, cp.async double-buffered K/V tiles.
// CTA: (b, h, 128 i-rows). 8 warps x 16 rows. o-tiles of 64.
// All operands arrive pre-converted tf32; output Mha written as tf32.
// ---------------------------------------------------------------------------
#define PSTR 68
#define KVSZ (64 * PSTR)
__global__ __launch_bounds__(256) void attn_mma_kernel(
    const unsigned* __restrict__ Qh, const unsigned* __restrict__ Kh,
    const unsigned* __restrict__ Vt, const unsigned* __restrict__ mbits,
    unsigned* __restrict__ Mha) {
  extern __shared__ unsigned smu[];
  // layout: [buf0 K][buf0 V][buf1 K][buf1 V][Ps 128*PSTR]
  unsigned* Ps = smu + 4 * KVSZ;
  unsigned sbase = (unsigned)__cvta_generic_to_shared(smu);

  int tid = threadIdx.x;
  int w = tid >> 5;
  int lane = tid & 31;
  int grp = lane >> 2;
  int thr = lane & 3;
  int i0 = blockIdx.x * 128;
  int h = blockIdx.y;
  int b = blockIdx.z;
  int bh = b * NH + h;
  const unsigned* Qb = Qh + (size_t)bh * L_SEQ * DK;
  const unsigned* Kb = Kh + (size_t)bh * L_SEQ * DK;
  const unsigned* Vb = Vt + (size_t)bh * DK * L_SEQ;

#define KV_ISSUE(o0, buf)                                             \
  {                                                                   \
    unsigned kbb = sbase + (buf)*2 * KVSZ * 4;                        \
    unsigned vbb = kbb + KVSZ * 4;                                    \
    _Pragma("unroll") for (int s = 0; s < 4; s++) {                   \
      int idx = tid + s * 256;                                        \
      int r = idx >> 4, c = (idx & 15) * 4;                           \
      cpa16(kbb + (r * PSTR + c) * 4, Kb + (size_t)((o0) + r) * DK + c); \
      cpa16(vbb + (r * PSTR + c) * 4, Vb + (size_t)r * L_SEQ + (o0) + c); \
    }                                                                 \
    cpcommit();                                                       \
  }

  KV_ISSUE(0, 0);

  // Stage Q (already scaled tf32) into Ps, pull persistent A-fragments
  for (int idx = tid; idx < 128 * 16; idx += 256) {
    int i = idx >> 4, dc = (idx & 15) << 2;
    *(uint4*)&Ps[i * PSTR + dc] = *(const uint4*)&Qb[(size_t)(i0 + i) * DK + dc];
  }
  __syncthreads();

  int rbase = w * 16;
  unsigned Qf[8][4];
#pragma unroll
  for (int kg = 0; kg < 8; kg++) {
    Qf[kg][0] = Ps[(rbase + grp) * PSTR + kg * 8 + thr];
    Qf[kg][1] = Ps[(rbase + grp + 8) * PSTR + kg * 8 + thr];
    Qf[kg][2] = Ps[(rbase + grp) * PSTR + kg * 8 + thr + 4];
    Qf[kg][3] = Ps[(rbase + grp + 8) * PSTR + kg * 8 + thr + 4];
  }
  __syncthreads();

  int rA = i0 + rbase + grp;
  int rB = rA + 8;
  const unsigned long long* mbA =
      (const unsigned long long*)mbits + (size_t)(b * L_SEQ + rA) * (L_SEQ / 64);
  const unsigned long long* mbB =
      (const unsigned long long*)mbits + (size_t)(b * L_SEQ + rB) * (L_SEQ / 64);

  float mA = -CUDART_INF_F, mB = -CUDART_INF_F;
  float lA = 0.f, lB = 0.f;
  float oa[8][4];
#pragma unroll
  for (int nt = 0; nt < 8; nt++)
#pragma unroll
    for (int e = 0; e < 4; e++) oa[nt][e] = 0.f;

  const int NT = L_SEQ / 64;
  for (int ot = 0; ot < NT; ot++) {
    int cur = ot & 1;
    unsigned long long mWa = mbA[ot];
    unsigned long long mWb = mbB[ot];
    cpwait0();
    __syncthreads();
    if (ot + 1 < NT) KV_ISSUE((ot + 1) * 64, cur ^ 1);
    const unsigned* Ks = smu + cur * 2 * KVSZ;
    const unsigned* Vs = Ks + KVSZ;

    // S = Q K^T  (16 x 64 per warp)
    float sa[8][4];
#pragma unroll
    for (int nt = 0; nt < 8; nt++) {
      sa[nt][0] = sa[nt][1] = sa[nt][2] = sa[nt][3] = 0.f;
#pragma unroll
      for (int kg = 0; kg < 8; kg++) {
        unsigned b0 = Ks[(nt * 8 + grp) * PSTR + kg * 8 + thr];
        unsigned b1 = Ks[(nt * 8 + grp) * PSTR + kg * 8 + thr + 4];
        float* c = sa[nt];
        asm volatile(
            "mma.sync.aligned.m16n8k8.row.col.f32.tf32.tf32.f32 "
            "{%0,%1,%2,%3}, {%4,%5,%6,%7}, {%8,%9}, {%0,%1,%2,%3};"
            : "+f"(c[0]), "+f"(c[1]), "+f"(c[2]), "+f"(c[3])
            : "r"(Qf[kg][0]), "r"(Qf[kg][1]), "r"(Qf[kg][2]), "r"(Qf[kg][3]),
              "r"(b0), "r"(b1));
      }
    }

    // Mask + register row-max
    float mxA = -CUDART_INF_F, mxB = -CUDART_INF_F;
#pragma unroll
    for (int nt = 0; nt < 8; nt++) {
      int c0 = nt * 8 + 2 * thr;
      if ((mWa >> c0) & 1ull) sa[nt][0] = NEG;
      if ((mWa >> (c0 + 1)) & 1ull) sa[nt][1] = NEG;
      if ((mWb >> c0) & 1ull) sa[nt][2] = NEG;
      if ((mWb >> (c0 + 1)) & 1ull) sa[nt][3] = NEG;
      mxA = fmaxf(mxA, fmaxf(sa[nt][0], sa[nt][1]));
      mxB = fmaxf(mxB, fmaxf(sa[nt][2], sa[nt][3]));
    }
    mxA = fmaxf(mxA, __shfl_xor_sync(0xffffffffu, mxA, 1));
    mxA = fmaxf(mxA, __shfl_xor_sync(0xffffffffu, mxA, 2));
    mxB = fmaxf(mxB, __shfl_xor_sync(0xffffffffu, mxB, 1));
    mxB = fmaxf(mxB, __shfl_xor_sync(0xffffffffu, mxB, 2));

    float nmA = fmaxf(mA, mxA), nmB = fmaxf(mB, mxB);
    float cA = __expf(mA - nmA), cB = __expf(mB - nmB);
    float sumA = 0.f, sumB = 0.f;
#pragma unroll
    for (int nt = 0; nt < 8; nt++) {
      float p0 = __expf(sa[nt][0] - nmA);
      float p1 = __expf(sa[nt][1] - nmA);
      float p2 = __expf(sa[nt][2] - nmB);
      float p3 = __expf(sa[nt][3] - nmB);
      sumA += p0 + p1;
      sumB += p2 + p3;
      uint2 u01 = make_uint2(f2tf32(p0), f2tf32(p1));
      uint2 u23 = make_uint2(f2tf32(p2), f2tf32(p3));
      *(uint2*)&Ps[(rbase + grp) * PSTR + nt * 8 + 2 * thr] = u01;
      *(uint2*)&Ps[(rbase + grp + 8) * PSTR + nt * 8 + 2 * thr] = u23;
    }
    sumA += __shfl_xor_sync(0xffffffffu, sumA, 1);
    sumA += __shfl_xor_sync(0xffffffffu, sumA, 2);
    sumB += __shfl_xor_sync(0xffffffffu, sumB, 1);
    sumB += __shfl_xor_sync(0xffffffffu, sumB, 2);
    lA = lA * cA + sumA;
    lB = lB * cB + sumB;
    mA = nmA;
    mB = nmB;

#pragma unroll
    for (int nt = 0; nt < 8; nt++) {
      oa[nt][0] *= cA;
      oa[nt][1] *= cA;
      oa[nt][2] *= cB;
      oa[nt][3] *= cB;
    }
    __syncwarp();

    // O += P V
    unsigned pf[8][4];
#pragma unroll
    for (int kg = 0; kg < 8; kg++) {
      pf[kg][0] = Ps[(rbase + grp) * PSTR + kg * 8 + thr];
      pf[kg][1] = Ps[(rbase + grp + 8) * PSTR + kg * 8 + thr];
      pf[kg][2] = Ps[(rbase + grp) * PSTR + kg * 8 + thr + 4];
      pf[kg][3] = Ps[(rbase + grp + 8) * PSTR + kg * 8 + thr + 4];
    }
#pragma unroll
    for (int nt = 0; nt < 8; nt++) {
#pragma unroll
      for (int kg = 0; kg < 8; kg++) {
        unsigned b0 = Vs[(nt * 8 + grp) * PSTR + kg * 8 + thr];
        unsigned b1 = Vs[(nt * 8 + grp) * PSTR + kg * 8 + thr + 4];
        float* c = oa[nt];
        asm volatile(
            "mma.sync.aligned.m16n8k8.row.col.f32.tf32.tf32.f32 "
            "{%0,%1,%2,%3}, {%4,%5,%6,%7}, {%8,%9}, {%0,%1,%2,%3};"
            : "+f"(c[0]), "+f"(c[1]), "+f"(c[2]), "+f"(c[3])
            : "r"(pf[kg][0]), "r"(pf[kg][1]), "r"(pf[kg][2]), "r"(pf[kg][3]),
              "r"(b0), "r"(b1));
      }
    }
  }

  float iA = 1.f / lA, iB = 1.f / lB;
  unsigned* outA = &Mha[(size_t)(b * L_SEQ + rA) * D_MODEL + h];
  unsigned* outB = &Mha[(size_t)(b * L_SEQ + rB) * D_MODEL + h];
#pragma unroll
  for (int nt = 0; nt < 8; nt++) {
    int d0 = nt * 8 + 2 * thr;
    outA[(d0 + 0) * 16] = f2tf32(oa[nt][0] * iA);
    outA[(d0 + 1) * 16] = f2tf32(oa[nt][1] * iA);
    outB[(d0 + 0) * 16] = f2tf32(oa[nt][2] * iB);
    outB[(d0 + 1) * 16] = f2tf32(oa[nt][3] * iB);
  }
}

// ---------------------------------------------------------------------------
extern "C" void kernel_launch(void* const* d_in, const int* in_sizes, int n_in,
                              void* d_out, int out_size) {
  const float* q = (const float*)d_in[0];
  const float* k = (const float*)d_in[1];
  const float* v = (const float*)d_in[2];
  const int* mask4 = (const int*)d_in[3];
  const float* Wq = (const float*)d_in[4];
  const float* Wk = (const float*)d_in[5];
  const float* Wv = (const float*)d_in[6];
  const float* Wo = (const float*)d_in[7];
  float* out = (float*)d_out;

  unsigned *Qh, *Kh, *Vt, *Mh, *Mb, *Qtf, *Ktf, *Vtf, *Wtf;
  cudaGetSymbolAddress((void**)&Qh, g_Qh);
  cudaGetSymbolAddress((void**)&Kh, g_Kh);
  cudaGetSymbolAddress((void**)&Vt, g_Vt);
  cudaGetSymbolAddress((void**)&Mh, g_Mha);
  cudaGetSymbolAddress((void**)&Mb, g_mbits);
  cudaGetSymbolAddress((void**)&Qtf, g_Qtf);
  cudaGetSymbolAddress((void**)&Ktf, g_Ktf);
  cudaGetSymbolAddress((void**)&Vtf, g_Vtf);
  cudaGetSymbolAddress((void**)&Wtf, g_Wtf);

  // Input conversions
  int nbig = M_TOT * D_MODEL / 4 / 256;   // 4096 blocks
  int nw = D_MODEL * D_MODEL / 4 / 256;   // 1024 blocks
  cvt_tf32_kernel<<<nbig, 256>>>((const float4*)q, (uint4*)Qtf);
  cvt_tf32_kernel<<<nbig, 256>>>((const float4*)k, (uint4*)Ktf);
  cvt_tf32_kernel<<<nbig, 256>>>((const float4*)v, (uint4*)Vtf);
  cvt_tf32_kernel<<<nw, 256>>>((const float4*)Wq, (uint4*)(Wtf + 0 * D_MODEL * D_MODEL));
  cvt_tf32_kernel<<<nw, 256>>>((const float4*)Wk, (uint4*)(Wtf + 1 * D_MODEL * D_MODEL));
  cvt_tf32_kernel<<<nw, 256>>>((const float4*)Wv, (uint4*)(Wtf + 2 * D_MODEL * D_MODEL));
  cvt_tf32_kernel<<<nw, 256>>>((const float4*)Wo, (uint4*)(Wtf + 3 * D_MODEL * D_MODEL));

  int nwords = B_SZ * L_SEQ * L_SEQ / 32;
  mask_bits_kernel<<<nwords / 256, 256>>>(mask4, Mb);

  int gsmem = 4 * GTILE * 4;  // 73728 bytes
  cudaFuncSetAttribute(gemm_tf32_kernel<0>, cudaFuncAttributeMaxDynamicSharedMemorySize, gsmem);
  cudaFuncSetAttribute(gemm_tf32_kernel<1>, cudaFuncAttributeMaxDynamicSharedMemorySize, gsmem);
  cudaFuncSetAttribute(gemm_tf32_kernel<2>, cudaFuncAttributeMaxDynamicSharedMemorySize, gsmem);
  cudaFuncSetAttribute(gemm_tf32_kernel<3>, cudaFuncAttributeMaxDynamicSharedMemorySize, gsmem);

  dim3 gg(D_MODEL / 128, M_TOT / 128);  // (8, 32)
  gemm_tf32_kernel<1><<<gg, 256, gsmem>>>(Qtf, Wtf + 0 * D_MODEL * D_MODEL, Qh);
  gemm_tf32_kernel<2><<<gg, 256, gsmem>>>(Ktf, Wtf + 1 * D_MODEL * D_MODEL, Kh);
  gemm_tf32_kernel<3><<<gg, 256, gsmem>>>(Vtf, Wtf + 2 * D_MODEL * D_MODEL, Vt);

  int asmem = (4 * KVSZ + 128 * PSTR) * 4;  // 104448 bytes
  cudaFuncSetAttribute(attn_mma_kernel,
                       cudaFuncAttributeMaxDynamicSharedMemorySize, asmem);
  dim3 ag(L_SEQ / 128, NH, B_SZ);  // (16, 16, 2)
  attn_mma_kernel<<<ag, 256, asmem>>>(Qh, Kh, Vt, Mb, Mh);

  gemm_tf32_kernel<0><<<gg, 256, gsmem>>>(Mh, Wtf + 3 * D_MODEL * D_MODEL, out);
}

// round 6
// speedup vs baseline: 1.4928x; 1.4928x over previous
#include <cuda_runtime.h>
#include <cuda_fp16.h>
#include <math_constants.h>

#define B_SZ 2
#define L_SEQ 2048
#define D_MODEL 1024
#define NH 16
#define DK 64
#define M_TOT (B_SZ * L_SEQ)
#define NEG (-1e10f)

// Scratch (device globals). All fp16.
__device__ __align__(16) __half g_Qh[B_SZ * NH * L_SEQ * DK];  // [b][h][i][d] *0.125
__device__ __align__(16) __half g_Kh[B_SZ * NH * L_SEQ * DK];  // [b][h][o][d]
__device__ __align__(16) __half g_Vt[B_SZ * NH * DK * L_SEQ];  // [b][h][d][o]
__device__ __align__(16) __half g_Mha[M_TOT * D_MODEL];        // [b*L+i][d*16+h]
__device__ unsigned g_mbits[B_SZ * L_SEQ * L_SEQ / 32];

__device__ __forceinline__ void cpa16(unsigned d, const void* s) {
  asm volatile("cp.async.cg.shared.global [%0], [%1], 16;" :: "r"(d), "l"(s));
}
__device__ __forceinline__ void cpcommit() {
  asm volatile("cp.async.commit_group;");
}
__device__ __forceinline__ void cpwait0() {
  asm volatile("cp.async.wait_group 0;");
}
#define MMA16(c, a, b)                                                    \
  asm volatile(                                                           \
      "mma.sync.aligned.m16n8k16.row.col.f32.f16.f16.f32 "                \
      "{%0,%1,%2,%3}, {%4,%5,%6,%7}, {%8,%9}, {%0,%1,%2,%3};"             \
      : "+f"((c)[0]), "+f"((c)[1]), "+f"((c)[2]), "+f"((c)[3])            \
      : "r"((a)[0]), "r"((a)[1]), "r"((a)[2]), "r"((a)[3]), "r"((b)[0]),  \
        "r"((b)[1]))

// ---------------------------------------------------------------------------
// Mask: 4-byte bool elements -> bit-packed (bit set == masked)
// ---------------------------------------------------------------------------
__global__ __launch_bounds__(256) void mask_bits_kernel(
    const int* __restrict__ m4, unsigned* __restrict__ out) {
  int w = blockIdx.x * 256 + threadIdx.x;
  const int4* p = (const int4*)m4 + (size_t)w * 8;
  unsigned bits = 0;
#pragma unroll
  for (int j = 0; j < 8; j++) {
    int4 v = p[j];
    bits |= (unsigned)(v.x != 0) << (4 * j + 0);
    bits |= (unsigned)(v.y != 0) << (4 * j + 1);
    bits |= (unsigned)(v.z != 0) << (4 * j + 2);
    bits |= (unsigned)(v.w != 0) << (4 * j + 3);
  }
  out[w] = bits;
}

// ---------------------------------------------------------------------------
// FP16 GEMM: C[m,n] = sum_k A[m,k] * W[n,k].  128x128 tile, KC=64.
// 8 warps x (64x32) via 4x4 m16n8k16 tiles. W always fp32 (converted in load).
// AHALF: A already __half (Mha). Else fp32 converted in load.
// MODE 0: fp32 C[m*1024+n]
// MODE 1: Q -> half * 0.125, [b,h,i,d]
// MODE 2: K -> half, [b,h,i,d]
// MODE 3: V -> half, [b,h,d,i] (transposed)
// ---------------------------------------------------------------------------
#define GSTR 72  // half units per row (64 + 8 pad)
template <int MODE, int AHALF>
__global__ __launch_bounds__(256, 2) void gemm_h_kernel(
    const void* __restrict__ Av, const float* __restrict__ W,
    void* __restrict__ Cv) {
  __shared__ __half As[128 * GSTR];
  __shared__ __half Bs[128 * GSTR];

  int tid = threadIdx.x;
  int m0 = blockIdx.y * 128;
  int n0 = blockIdx.x * 128;
  int wid = tid >> 5;
  int lane = tid & 31;
  int warp_m = (wid & 1) * 64;
  int warp_n = (wid >> 1) * 32;
  int grp = lane >> 2;
  int thr = lane & 3;

  float acc[4][4][4];
#pragma unroll
  for (int i = 0; i < 4; i++)
#pragma unroll
    for (int j = 0; j < 4; j++)
#pragma unroll
      for (int r = 0; r < 4; r++) acc[i][j][r] = 0.f;

  for (int k0 = 0; k0 < D_MODEL; k0 += 64) {
    // Load A tile (128 x 64)
    if (AHALF) {
      const __half* A = (const __half*)Av;
#pragma unroll
      for (int it = 0; it < 4; it++) {
        int idx = tid + it * 256;
        int r = idx >> 3, ch = (idx & 7) * 8;
        *(uint4*)&As[r * GSTR + ch] =
            *(const uint4*)&A[(size_t)(m0 + r) * D_MODEL + k0 + ch];
      }
    } else {
      const float* A = (const float*)Av;
#pragma unroll
      for (int it = 0; it < 8; it++) {
        int idx = tid + it * 256;
        int r = idx >> 4, c = (idx & 15) * 4;
        float4 a = *(const float4*)&A[(size_t)(m0 + r) * D_MODEL + k0 + c];
        __half2* d = (__half2*)&As[r * GSTR + c];
        d[0] = __floats2half2_rn(a.x, a.y);
        d[1] = __floats2half2_rn(a.z, a.w);
      }
    }
    // Load W tile (128 x 64), fp32 -> fp16
#pragma unroll
    for (int it = 0; it < 8; it++) {
      int idx = tid + it * 256;
      int r = idx >> 4, c = (idx & 15) * 4;
      float4 w = *(const float4*)&W[(size_t)(n0 + r) * D_MODEL + k0 + c];
      __half2* d = (__half2*)&Bs[r * GSTR + c];
      d[0] = __floats2half2_rn(w.x, w.y);
      d[1] = __floats2half2_rn(w.z, w.w);
    }
    __syncthreads();

#pragma unroll
    for (int kk = 0; kk < 64; kk += 16) {
      unsigned af[4][4], bf[4][2];
#pragma unroll
      for (int mt = 0; mt < 4; mt++) {
        int rb = warp_m + mt * 16;
        af[mt][0] = *(const unsigned*)&As[(rb + grp) * GSTR + kk + 2 * thr];
        af[mt][1] = *(const unsigned*)&As[(rb + grp + 8) * GSTR + kk + 2 * thr];
        af[mt][2] = *(const unsigned*)&As[(rb + grp) * GSTR + kk + 2 * thr + 8];
        af[mt][3] = *(const unsigned*)&As[(rb + grp + 8) * GSTR + kk + 2 * thr + 8];
      }
#pragma unroll
      for (int nt = 0; nt < 4; nt++) {
        int nb = warp_n + nt * 8;
        bf[nt][0] = *(const unsigned*)&Bs[(nb + grp) * GSTR + kk + 2 * thr];
        bf[nt][1] = *(const unsigned*)&Bs[(nb + grp) * GSTR + kk + 2 * thr + 8];
      }
#pragma unroll
      for (int mt = 0; mt < 4; mt++)
#pragma unroll
        for (int nt = 0; nt < 4; nt++) MMA16(acc[mt][nt], af[mt], bf[nt]);
    }
    __syncthreads();
  }

#pragma unroll
  for (int mt = 0; mt < 4; mt++) {
#pragma unroll
    for (int nt = 0; nt < 4; nt++) {
      int row = m0 + warp_m + mt * 16 + grp;
      int col = n0 + warp_n + nt * 8 + thr * 2;
      float* c = acc[mt][nt];
      if (MODE == 0) {
        float* C = (float*)Cv;
        *(float2*)&C[(size_t)row * D_MODEL + col] = make_float2(c[0], c[1]);
        *(float2*)&C[(size_t)(row + 8) * D_MODEL + col] = make_float2(c[2], c[3]);
      } else {
        __half* C = (__half*)Cv;
#pragma unroll
        for (int e = 0; e < 4; e++) {
          int r = row + (e >> 1) * 8;
          int n = col + (e & 1);
          int b = r >> 11;
          int ii = r & (L_SEQ - 1);
          int h = n & 15;
          int d = n >> 4;
          __half u = __float2half_rn(MODE == 1 ? c[e] * 0.125f : c[e]);
          if (MODE == 3)
            C[((((size_t)b * NH + h) * DK) + d) * L_SEQ + ii] = u;
          else
            C[((((size_t)b * NH + h) * L_SEQ) + ii) * DK + d] = u;
        }
      }
    }
  }
}

// ---------------------------------------------------------------------------
// FP16 flash attention. CTA: (b, h, 128 i-rows). 8 warps x 16 rows.
// o-tiles of 64, K/V cp.async double-buffered. m16n8k16 MMAs.
// ---------------------------------------------------------------------------
#define PSTR 72                 // half units per row
#define KVSZ (64 * PSTR)        // halves per K or V tile
__global__ __launch_bounds__(256) void attn_mma_kernel(
    const __half* __restrict__ Qh, const __half* __restrict__ Kh,
    const __half* __restrict__ Vt, const unsigned* __restrict__ mbits,
    __half* __restrict__ Mha) {
  extern __shared__ __half smh[];
  // [buf0 K][buf0 V][buf1 K][buf1 V][Ps 128*PSTR]
  __half* Ps = smh + 4 * KVSZ;
  unsigned sbase = (unsigned)__cvta_generic_to_shared(smh);

  int tid = threadIdx.x;
  int w = tid >> 5;
  int lane = tid & 31;
  int grp = lane >> 2;
  int thr = lane & 3;
  int i0 = blockIdx.x * 128;
  int h = blockIdx.y;
  int b = blockIdx.z;
  int bh = b * NH + h;
  const __half* Qb = Qh + (size_t)bh * L_SEQ * DK;
  const __half* Kb = Kh + (size_t)bh * L_SEQ * DK;
  const __half* Vb = Vt + (size_t)bh * DK * L_SEQ;

#define KV_ISSUE(o0, buf)                                                  \
  {                                                                        \
    unsigned kbb = sbase + (buf)*2 * KVSZ * 2;                             \
    unsigned vbb = kbb + KVSZ * 2;                                         \
    _Pragma("unroll") for (int s = 0; s < 2; s++) {                        \
      int idx = tid + s * 256;                                             \
      int r = idx >> 3, ch = (idx & 7) * 8;                                \
      cpa16(kbb + (r * PSTR + ch) * 2, Kb + (size_t)((o0) + r) * DK + ch); \
      cpa16(vbb + (r * PSTR + ch) * 2, Vb + (size_t)r * L_SEQ + (o0) + ch); \
    }                                                                      \
    cpcommit();                                                            \
  }

  KV_ISSUE(0, 0);

  // Stage Q (scaled fp16) into Ps, pull persistent A-fragments
#pragma unroll
  for (int it = 0; it < 4; it++) {
    int idx = tid + it * 256;
    int r = idx >> 3, ch = (idx & 7) * 8;
    *(uint4*)&Ps[r * PSTR + ch] = *(const uint4*)&Qb[(size_t)(i0 + r) * DK + ch];
  }
  __syncthreads();

  int rbase = w * 16;
  unsigned Qf[4][4];
#pragma unroll
  for (int kg = 0; kg < 4; kg++) {
    Qf[kg][0] = *(const unsigned*)&Ps[(rbase + grp) * PSTR + kg * 16 + 2 * thr];
    Qf[kg][1] = *(const unsigned*)&Ps[(rbase + grp + 8) * PSTR + kg * 16 + 2 * thr];
    Qf[kg][2] = *(const unsigned*)&Ps[(rbase + grp) * PSTR + kg * 16 + 2 * thr + 8];
    Qf[kg][3] = *(const unsigned*)&Ps[(rbase + grp + 8) * PSTR + kg * 16 + 2 * thr + 8];
  }
  __syncthreads();

  int rA = i0 + rbase + grp;
  int rB = rA + 8;
  const unsigned long long* mbA =
      (const unsigned long long*)mbits + (size_t)(b * L_SEQ + rA) * (L_SEQ / 64);
  const unsigned long long* mbB =
      (const unsigned long long*)mbits + (size_t)(b * L_SEQ + rB) * (L_SEQ / 64);

  float mA = -CUDART_INF_F, mB = -CUDART_INF_F;
  float lA = 0.f, lB = 0.f;
  float oa[8][4];
#pragma unroll
  for (int nt = 0; nt < 8; nt++)
#pragma unroll
    for (int e = 0; e < 4; e++) oa[nt][e] = 0.f;

  const int NT = L_SEQ / 64;
  for (int ot = 0; ot < NT; ot++) {
    int cur = ot & 1;
    unsigned long long mWa = mbA[ot];
    unsigned long long mWb = mbB[ot];
    cpwait0();
    __syncthreads();
    if (ot + 1 < NT) KV_ISSUE((ot + 1) * 64, cur ^ 1);
    const __half* Ks = smh + cur * 2 * KVSZ;
    const __half* Vs = Ks + KVSZ;

    // S = Q K^T  (16 x 64 per warp)
    float sa[8][4];
#pragma unroll
    for (int nt = 0; nt < 8; nt++) {
      sa[nt][0] = sa[nt][1] = sa[nt][2] = sa[nt][3] = 0.f;
#pragma unroll
      for (int kg = 0; kg < 4; kg++) {
        unsigned bf[2];
        bf[0] = *(const unsigned*)&Ks[(nt * 8 + grp) * PSTR + kg * 16 + 2 * thr];
        bf[1] = *(const unsigned*)&Ks[(nt * 8 + grp) * PSTR + kg * 16 + 2 * thr + 8];
        MMA16(sa[nt], Qf[kg], bf);
      }
    }

    // Mask + register row-max
    float mxA = -CUDART_INF_F, mxB = -CUDART_INF_F;
#pragma unroll
    for (int nt = 0; nt < 8; nt++) {
      int c0 = nt * 8 + 2 * thr;
      if ((mWa >> c0) & 1ull) sa[nt][0] = NEG;
      if ((mWa >> (c0 + 1)) & 1ull) sa[nt][1] = NEG;
      if ((mWb >> c0) & 1ull) sa[nt][2] = NEG;
      if ((mWb >> (c0 + 1)) & 1ull) sa[nt][3] = NEG;
      mxA = fmaxf(mxA, fmaxf(sa[nt][0], sa[nt][1]));
      mxB = fmaxf(mxB, fmaxf(sa[nt][2], sa[nt][3]));
    }
    mxA = fmaxf(mxA, __shfl_xor_sync(0xffffffffu, mxA, 1));
    mxA = fmaxf(mxA, __shfl_xor_sync(0xffffffffu, mxA, 2));
    mxB = fmaxf(mxB, __shfl_xor_sync(0xffffffffu, mxB, 1));
    mxB = fmaxf(mxB, __shfl_xor_sync(0xffffffffu, mxB, 2));

    float nmA = fmaxf(mA, mxA), nmB = fmaxf(mB, mxB);
    float cA = __expf(mA - nmA), cB = __expf(mB - nmB);
    float sumA = 0.f, sumB = 0.f;
#pragma unroll
    for (int nt = 0; nt < 8; nt++) {
      float p0 = __expf(sa[nt][0] - nmA);
      float p1 = __expf(sa[nt][1] - nmA);
      float p2 = __expf(sa[nt][2] - nmB);
      float p3 = __expf(sa[nt][3] - nmB);
      sumA += p0 + p1;
      sumB += p2 + p3;
      *(__half2*)&Ps[(rbase + grp) * PSTR + nt * 8 + 2 * thr] =
          __floats2half2_rn(p0, p1);
      *(__half2*)&Ps[(rbase + grp + 8) * PSTR + nt * 8 + 2 * thr] =
          __floats2half2_rn(p2, p3);
    }
    sumA += __shfl_xor_sync(0xffffffffu, sumA, 1);
    sumA += __shfl_xor_sync(0xffffffffu, sumA, 2);
    sumB += __shfl_xor_sync(0xffffffffu, sumB, 1);
    sumB += __shfl_xor_sync(0xffffffffu, sumB, 2);
    lA = lA * cA + sumA;
    lB = lB * cB + sumB;
    mA = nmA;
    mB = nmB;

#pragma unroll
    for (int nt = 0; nt < 8; nt++) {
      oa[nt][0] *= cA;
      oa[nt][1] *= cA;
      oa[nt][2] *= cB;
      oa[nt][3] *= cB;
    }
    __syncwarp();

    // O += P V  (A-frags from Ps rows [i][o], B-frags from Vs = V^T [d][o])
    unsigned pf[4][4];
#pragma unroll
    for (int kg = 0; kg < 4; kg++) {
      pf[kg][0] = *(const unsigned*)&Ps[(rbase + grp) * PSTR + kg * 16 + 2 * thr];
      pf[kg][1] = *(const unsigned*)&Ps[(rbase + grp + 8) * PSTR + kg * 16 + 2 * thr];
      pf[kg][2] = *(const unsigned*)&Ps[(rbase + grp) * PSTR + kg * 16 + 2 * thr + 8];
      pf[kg][3] = *(const unsigned*)&Ps[(rbase + grp + 8) * PSTR + kg * 16 + 2 * thr + 8];
    }
#pragma unroll
    for (int nt = 0; nt < 8; nt++) {
#pragma unroll
      for (int kg = 0; kg < 4; kg++) {
        unsigned bf[2];
        bf[0] = *(const unsigned*)&Vs[(nt * 8 + grp) * PSTR + kg * 16 + 2 * thr];
        bf[1] = *(const unsigned*)&Vs[(nt * 8 + grp) * PSTR + kg * 16 + 2 * thr + 8];
        MMA16(oa[nt], pf[kg], bf);
      }
    }
  }

  float iA = 1.f / lA, iB = 1.f / lB;
  __half* outA = &Mha[(size_t)(b * L_SEQ + rA) * D_MODEL + h];
  __half* outB = &Mha[(size_t)(b * L_SEQ + rB) * D_MODEL + h];
#pragma unroll
  for (int nt = 0; nt < 8; nt++) {
    int d0 = nt * 8 + 2 * thr;
    outA[(d0 + 0) * 16] = __float2half_rn(oa[nt][0] * iA);
    outA[(d0 + 1) * 16] = __float2half_rn(oa[nt][1] * iA);
    outB[(d0 + 0) * 16] = __float2half_rn(oa[nt][2] * iB);
    outB[(d0 + 1) * 16] = __float2half_rn(oa[nt][3] * iB);
  }
}

// ---------------------------------------------------------------------------
extern "C" void kernel_launch(void* const* d_in, const int* in_sizes, int n_in,
                              void* d_out, int out_size) {
  const float* q = (const float*)d_in[0];
  const float* k = (const float*)d_in[1];
  const float* v = (const float*)d_in[2];
  const int* mask4 = (const int*)d_in[3];
  const float* Wq = (const float*)d_in[4];
  const float* Wk = (const float*)d_in[5];
  const float* Wv = (const float*)d_in[6];
  const float* Wo = (const float*)d_in[7];
  float* out = (float*)d_out;

  __half *Qh, *Kh, *Vt, *Mh;
  unsigned* Mb;
  cudaGetSymbolAddress((void**)&Qh, g_Qh);
  cudaGetSymbolAddress((void**)&Kh, g_Kh);
  cudaGetSymbolAddress((void**)&Vt, g_Vt);
  cudaGetSymbolAddress((void**)&Mh, g_Mha);
  cudaGetSymbolAddress((void**)&Mb, g_mbits);

  int nwords = B_SZ * L_SEQ * L_SEQ / 32;
  mask_bits_kernel<<<nwords / 256, 256>>>(mask4, Mb);

  dim3 gg(D_MODEL / 128, M_TOT / 128);  // (8, 32)
  gemm_h_kernel<1, 0><<<gg, 256>>>(q, Wq, Qh);
  gemm_h_kernel<2, 0><<<gg, 256>>>(k, Wk, Kh);
  gemm_h_kernel<3, 0><<<gg, 256>>>(v, Wv, Vt);

  int asmem = (4 * KVSZ + 128 * PSTR) * 2;  // 55296 bytes
  cudaFuncSetAttribute(attn_mma_kernel,
                       cudaFuncAttributeMaxDynamicSharedMemorySize, asmem);
  dim3 ag(L_SEQ / 128, NH, B_SZ);  // (16, 16, 2)
  attn_mma_kernel<<<ag, 256, asmem>>>(Qh, Kh, Vt, Mb, Mh);

  gemm_h_kernel<0, 1><<<gg, 256>>>(Mh, Wo, out);
}

// round 7
// speedup vs baseline: 1.5771x; 1.0565x over previous
#include <cuda_runtime.h>
#include <cuda_fp16.h>
#include <math_constants.h>

#define B_SZ 2
#define L_SEQ 2048
#define D_MODEL 1024
#define NH 16
#define DK 64
#define M_TOT (B_SZ * L_SEQ)
#define NEGL2 (-1.44269504e10f)  // -1e10 * log2(e)
#define QSCALE (0.125f * 1.442695040888963f)

// Scratch (device globals). All fp16.
__device__ __align__(16) __half g_Qh[B_SZ * NH * L_SEQ * DK];  // [b][h][i][d] * 0.125*log2e
__device__ __align__(16) __half g_Kh[B_SZ * NH * L_SEQ * DK];  // [b][h][o][d]
__device__ __align__(16) __half g_Vt[B_SZ * NH * DK * L_SEQ];  // [b][h][d][o]
__device__ __align__(16) __half g_Mha[M_TOT * D_MODEL];        // [b*L+i][d*16+h]
__device__ unsigned g_mbits[B_SZ * L_SEQ * L_SEQ / 32];

__device__ __forceinline__ void cpa16(unsigned d, const void* s) {
  asm volatile("cp.async.cg.shared.global [%0], [%1], 16;" :: "r"(d), "l"(s));
}
__device__ __forceinline__ void cpcommit() { asm volatile("cp.async.commit_group;"); }
__device__ __forceinline__ void cpwait0() { asm volatile("cp.async.wait_group 0;"); }
__device__ __forceinline__ float ex2f(float x) {
  float r;
  asm("ex2.approx.ftz.f32 %0, %1;" : "=f"(r) : "f"(x));
  return r;
}
__device__ __forceinline__ unsigned pack2(float a, float b) {
  __half2 h = __floats2half2_rn(a, b);
  return *(unsigned*)&h;
}
#define MMA16(c, a, b)                                                    \
  asm volatile(                                                           \
      "mma.sync.aligned.m16n8k16.row.col.f32.f16.f16.f32 "                \
      "{%0,%1,%2,%3}, {%4,%5,%6,%7}, {%8,%9}, {%0,%1,%2,%3};"             \
      : "+f"((c)[0]), "+f"((c)[1]), "+f"((c)[2]), "+f"((c)[3])            \
      : "r"((a)[0]), "r"((a)[1]), "r"((a)[2]), "r"((a)[3]), "r"((b)[0]),  \
        "r"((b)[1]))
#define LDSM4(r0, r1, r2, r3, addr)                                       \
  asm volatile(                                                           \
      "ldmatrix.sync.aligned.m8n8.x4.shared.b16 {%0,%1,%2,%3}, [%4];"     \
      : "=r"(r0), "=r"(r1), "=r"(r2), "=r"(r3) : "r"(addr))

// ---------------------------------------------------------------------------
// Mask: 4-byte bool elements -> bit-packed (bit set == masked)
// ---------------------------------------------------------------------------
__global__ __launch_bounds__(256) void mask_bits_kernel(
    const int* __restrict__ m4, unsigned* __restrict__ out) {
  int w = blockIdx.x * 256 + threadIdx.x;
  const int4* p = (const int4*)m4 + (size_t)w * 8;
  unsigned bits = 0;
#pragma unroll
  for (int j = 0; j < 8; j++) {
    int4 v = p[j];
    bits |= (unsigned)(v.x != 0) << (4 * j + 0);
    bits |= (unsigned)(v.y != 0) << (4 * j + 1);
    bits |= (unsigned)(v.z != 0) << (4 * j + 2);
    bits |= (unsigned)(v.w != 0) << (4 * j + 3);
  }
  out[w] = bits;
}

// ---------------------------------------------------------------------------
// FP16 GEMM with ldmatrix fragments. C[m,n] = sum_k A[m,k]*W[n,k].
// 128x128 tile, KC=64, 8 warps x (64x32).
// MODE 0: fp32 C[m*1024+n]
// MODE 1: Q -> half * 0.125*log2e, [b,h,i,d]
// MODE 2: K -> half, [b,h,i,d]
// MODE 3: V -> half, [b,h,d,i]
// ---------------------------------------------------------------------------
#define GSTR 72
template <int MODE, int AHALF>
__global__ __launch_bounds__(256, 2) void gemm_h_kernel(
    const void* __restrict__ Av, const float* __restrict__ W,
    void* __restrict__ Cv) {
  __shared__ __half As[128 * GSTR];
  __shared__ __half Bs[128 * GSTR];

  int tid = threadIdx.x;
  int m0 = blockIdx.y * 128;
  int n0 = blockIdx.x * 128;
  int wid = tid >> 5;
  int lane = tid & 31;
  int warp_m = (wid & 1) * 64;
  int warp_n = (wid >> 1) * 32;
  int grp = lane >> 2;
  int thr = lane & 3;
  int lrow = lane & 15;
  int lcol = (lane >> 4) * 8;

  unsigned aAddr = (unsigned)__cvta_generic_to_shared(As) +
                   ((warp_m + lrow) * GSTR + lcol) * 2;
  unsigned bAddr = (unsigned)__cvta_generic_to_shared(Bs) +
                   ((warp_n + lrow) * GSTR + lcol) * 2;

  float acc[4][4][4];
#pragma unroll
  for (int i = 0; i < 4; i++)
#pragma unroll
    for (int j = 0; j < 4; j++)
#pragma unroll
      for (int r = 0; r < 4; r++) acc[i][j][r] = 0.f;

  for (int k0 = 0; k0 < D_MODEL; k0 += 64) {
    if (AHALF) {
      const __half* A = (const __half*)Av;
#pragma unroll
      for (int it = 0; it < 4; it++) {
        int idx = tid + it * 256;
        int r = idx >> 3, ch = (idx & 7) * 8;
        *(uint4*)&As[r * GSTR + ch] =
            *(const uint4*)&A[(size_t)(m0 + r) * D_MODEL + k0 + ch];
      }
    } else {
      const float* A = (const float*)Av;
#pragma unroll
      for (int it = 0; it < 8; it++) {
        int idx = tid + it * 256;
        int r = idx >> 4, c = (idx & 15) * 4;
        float4 a = *(const float4*)&A[(size_t)(m0 + r) * D_MODEL + k0 + c];
        __half2* d = (__half2*)&As[r * GSTR + c];
        d[0] = __floats2half2_rn(a.x, a.y);
        d[1] = __floats2half2_rn(a.z, a.w);
      }
    }
#pragma unroll
    for (int it = 0; it < 8; it++) {
      int idx = tid + it * 256;
      int r = idx >> 4, c = (idx & 15) * 4;
      float4 w = *(const float4*)&W[(size_t)(n0 + r) * D_MODEL + k0 + c];
      __half2* d = (__half2*)&Bs[r * GSTR + c];
      d[0] = __floats2half2_rn(w.x, w.y);
      d[1] = __floats2half2_rn(w.z, w.w);
    }
    __syncthreads();

#pragma unroll
    for (int kk = 0; kk < 64; kk += 16) {
      unsigned af[4][4], bf[4][2];
#pragma unroll
      for (int mt = 0; mt < 4; mt++)
        LDSM4(af[mt][0], af[mt][1], af[mt][2], af[mt][3],
              aAddr + (mt * 16 * GSTR + kk) * 2);
#pragma unroll
      for (int ntp = 0; ntp < 2; ntp++) {
        unsigned b0, b1, b2, b3;
        LDSM4(b0, b1, b2, b3, bAddr + (ntp * 16 * GSTR + kk) * 2);
        bf[2 * ntp][0] = b0;
        bf[2 * ntp][1] = b2;
        bf[2 * ntp + 1][0] = b1;
        bf[2 * ntp + 1][1] = b3;
      }
#pragma unroll
      for (int mt = 0; mt < 4; mt++)
#pragma unroll
        for (int nt = 0; nt < 4; nt++) MMA16(acc[mt][nt], af[mt], bf[nt]);
    }
    __syncthreads();
  }

#pragma unroll
  for (int mt = 0; mt < 4; mt++) {
#pragma unroll
    for (int nt = 0; nt < 4; nt++) {
      int row = m0 + warp_m + mt * 16 + grp;
      int col = n0 + warp_n + nt * 8 + thr * 2;
      float* c = acc[mt][nt];
      if (MODE == 0) {
        float* C = (float*)Cv;
        *(float2*)&C[(size_t)row * D_MODEL + col] = make_float2(c[0], c[1]);
        *(float2*)&C[(size_t)(row + 8) * D_MODEL + col] = make_float2(c[2], c[3]);
      } else {
        __half* C = (__half*)Cv;
#pragma unroll
        for (int e = 0; e < 4; e++) {
          int r = row + (e >> 1) * 8;
          int n = col + (e & 1);
          int b = r >> 11;
          int ii = r & (L_SEQ - 1);
          int h = n & 15;
          int d = n >> 4;
          __half u = __float2half_rn(MODE == 1 ? c[e] * QSCALE : c[e]);
          if (MODE == 3)
            C[((((size_t)b * NH + h) * DK) + d) * L_SEQ + ii] = u;
          else
            C[((((size_t)b * NH + h) * L_SEQ) + ii) * DK + d] = u;
        }
      }
    }
  }
}

// ---------------------------------------------------------------------------
// FP16 flash attention. CTA: (b, h, 128 i-rows). 8 warps x 16 rows.
// o-tiles of 64, cp.async double-buffered K/V, ldmatrix B-fragments,
// register-only P (exp'd S packs directly into PV A-fragments).
// Softmax in log2 domain (Q pre-scaled by 0.125*log2e).
// ---------------------------------------------------------------------------
#define PSTR 72
#define KVSZ (64 * PSTR)
__global__ __launch_bounds__(256) void attn_mma_kernel(
    const __half* __restrict__ Qh, const __half* __restrict__ Kh,
    const __half* __restrict__ Vt, const unsigned* __restrict__ mbits,
    __half* __restrict__ Mha) {
  extern __shared__ __half smh[];
  __half* Ps = smh + 4 * KVSZ;  // Q staging only
  unsigned sbase = (unsigned)__cvta_generic_to_shared(smh);

  int tid = threadIdx.x;
  int w = tid >> 5;
  int lane = tid & 31;
  int grp = lane >> 2;
  int thr = lane & 3;
  int lrow = lane & 15;
  int lcol = (lane >> 4) * 8;
  int i0 = blockIdx.x * 128;
  int h = blockIdx.y;
  int b = blockIdx.z;
  int bh = b * NH + h;
  const __half* Qb = Qh + (size_t)bh * L_SEQ * DK;
  const __half* Kb = Kh + (size_t)bh * L_SEQ * DK;
  const __half* Vb = Vt + (size_t)bh * DK * L_SEQ;

#define KV_ISSUE(o0, buf)                                                  \
  {                                                                        \
    unsigned kbb = sbase + (buf)*2 * KVSZ * 2;                             \
    unsigned vbb = kbb + KVSZ * 2;                                         \
    _Pragma("unroll") for (int s = 0; s < 2; s++) {                        \
      int idx = tid + s * 256;                                             \
      int r = idx >> 3, ch = (idx & 7) * 8;                                \
      cpa16(kbb + (r * PSTR + ch) * 2, Kb + (size_t)((o0) + r) * DK + ch); \
      cpa16(vbb + (r * PSTR + ch) * 2, Vb + (size_t)r * L_SEQ + (o0) + ch); \
    }                                                                      \
    cpcommit();                                                            \
  }

  KV_ISSUE(0, 0);

#pragma unroll
  for (int it = 0; it < 4; it++) {
    int idx = tid + it * 256;
    int r = idx >> 3, ch = (idx & 7) * 8;
    *(uint4*)&Ps[r * PSTR + ch] = *(const uint4*)&Qb[(size_t)(i0 + r) * DK + ch];
  }
  __syncthreads();

  int rbase = w * 16;
  unsigned Qf[4][4];
#pragma unroll
  for (int kg = 0; kg < 4; kg++) {
    Qf[kg][0] = *(const unsigned*)&Ps[(rbase + grp) * PSTR + kg * 16 + 2 * thr];
    Qf[kg][1] = *(const unsigned*)&Ps[(rbase + grp + 8) * PSTR + kg * 16 + 2 * thr];
    Qf[kg][2] = *(const unsigned*)&Ps[(rbase + grp) * PSTR + kg * 16 + 2 * thr + 8];
    Qf[kg][3] = *(const unsigned*)&Ps[(rbase + grp + 8) * PSTR + kg * 16 + 2 * thr + 8];
  }
  __syncthreads();

  int rA = i0 + rbase + grp;
  int rB = rA + 8;
  const unsigned long long* mbA =
      (const unsigned long long*)mbits + (size_t)(b * L_SEQ + rA) * (L_SEQ / 64);
  const unsigned long long* mbB =
      (const unsigned long long*)mbits + (size_t)(b * L_SEQ + rB) * (L_SEQ / 64);

  float mA = -CUDART_INF_F, mB = -CUDART_INF_F;
  float lA = 0.f, lB = 0.f;
  float oa[8][4];
#pragma unroll
  for (int nt = 0; nt < 8; nt++)
#pragma unroll
    for (int e = 0; e < 4; e++) oa[nt][e] = 0.f;

  const int NT = L_SEQ / 64;
  for (int ot = 0; ot < NT; ot++) {
    int cur = ot & 1;
    unsigned long long mWa = mbA[ot];
    unsigned long long mWb = mbB[ot];
    cpwait0();
    __syncthreads();
    if (ot + 1 < NT) KV_ISSUE((ot + 1) * 64, cur ^ 1);
    unsigned kAddr = sbase + cur * 2 * KVSZ * 2 + (lrow * PSTR + lcol) * 2;
    unsigned vAddr = kAddr + KVSZ * 2;

    // S = Q K^T
    float sa[8][4];
#pragma unroll
    for (int nt = 0; nt < 8; nt++)
      sa[nt][0] = sa[nt][1] = sa[nt][2] = sa[nt][3] = 0.f;
#pragma unroll
    for (int ntp = 0; ntp < 4; ntp++) {
#pragma unroll
      for (int kg = 0; kg < 4; kg++) {
        unsigned b0, b1, b2, b3;
        LDSM4(b0, b1, b2, b3, kAddr + (ntp * 16 * PSTR + kg * 16) * 2);
        unsigned bfA[2] = {b0, b2}, bfB[2] = {b1, b3};
        MMA16(sa[2 * ntp], Qf[kg], bfA);
        MMA16(sa[2 * ntp + 1], Qf[kg], bfB);
      }
    }

    // Mask + register row-max (log2 domain)
    float mxA = -CUDART_INF_F, mxB = -CUDART_INF_F;
#pragma unroll
    for (int nt = 0; nt < 8; nt++) {
      int c0 = nt * 8 + 2 * thr;
      if ((mWa >> c0) & 1ull) sa[nt][0] = NEGL2;
      if ((mWa >> (c0 + 1)) & 1ull) sa[nt][1] = NEGL2;
      if ((mWb >> c0) & 1ull) sa[nt][2] = NEGL2;
      if ((mWb >> (c0 + 1)) & 1ull) sa[nt][3] = NEGL2;
      mxA = fmaxf(mxA, fmaxf(sa[nt][0], sa[nt][1]));
      mxB = fmaxf(mxB, fmaxf(sa[nt][2], sa[nt][3]));
    }
    mxA = fmaxf(mxA, __shfl_xor_sync(0xffffffffu, mxA, 1));
    mxA = fmaxf(mxA, __shfl_xor_sync(0xffffffffu, mxA, 2));
    mxB = fmaxf(mxB, __shfl_xor_sync(0xffffffffu, mxB, 1));
    mxB = fmaxf(mxB, __shfl_xor_sync(0xffffffffu, mxB, 2));

    float nmA = fmaxf(mA, mxA), nmB = fmaxf(mB, mxB);
    float cA = ex2f(mA - nmA), cB = ex2f(mB - nmB);
    float sumA = 0.f, sumB = 0.f;
    unsigned pf[4][4];  // PV A-fragments, packed directly from registers
#pragma unroll
    for (int nt = 0; nt < 8; nt++) {
      float p0 = ex2f(sa[nt][0] - nmA);
      float p1 = ex2f(sa[nt][1] - nmA);
      float p2 = ex2f(sa[nt][2] - nmB);
      float p3 = ex2f(sa[nt][3] - nmB);
      sumA += p0 + p1;
      sumB += p2 + p3;
      int kg = nt >> 1;
      if ((nt & 1) == 0) {
        pf[kg][0] = pack2(p0, p1);
        pf[kg][1] = pack2(p2, p3);
      } else {
        pf[kg][2] = pack2(p0, p1);
        pf[kg][3] = pack2(p2, p3);
      }
    }
    sumA += __shfl_xor_sync(0xffffffffu, sumA, 1);
    sumA += __shfl_xor_sync(0xffffffffu, sumA, 2);
    sumB += __shfl_xor_sync(0xffffffffu, sumB, 1);
    sumB += __shfl_xor_sync(0xffffffffu, sumB, 2);
    lA = lA * cA + sumA;
    lB = lB * cB + sumB;
    mA = nmA;
    mB = nmB;

#pragma unroll
    for (int nt = 0; nt < 8; nt++) {
      oa[nt][0] *= cA;
      oa[nt][1] *= cA;
      oa[nt][2] *= cB;
      oa[nt][3] *= cB;
    }

    // O += P V  (A-frags in registers, B-frags via ldmatrix from V^T)
#pragma unroll
    for (int ntp = 0; ntp < 4; ntp++) {
#pragma unroll
      for (int kg = 0; kg < 4; kg++) {
        unsigned b0, b1, b2, b3;
        LDSM4(b0, b1, b2, b3, vAddr + (ntp * 16 * PSTR + kg * 16) * 2);
        unsigned bfA[2] = {b0, b2}, bfB[2] = {b1, b3};
        MMA16(oa[2 * ntp], pf[kg], bfA);
        MMA16(oa[2 * ntp + 1], pf[kg], bfB);
      }
    }
  }

  float iA = 1.f / lA, iB = 1.f / lB;
  __half* outA = &Mha[(size_t)(b * L_SEQ + rA) * D_MODEL + h];
  __half* outB = &Mha[(size_t)(b * L_SEQ + rB) * D_MODEL + h];
#pragma unroll
  for (int nt = 0; nt < 8; nt++) {
    int d0 = nt * 8 + 2 * thr;
    outA[(d0 + 0) * 16] = __float2half_rn(oa[nt][0] * iA);
    outA[(d0 + 1) * 16] = __float2half_rn(oa[nt][1] * iA);
    outB[(d0 + 0) * 16] = __float2half_rn(oa[nt][2] * iB);
    outB[(d0 + 1) * 16] = __float2half_rn(oa[nt][3] * iB);
  }
}

// ---------------------------------------------------------------------------
extern "C" void kernel_launch(void* const* d_in, const int* in_sizes, int n_in,
                              void* d_out, int out_size) {
  const float* q = (const float*)d_in[0];
  const float* k = (const float*)d_in[1];
  const float* v = (const float*)d_in[2];
  const int* mask4 = (const int*)d_in[3];
  const float* Wq = (const float*)d_in[4];
  const float* Wk = (const float*)d_in[5];
  const float* Wv = (const float*)d_in[6];
  const float* Wo = (const float*)d_in[7];
  float* out = (float*)d_out;

  __half *Qh, *Kh, *Vt, *Mh;
  unsigned* Mb;
  cudaGetSymbolAddress((void**)&Qh, g_Qh);
  cudaGetSymbolAddress((void**)&Kh, g_Kh);
  cudaGetSymbolAddress((void**)&Vt, g_Vt);
  cudaGetSymbolAddress((void**)&Mh, g_Mha);
  cudaGetSymbolAddress((void**)&Mb, g_mbits);

  int nwords = B_SZ * L_SEQ * L_SEQ / 32;
  mask_bits_kernel<<<nwords / 256, 256>>>(mask4, Mb);

  dim3 gg(D_MODEL / 128, M_TOT / 128);  // (8, 32)
  gemm_h_kernel<1, 0><<<gg, 256>>>(q, Wq, Qh);
  gemm_h_kernel<2, 0><<<gg, 256>>>(k, Wk, Kh);
  gemm_h_kernel<3, 0><<<gg, 256>>>(v, Wv, Vt);

  int asmem = (4 * KVSZ + 128 * PSTR) * 2;  // 55296 bytes
  cudaFuncSetAttribute(attn_mma_kernel,
                       cudaFuncAttributeMaxDynamicSharedMemorySize, asmem);
  dim3 ag(L_SEQ / 128, NH, B_SZ);  // (16, 16, 2)
  attn_mma_kernel<<<ag, 256, asmem>>>(Qh, Kh, Vt, Mb, Mh);

  gemm_h_kernel<0, 1><<<gg, 256>>>(Mh, Wo, out);
}

// round 9
// speedup vs baseline: 1.6990x; 1.0773x over previous
#include <cuda_runtime.h>
#include <cuda_fp16.h>
#include <math_constants.h>

#define B_SZ 2
#define L_SEQ 2048
#define D_MODEL 1024
#define NH 16
#define DK 64
#define M_TOT (B_SZ * L_SEQ)
#define NEGL2 (-1.44269504e10f)
#define QSCALE (0.125f * 1.442695040888963f)

// Scratch (device globals). All fp16.
__device__ __align__(16) __half g_Qh[B_SZ * NH * L_SEQ * DK];
__device__ __align__(16) __half g_Kh[B_SZ * NH * L_SEQ * DK];
__device__ __align__(16) __half g_Vt[B_SZ * NH * DK * L_SEQ];
__device__ __align__(16) __half g_Mha[M_TOT * D_MODEL];
__device__ unsigned g_mbits[B_SZ * L_SEQ * L_SEQ / 32];
__device__ __align__(16) __half g_x16[3][M_TOT * D_MODEL];
__device__ __align__(16) __half g_w16[4][D_MODEL * D_MODEL];

__device__ __forceinline__ void cpa16(unsigned d, const void* s) {
  asm volatile("cp.async.cg.shared.global [%0], [%1], 16;" :: "r"(d), "l"(s));
}
__device__ __forceinline__ void cpcommit() { asm volatile("cp.async.commit_group;"); }
__device__ __forceinline__ void cpwait0() { asm volatile("cp.async.wait_group 0;"); }
__device__ __forceinline__ float ex2f(float x) {
  float r;
  asm("ex2.approx.ftz.f32 %0, %1;" : "=f"(r) : "f"(x));
  return r;
}
__device__ __forceinline__ unsigned pack2(float a, float b) {
  __half2 h = __floats2half2_rn(a, b);
  return *(unsigned*)&h;
}
#define MMA16(c, a, b)                                                    \
  asm volatile(                                                           \
      "mma.sync.aligned.m16n8k16.row.col.f32.f16.f16.f32 "                \
      "{%0,%1,%2,%3}, {%4,%5,%6,%7}, {%8,%9}, {%0,%1,%2,%3};"             \
      : "+f"((c)[0]), "+f"((c)[1]), "+f"((c)[2]), "+f"((c)[3])            \
      : "r"((a)[0]), "r"((a)[1]), "r"((a)[2]), "r"((a)[3]), "r"((b)[0]),  \
        "r"((b)[1]))
#define LDSM4(r0, r1, r2, r3, addr)                                       \
  asm volatile(                                                           \
      "ldmatrix.sync.aligned.m8n8.x4.shared.b16 {%0,%1,%2,%3}, [%4];"     \
      : "=r"(r0), "=r"(r1), "=r"(r2), "=r"(r3) : "r"(addr))

// ---------------------------------------------------------------------------
__global__ __launch_bounds__(256) void mask_bits_kernel(
    const int* __restrict__ m4, unsigned* __restrict__ out) {
  int w = blockIdx.x * 256 + threadIdx.x;
  const int4* p = (const int4*)m4 + (size_t)w * 8;
  unsigned bits = 0;
#pragma unroll
  for (int j = 0; j < 8; j++) {
    int4 v = p[j];
    bits |= (unsigned)(v.x != 0) << (4 * j + 0);
    bits |= (unsigned)(v.y != 0) << (4 * j + 1);
    bits |= (unsigned)(v.z != 0) << (4 * j + 2);
    bits |= (unsigned)(v.w != 0) << (4 * j + 3);
  }
  out[w] = bits;
}

__global__ __launch_bounds__(256) void cvt16_kernel(
    const float4* __restrict__ in, uint2* __restrict__ out) {
  int i = blockIdx.x * 256 + threadIdx.x;
  float4 v = in[i];
  __half2 a = __floats2half2_rn(v.x, v.y);
  __half2 b = __floats2half2_rn(v.z, v.w);
  out[i] = make_uint2(*(unsigned*)&a, *(unsigned*)&b);
}

// ---------------------------------------------------------------------------
// FP16 GEMM, cp.async double-buffered, pre-converted fp16 operands.
// C[m,n] = sum_k A[m,k]*W[n,k]. 128x128 tile, KC=64, 8 warps x (64x32).
// MODE 0: fp32 C[m*1024+n]; MODE 1: Q half*QSCALE [b,h,i,d];
// MODE 2: K half [b,h,i,d]; MODE 3: V half [b,h,d,i].
// ---------------------------------------------------------------------------
#define GSTR 72
#define GT (128 * GSTR)  // halves per tile buffer
template <int MODE>
__global__ __launch_bounds__(256, 2) void gemm_h_kernel(
    const __half* __restrict__ A, const __half* __restrict__ W,
    void* __restrict__ Cv) {
  extern __shared__ __half gsm[];  // [2][GT] A, [2][GT] B
  unsigned sA = (unsigned)__cvta_generic_to_shared(gsm);
  unsigned sB = sA + 2 * GT * 2;

  int tid = threadIdx.x;
  int m0 = blockIdx.y * 128;
  int n0 = blockIdx.x * 128;
  int wid = tid >> 5;
  int lane = tid & 31;
  int warp_m = (wid & 1) * 64;
  int warp_n = (wid >> 1) * 32;
  int grp = lane >> 2;
  int thr = lane & 3;
  int lrow = lane & 15;
  int lcol = (lane >> 4) * 8;

  const __half* Ap = A + (size_t)m0 * D_MODEL;
  const __half* Wp = W + (size_t)n0 * D_MODEL;
  unsigned aAddr = sA + ((warp_m + lrow) * GSTR + lcol) * 2;
  unsigned bAddr = sB + ((warp_n + lrow) * GSTR + lcol) * 2;

  float acc[4][4][4];
#pragma unroll
  for (int i = 0; i < 4; i++)
#pragma unroll
    for (int j = 0; j < 4; j++)
#pragma unroll
      for (int r = 0; r < 4; r++) acc[i][j][r] = 0.f;

#define GLOAD(k0, buf)                                                     \
  {                                                                        \
    _Pragma("unroll") for (int s = 0; s < 4; s++) {                        \
      int idx = tid + s * 256;                                             \
      int r = idx >> 3, ch = (idx & 7) * 8;                                \
      cpa16(sA + ((buf)*GT + r * GSTR + ch) * 2,                           \
            Ap + (size_t)r * D_MODEL + (k0) + ch);                         \
      cpa16(sB + ((buf)*GT + r * GSTR + ch) * 2,                           \
            Wp + (size_t)r * D_MODEL + (k0) + ch);                         \
    }                                                                      \
    cpcommit();                                                            \
  }

  GLOAD(0, 0);
  const int T = D_MODEL / 64;  // 16
  for (int t = 0; t < T; t++) {
    int cur = t & 1;
    cpwait0();
    __syncthreads();
    if (t + 1 < T) GLOAD((t + 1) * 64, cur ^ 1);
    unsigned aB = aAddr + cur * GT * 2;
    unsigned bB = bAddr + cur * GT * 2;
#pragma unroll
    for (int kk = 0; kk < 64; kk += 16) {
      unsigned af[4][4], bf[4][2];
#pragma unroll
      for (int mt = 0; mt < 4; mt++)
        LDSM4(af[mt][0], af[mt][1], af[mt][2], af[mt][3],
              aB + (mt * 16 * GSTR + kk) * 2);
#pragma unroll
      for (int ntp = 0; ntp < 2; ntp++) {
        unsigned b0, b1, b2, b3;
        LDSM4(b0, b1, b2, b3, bB + (ntp * 16 * GSTR + kk) * 2);
        bf[2 * ntp][0] = b0;
        bf[2 * ntp][1] = b2;
        bf[2 * ntp + 1][0] = b1;
        bf[2 * ntp + 1][1] = b3;
      }
#pragma unroll
      for (int mt = 0; mt < 4; mt++)
#pragma unroll
        for (int nt = 0; nt < 4; nt++) MMA16(acc[mt][nt], af[mt], bf[nt]);
    }
  }

#pragma unroll
  for (int mt = 0; mt < 4; mt++) {
#pragma unroll
    for (int nt = 0; nt < 4; nt++) {
      int row = m0 + warp_m + mt * 16 + grp;
      int col = n0 + warp_n + nt * 8 + thr * 2;
      float* c = acc[mt][nt];
      if (MODE == 0) {
        float* C = (float*)Cv;
        *(float2*)&C[(size_t)row * D_MODEL + col] = make_float2(c[0], c[1]);
        *(float2*)&C[(size_t)(row + 8) * D_MODEL + col] = make_float2(c[2], c[3]);
      } else {
        __half* C = (__half*)Cv;
#pragma unroll
        for (int e = 0; e < 4; e++) {
          int r = row + (e >> 1) * 8;
          int n = col + (e & 1);
          int b = r >> 11;
          int ii = r & (L_SEQ - 1);
          int h = n & 15;
          int d = n >> 4;
          __half u = __float2half_rn(MODE == 1 ? c[e] * QSCALE : c[e]);
          if (MODE == 3)
            C[((((size_t)b * NH + h) * DK) + d) * L_SEQ + ii] = u;
          else
            C[((((size_t)b * NH + h) * L_SEQ) + ii) * DK + d] = u;
        }
      }
    }
  }
}

// ---------------------------------------------------------------------------
// FP16 flash attention (round-7 version, unchanged).
// ---------------------------------------------------------------------------
#define PSTR 72
#define KVSZ (64 * PSTR)
__global__ __launch_bounds__(256) void attn_mma_kernel(
    const __half* __restrict__ Qh, const __half* __restrict__ Kh,
    const __half* __restrict__ Vt, const unsigned* __restrict__ mbits,
    __half* __restrict__ Mha) {
  extern __shared__ __half smh[];
  __half* Ps = smh + 4 * KVSZ;
  unsigned sbase = (unsigned)__cvta_generic_to_shared(smh);

  int tid = threadIdx.x;
  int w = tid >> 5;
  int lane = tid & 31;
  int grp = lane >> 2;
  int thr = lane & 3;
  int lrow = lane & 15;
  int lcol = (lane >> 4) * 8;
  int i0 = blockIdx.x * 128;
  int h = blockIdx.y;
  int b = blockIdx.z;
  int bh = b * NH + h;
  const __half* Qb = Qh + (size_t)bh * L_SEQ * DK;
  const __half* Kb = Kh + (size_t)bh * L_SEQ * DK;
  const __half* Vb = Vt + (size_t)bh * DK * L_SEQ;

#define KV_ISSUE(o0, buf)                                                  \
  {                                                                        \
    unsigned kbb = sbase + (buf)*2 * KVSZ * 2;                             \
    unsigned vbb = kbb + KVSZ * 2;                                         \
    _Pragma("unroll") for (int s = 0; s < 2; s++) {                        \
      int idx = tid + s * 256;                                             \
      int r = idx >> 3, ch = (idx & 7) * 8;                                \
      cpa16(kbb + (r * PSTR + ch) * 2, Kb + (size_t)((o0) + r) * DK + ch); \
      cpa16(vbb + (r * PSTR + ch) * 2, Vb + (size_t)r * L_SEQ + (o0) + ch); \
    }                                                                      \
    cpcommit();                                                            \
  }

  KV_ISSUE(0, 0);

#pragma unroll
  for (int it = 0; it < 4; it++) {
    int idx = tid + it * 256;
    int r = idx >> 3, ch = (idx & 7) * 8;
    *(uint4*)&Ps[r * PSTR + ch] = *(const uint4*)&Qb[(size_t)(i0 + r) * DK + ch];
  }
  __syncthreads();

  int rbase = w * 16;
  unsigned Qf[4][4];
#pragma unroll
  for (int kg = 0; kg < 4; kg++) {
    Qf[kg][0] = *(const unsigned*)&Ps[(rbase + grp) * PSTR + kg * 16 + 2 * thr];
    Qf[kg][1] = *(const unsigned*)&Ps[(rbase + grp + 8) * PSTR + kg * 16 + 2 * thr];
    Qf[kg][2] = *(const unsigned*)&Ps[(rbase + grp) * PSTR + kg * 16 + 2 * thr + 8];
    Qf[kg][3] = *(const unsigned*)&Ps[(rbase + grp + 8) * PSTR + kg * 16 + 2 * thr + 8];
  }
  __syncthreads();

  int rA = i0 + rbase + grp;
  int rB = rA + 8;
  const unsigned long long* mbA =
      (const unsigned long long*)mbits + (size_t)(b * L_SEQ + rA) * (L_SEQ / 64);
  const unsigned long long* mbB =
      (const unsigned long long*)mbits + (size_t)(b * L_SEQ + rB) * (L_SEQ / 64);

  float mA = -CUDART_INF_F, mB = -CUDART_INF_F;
  float lA = 0.f, lB = 0.f;
  float oa[8][4];
#pragma unroll
  for (int nt = 0; nt < 8; nt++)
#pragma unroll
    for (int e = 0; e < 4; e++) oa[nt][e] = 0.f;

  const int NT = L_SEQ / 64;
  for (int ot = 0; ot < NT; ot++) {
    int cur = ot & 1;
    unsigned long long mWa = mbA[ot];
    unsigned long long mWb = mbB[ot];
    cpwait0();
    __syncthreads();
    if (ot + 1 < NT) KV_ISSUE((ot + 1) * 64, cur ^ 1);
    unsigned kAddr = sbase + cur * 2 * KVSZ * 2 + (lrow * PSTR + lcol) * 2;
    unsigned vAddr = kAddr + KVSZ * 2;

    float sa[8][4];
#pragma unroll
    for (int nt = 0; nt < 8; nt++)
      sa[nt][0] = sa[nt][1] = sa[nt][2] = sa[nt][3] = 0.f;
#pragma unroll
    for (int ntp = 0; ntp < 4; ntp++) {
#pragma unroll
      for (int kg = 0; kg < 4; kg++) {
        unsigned b0, b1, b2, b3;
        LDSM4(b0, b1, b2, b3, kAddr + (ntp * 16 * PSTR + kg * 16) * 2);
        unsigned bfA[2] = {b0, b2}, bfB[2] = {b1, b3};
        MMA16(sa[2 * ntp], Qf[kg], bfA);
        MMA16(sa[2 * ntp + 1], Qf[kg], bfB);
      }
    }

    float mxA = -CUDART_INF_F, mxB = -CUDART_INF_F;
#pragma unroll
    for (int nt = 0; nt < 8; nt++) {
      int c0 = nt * 8 + 2 * thr;
      if ((mWa >> c0) & 1ull) sa[nt][0] = NEGL2;
      if ((mWa >> (c0 + 1)) & 1ull) sa[nt][1] = NEGL2;
      if ((mWb >> c0) & 1ull) sa[nt][2] = NEGL2;
      if ((mWb >> (c0 + 1)) & 1ull) sa[nt][3] = NEGL2;
      mxA = fmaxf(mxA, fmaxf(sa[nt][0], sa[nt][1]));
      mxB = fmaxf(mxB, fmaxf(sa[nt][2], sa[nt][3]));
    }
    mxA = fmaxf(mxA, __shfl_xor_sync(0xffffffffu, mxA, 1));
    mxA = fmaxf(mxA, __shfl_xor_sync(0xffffffffu, mxA, 2));
    mxB = fmaxf(mxB, __shfl_xor_sync(0xffffffffu, mxB, 1));
    mxB = fmaxf(mxB, __shfl_xor_sync(0xffffffffu, mxB, 2));

    float nmA = fmaxf(mA, mxA), nmB = fmaxf(mB, mxB);
    float cA = ex2f(mA - nmA), cB = ex2f(mB - nmB);
    float sumA = 0.f, sumB = 0.f;
    unsigned pf[4][4];
#pragma unroll
    for (int nt = 0; nt < 8; nt++) {
      float p0 = ex2f(sa[nt][0] - nmA);
      float p1 = ex2f(sa[nt][1] - nmA);
      float p2 = ex2f(sa[nt][2] - nmB);
      float p3 = ex2f(sa[nt][3] - nmB);
      sumA += p0 + p1;
      sumB += p2 + p3;
      int kg = nt >> 1;
      if ((nt & 1) == 0) {
        pf[kg][0] = pack2(p0, p1);
        pf[kg][1] = pack2(p2, p3);
      } else {
        pf[kg][2] = pack2(p0, p1);
        pf[kg][3] = pack2(p2, p3);
      }
    }
    sumA += __shfl_xor_sync(0xffffffffu, sumA, 1);
    sumA += __shfl_xor_sync(0xffffffffu, sumA, 2);
    sumB += __shfl_xor_sync(0xffffffffu, sumB, 1);
    sumB += __shfl_xor_sync(0xffffffffu, sumB, 2);
    lA = lA * cA + sumA;
    lB = lB * cB + sumB;
    mA = nmA;
    mB = nmB;

#pragma unroll
    for (int nt = 0; nt < 8; nt++) {
      oa[nt][0] *= cA;
      oa[nt][1] *= cA;
      oa[nt][2] *= cB;
      oa[nt][3] *= cB;
    }

#pragma unroll
    for (int ntp = 0; ntp < 4; ntp++) {
#pragma unroll
      for (int kg = 0; kg < 4; kg++) {
        unsigned b0, b1, b2, b3;
        LDSM4(b0, b1, b2, b3, vAddr + (ntp * 16 * PSTR + kg * 16) * 2);
        unsigned bfA[2] = {b0, b2}, bfB[2] = {b1, b3};
        MMA16(oa[2 * ntp], pf[kg], bfA);
        MMA16(oa[2 * ntp + 1], pf[kg], bfB);
      }
    }
  }

  float iA = 1.f / lA, iB = 1.f / lB;
  __half* outA = &Mha[(size_t)(b * L_SEQ + rA) * D_MODEL + h];
  __half* outB = &Mha[(size_t)(b * L_SEQ + rB) * D_MODEL + h];
#pragma unroll
  for (int nt = 0; nt < 8; nt++) {
    int d0 = nt * 8 + 2 * thr;
    outA[(d0 + 0) * 16] = __float2half_rn(oa[nt][0] * iA);
    outA[(d0 + 1) * 16] = __float2half_rn(oa[nt][1] * iA);
    outB[(d0 + 0) * 16] = __float2half_rn(oa[nt][2] * iB);
    outB[(d0 + 1) * 16] = __float2half_rn(oa[nt][3] * iB);
  }
}

// ---------------------------------------------------------------------------
extern "C" void kernel_launch(void* const* d_in, const int* in_sizes, int n_in,
                              void* d_out, int out_size) {
  const float* q = (const float*)d_in[0];
  const float* k = (const float*)d_in[1];
  const float* v = (const float*)d_in[2];
  const int* mask4 = (const int*)d_in[3];
  const float* Ws[4] = {(const float*)d_in[4], (const float*)d_in[5],
                        (const float*)d_in[6], (const float*)d_in[7]};
  float* out = (float*)d_out;

  __half *Qh, *Kh, *Vt, *Mh, *X16, *W16;
  unsigned* Mb;
  cudaGetSymbolAddress((void**)&Qh, g_Qh);
  cudaGetSymbolAddress((void**)&Kh, g_Kh);
  cudaGetSymbolAddress((void**)&Vt, g_Vt);
  cudaGetSymbolAddress((void**)&Mh, g_Mha);
  cudaGetSymbolAddress((void**)&Mb, g_mbits);
  cudaGetSymbolAddress((void**)&X16, g_x16);
  cudaGetSymbolAddress((void**)&W16, g_w16);

  int nwords = B_SZ * L_SEQ * L_SEQ / 32;
  mask_bits_kernel<<<nwords / 256, 256>>>(mask4, Mb);

  int nbig = M_TOT * D_MODEL / 4 / 256;  // 4096
  int nw = D_MODEL * D_MODEL / 4 / 256;  // 1024
  cvt16_kernel<<<nbig, 256>>>((const float4*)q, (uint2*)(X16 + 0ull * M_TOT * D_MODEL));
  cvt16_kernel<<<nbig, 256>>>((const float4*)k, (uint2*)(X16 + 1ull * M_TOT * D_MODEL));
  cvt16_kernel<<<nbig, 256>>>((const float4*)v, (uint2*)(X16 + 2ull * M_TOT * D_MODEL));
  for (int i = 0; i < 4; i++)
    cvt16_kernel<<<nw, 256>>>((const float4*)Ws[i],
                              (uint2*)(W16 + (size_t)i * D_MODEL * D_MODEL));

  int gsmem = 4 * GT * 2;  // 73728 bytes
  cudaFuncSetAttribute(gemm_h_kernel<0>, cudaFuncAttributeMaxDynamicSharedMemorySize, gsmem);
  cudaFuncSetAttribute(gemm_h_kernel<1>, cudaFuncAttributeMaxDynamicSharedMemorySize, gsmem);
  cudaFuncSetAttribute(gemm_h_kernel<2>, cudaFuncAttributeMaxDynamicSharedMemorySize, gsmem);
  cudaFuncSetAttribute(gemm_h_kernel<3>, cudaFuncAttributeMaxDynamicSharedMemorySize, gsmem);

  dim3 gg(D_MODEL / 128, M_TOT / 128);  // (8, 32)
  gemm_h_kernel<1><<<gg, 256, gsmem>>>(X16 + 0ull * M_TOT * D_MODEL,
                                       W16 + 0ull * D_MODEL * D_MODEL, Qh);
  gemm_h_kernel<2><<<gg, 256, gsmem>>>(X16 + 1ull * M_TOT * D_MODEL,
                                       W16 + 1ull * D_MODEL * D_MODEL, Kh);
  gemm_h_kernel<3><<<gg, 256, gsmem>>>(X16 + 2ull * M_TOT * D_MODEL,
                                       W16 + 2ull * D_MODEL * D_MODEL, Vt);

  int asmem = (4 * KVSZ + 128 * PSTR) * 2;  // 55296
  cudaFuncSetAttribute(attn_mma_kernel,
                       cudaFuncAttributeMaxDynamicSharedMemorySize, asmem);
  dim3 ag(L_SEQ / 128, NH, B_SZ);
  attn_mma_kernel<<<ag, 256, asmem>>>(Qh, Kh, Vt, Mb, Mh);

  gemm_h_kernel<0><<<gg, 256, gsmem>>>(Mh, W16 + 3ull * D_MODEL * D_MODEL, out);
}

// round 10
// speedup vs baseline: 1.7909x; 1.0541x over previous
#include <cuda_runtime.h>
#include <cuda_fp16.h>
#include <math_constants.h>

#define B_SZ 2
#define L_SEQ 2048
#define D_MODEL 1024
#define NH 16
#define DK 64
#define M_TOT (B_SZ * L_SEQ)
#define NEGL2 (-1.44269504e10f)
#define QSCALE (0.125f * 1.442695040888963f)

// Scratch (device globals). All fp16.
__device__ __align__(16) __half g_Qh[B_SZ * NH * L_SEQ * DK];
__device__ __align__(16) __half g_Kh[B_SZ * NH * L_SEQ * DK];
__device__ __align__(16) __half g_Vt[B_SZ * NH * DK * L_SEQ];
__device__ __align__(16) __half g_Mha[M_TOT * D_MODEL];
__device__ unsigned g_mbits[B_SZ * L_SEQ * L_SEQ / 32];
__device__ __align__(16) __half g_x16[3][M_TOT * D_MODEL];
__device__ __align__(16) __half g_w16[4][D_MODEL * D_MODEL];

__device__ __forceinline__ void cpa16(unsigned d, const void* s) {
  asm volatile("cp.async.cg.shared.global [%0], [%1], 16;" :: "r"(d), "l"(s));
}
__device__ __forceinline__ void cpcommit() { asm volatile("cp.async.commit_group;"); }
__device__ __forceinline__ void cpwait0() { asm volatile("cp.async.wait_group 0;"); }
__device__ __forceinline__ float ex2f(float x) {
  float r;
  asm("ex2.approx.ftz.f32 %0, %1;" : "=f"(r) : "f"(x));
  return r;
}
__device__ __forceinline__ unsigned pack2(float a, float b) {
  __half2 h = __floats2half2_rn(a, b);
  return *(unsigned*)&h;
}
#define MMA16(c, a, b)                                                    \
  asm volatile(                                                           \
      "mma.sync.aligned.m16n8k16.row.col.f32.f16.f16.f32 "                \
      "{%0,%1,%2,%3}, {%4,%5,%6,%7}, {%8,%9}, {%0,%1,%2,%3};"             \
      : "+f"((c)[0]), "+f"((c)[1]), "+f"((c)[2]), "+f"((c)[3])            \
      : "r"((a)[0]), "r"((a)[1]), "r"((a)[2]), "r"((a)[3]), "r"((b)[0]),  \
        "r"((b)[1]))
#define LDSM4(r0, r1, r2, r3, addr)                                       \
  asm volatile(                                                           \
      "ldmatrix.sync.aligned.m8n8.x4.shared.b16 {%0,%1,%2,%3}, [%4];"     \
      : "=r"(r0), "=r"(r1), "=r"(r2), "=r"(r3) : "r"(addr))

// ---------------------------------------------------------------------------
__global__ __launch_bounds__(256) void mask_bits_kernel(
    const int* __restrict__ m4, unsigned* __restrict__ out) {
  int w = blockIdx.x * 256 + threadIdx.x;
  const int4* p = (const int4*)m4 + (size_t)w * 8;
  unsigned bits = 0;
#pragma unroll
  for (int j = 0; j < 8; j++) {
    int4 v = p[j];
    bits |= (unsigned)(v.x != 0) << (4 * j + 0);
    bits |= (unsigned)(v.y != 0) << (4 * j + 1);
    bits |= (unsigned)(v.z != 0) << (4 * j + 2);
    bits |= (unsigned)(v.w != 0) << (4 * j + 3);
  }
  out[w] = bits;
}

// Fused conversions: y selects segment
__global__ __launch_bounds__(256) void cvt16_in_kernel(
    const float4* __restrict__ q, const float4* __restrict__ k,
    const float4* __restrict__ v, uint2* __restrict__ out) {
  int y = blockIdx.y;
  const float4* in = (y == 0) ? q : (y == 1) ? k : v;
  int i = blockIdx.x * 256 + threadIdx.x;
  float4 f = in[i];
  __half2 a = __floats2half2_rn(f.x, f.y);
  __half2 b = __floats2half2_rn(f.z, f.w);
  out[(size_t)y * (M_TOT * D_MODEL / 4) + i] =
      make_uint2(*(unsigned*)&a, *(unsigned*)&b);
}
__global__ __launch_bounds__(256) void cvt16_w_kernel(
    const float4* __restrict__ w0, const float4* __restrict__ w1,
    const float4* __restrict__ w2, const float4* __restrict__ w3,
    uint2* __restrict__ out) {
  int y = blockIdx.y;
  const float4* in = (y == 0) ? w0 : (y == 1) ? w1 : (y == 2) ? w2 : w3;
  int i = blockIdx.x * 256 + threadIdx.x;
  float4 f = in[i];
  __half2 a = __floats2half2_rn(f.x, f.y);
  __half2 b = __floats2half2_rn(f.z, f.w);
  out[(size_t)y * (D_MODEL * D_MODEL / 4) + i] =
      make_uint2(*(unsigned*)&a, *(unsigned*)&b);
}

// ---------------------------------------------------------------------------
// FP16 GEMM, 128(M) x 256(N) CTA tile, KC=64, cp.async double-buffered.
// 8 warps x (64x64): mt<4, nt<8 m16n8k16 tiles. 4 MMA per LDSM.
// QKV variant: grid.z=0,1,2 -> Q(scale,[b,h,i,d]) / K([b,h,i,d]) / V([b,h,d,i])
// OUT variant: fp32 C[m*1024+n]
// ---------------------------------------------------------------------------
#define GSTR 72
#define AT (128 * GSTR)
#define BT (256 * GSTR)

#define GEMM_PRE()                                                         \
  extern __shared__ __half gsm[];                                          \
  unsigned sA = (unsigned)__cvta_generic_to_shared(gsm);                   \
  unsigned sB = sA + 2 * AT * 2;                                           \
  int tid = threadIdx.x;                                                   \
  int m0 = blockIdx.y * 128;                                               \
  int n0 = blockIdx.x * 256;                                               \
  int wid = tid >> 5;                                                      \
  int lane = tid & 31;                                                     \
  int warp_m = (wid & 1) * 64;                                             \
  int warp_n = (wid >> 1) * 64;                                            \
  int grp = lane >> 2;                                                     \
  int thr = lane & 3;                                                      \
  int lrow = lane & 15;                                                    \
  int lcol = (lane >> 4) * 8;                                              \
  unsigned aAddr = sA + ((warp_m + lrow) * GSTR + lcol) * 2;               \
  unsigned bAddr = sB + ((warp_n + lrow) * GSTR + lcol) * 2;               \
  float acc[4][8][4];                                                      \
  _Pragma("unroll") for (int i = 0; i < 4; i++)                            \
  _Pragma("unroll") for (int j = 0; j < 8; j++)                            \
  _Pragma("unroll") for (int r = 0; r < 4; r++) acc[i][j][r] = 0.f;

#define GLOAD(k0, buf)                                                     \
  {                                                                        \
    _Pragma("unroll") for (int s = 0; s < 4; s++) {                        \
      int idx = tid + s * 256;                                             \
      int r = idx >> 3, ch = (idx & 7) * 8;                                \
      cpa16(sA + ((buf)*AT + r * GSTR + ch) * 2,                           \
            Ap + (size_t)r * D_MODEL + (k0) + ch);                         \
    }                                                                      \
    _Pragma("unroll") for (int s = 0; s < 8; s++) {                        \
      int idx = tid + s * 256;                                             \
      int r = idx >> 3, ch = (idx & 7) * 8;                                \
      cpa16(sB + ((buf)*BT + r * GSTR + ch) * 2,                           \
            Wp + (size_t)r * D_MODEL + (k0) + ch);                         \
    }                                                                      \
    cpcommit();                                                            \
  }

#define GEMM_MAIN()                                                        \
  GLOAD(0, 0);                                                             \
  for (int t = 0; t < D_MODEL / 64; t++) {                                 \
    int cur = t & 1;                                                       \
    cpwait0();                                                             \
    __syncthreads();                                                       \
    if (t + 1 < D_MODEL / 64) GLOAD((t + 1) * 64, cur ^ 1);                \
    unsigned aB = aAddr + cur * AT * 2;                                    \
    unsigned bB = bAddr + cur * BT * 2;                                    \
    _Pragma("unroll") for (int kk = 0; kk < 64; kk += 16) {                \
      unsigned af[4][4], bf[8][2];                                         \
      _Pragma("unroll") for (int mt = 0; mt < 4; mt++)                     \
        LDSM4(af[mt][0], af[mt][1], af[mt][2], af[mt][3],                  \
              aB + (mt * 16 * GSTR + kk) * 2);                             \
      _Pragma("unroll") for (int ntp = 0; ntp < 4; ntp++) {                \
        unsigned b0, b1, b2, b3;                                           \
        LDSM4(b0, b1, b2, b3, bB + (ntp * 16 * GSTR + kk) * 2);            \
        bf[2 * ntp][0] = b0;                                               \
        bf[2 * ntp][1] = b2;                                               \
        bf[2 * ntp + 1][0] = b1;                                           \
        bf[2 * ntp + 1][1] = b3;                                           \
      }                                                                    \
      _Pragma("unroll") for (int mt = 0; mt < 4; mt++)                     \
      _Pragma("unroll") for (int nt = 0; nt < 8; nt++)                     \
        MMA16(acc[mt][nt], af[mt], bf[nt]);                                \
    }                                                                      \
  }

__global__ __launch_bounds__(256, 1) void gemm_qkv_kernel(
    const __half* __restrict__ X, const __half* __restrict__ Wb) {
  int z = blockIdx.z;
  const __half* Ap = X + (size_t)z * M_TOT * D_MODEL + (size_t)blockIdx.y * 128 * D_MODEL;
  const __half* Wp = Wb + (size_t)z * D_MODEL * D_MODEL + (size_t)blockIdx.x * 256 * D_MODEL;
  GEMM_PRE();
  GEMM_MAIN();
  __half* C = (z == 0) ? g_Qh : (z == 1) ? g_Kh : g_Vt;
#pragma unroll
  for (int mt = 0; mt < 4; mt++) {
#pragma unroll
    for (int nt = 0; nt < 8; nt++) {
      int row = m0 + warp_m + mt * 16 + grp;
      int col = n0 + warp_n + nt * 8 + thr * 2;
      float* c = acc[mt][nt];
#pragma unroll
      for (int e = 0; e < 4; e++) {
        int r = row + (e >> 1) * 8;
        int n = col + (e & 1);
        int b = r >> 11;
        int ii = r & (L_SEQ - 1);
        int h = n & 15;
        int d = n >> 4;
        __half u = __float2half_rn(z == 0 ? c[e] * QSCALE : c[e]);
        if (z == 2)
          C[((((size_t)b * NH + h) * DK) + d) * L_SEQ + ii] = u;
        else
          C[((((size_t)b * NH + h) * L_SEQ) + ii) * DK + d] = u;
      }
    }
  }
}

__global__ __launch_bounds__(256, 1) void gemm_out_kernel(
    const __half* __restrict__ A, const __half* __restrict__ W,
    float* __restrict__ C) {
  const __half* Ap = A + (size_t)blockIdx.y * 128 * D_MODEL;
  const __half* Wp = W + (size_t)blockIdx.x * 256 * D_MODEL;
  GEMM_PRE();
  GEMM_MAIN();
#pragma unroll
  for (int mt = 0; mt < 4; mt++) {
#pragma unroll
    for (int nt = 0; nt < 8; nt++) {
      int row = m0 + warp_m + mt * 16 + grp;
      int col = n0 + warp_n + nt * 8 + thr * 2;
      float* c = acc[mt][nt];
      *(float2*)&C[(size_t)row * D_MODEL + col] = make_float2(c[0], c[1]);
      *(float2*)&C[(size_t)(row + 8) * D_MODEL + col] = make_float2(c[2], c[3]);
    }
  }
}

// ---------------------------------------------------------------------------
// FP16 flash attention (unchanged from round 9).
// ---------------------------------------------------------------------------
#define PSTR 72
#define KVSZ (64 * PSTR)
__global__ __launch_bounds__(256) void attn_mma_kernel(
    const __half* __restrict__ Qh, const __half* __restrict__ Kh,
    const __half* __restrict__ Vt, const unsigned* __restrict__ mbits,
    __half* __restrict__ Mha) {
  extern __shared__ __half smh[];
  __half* Ps = smh + 4 * KVSZ;
  unsigned sbase = (unsigned)__cvta_generic_to_shared(smh);

  int tid = threadIdx.x;
  int w = tid >> 5;
  int lane = tid & 31;
  int grp = lane >> 2;
  int thr = lane & 3;
  int lrow = lane & 15;
  int lcol = (lane >> 4) * 8;
  int i0 = blockIdx.x * 128;
  int h = blockIdx.y;
  int b = blockIdx.z;
  int bh = b * NH + h;
  const __half* Qb = Qh + (size_t)bh * L_SEQ * DK;
  const __half* Kb = Kh + (size_t)bh * L_SEQ * DK;
  const __half* Vb = Vt + (size_t)bh * DK * L_SEQ;

#define KV_ISSUE(o0, buf)                                                  \
  {                                                                        \
    unsigned kbb = sbase + (buf)*2 * KVSZ * 2;                             \
    unsigned vbb = kbb + KVSZ * 2;                                         \
    _Pragma("unroll") for (int s = 0; s < 2; s++) {                        \
      int idx = tid + s * 256;                                             \
      int r = idx >> 3, ch = (idx & 7) * 8;                                \
      cpa16(kbb + (r * PSTR + ch) * 2, Kb + (size_t)((o0) + r) * DK + ch); \
      cpa16(vbb + (r * PSTR + ch) * 2, Vb + (size_t)r * L_SEQ + (o0) + ch); \
    }                                                                      \
    cpcommit();                                                            \
  }

  KV_ISSUE(0, 0);

#pragma unroll
  for (int it = 0; it < 4; it++) {
    int idx = tid + it * 256;
    int r = idx >> 3, ch = (idx & 7) * 8;
    *(uint4*)&Ps[r * PSTR + ch] = *(const uint4*)&Qb[(size_t)(i0 + r) * DK + ch];
  }
  __syncthreads();

  int rbase = w * 16;
  unsigned Qf[4][4];
#pragma unroll
  for (int kg = 0; kg < 4; kg++) {
    Qf[kg][0] = *(const unsigned*)&Ps[(rbase + grp) * PSTR + kg * 16 + 2 * thr];
    Qf[kg][1] = *(const unsigned*)&Ps[(rbase + grp + 8) * PSTR + kg * 16 + 2 * thr];
    Qf[kg][2] = *(const unsigned*)&Ps[(rbase + grp) * PSTR + kg * 16 + 2 * thr + 8];
    Qf[kg][3] = *(const unsigned*)&Ps[(rbase + grp + 8) * PSTR + kg * 16 + 2 * thr + 8];
  }
  __syncthreads();

  int rA = i0 + rbase + grp;
  int rB = rA + 8;
  const unsigned long long* mbA =
      (const unsigned long long*)mbits + (size_t)(b * L_SEQ + rA) * (L_SEQ / 64);
  const unsigned long long* mbB =
      (const unsigned long long*)mbits + (size_t)(b * L_SEQ + rB) * (L_SEQ / 64);

  float mA = -CUDART_INF_F, mB = -CUDART_INF_F;
  float lA = 0.f, lB = 0.f;
  float oa[8][4];
#pragma unroll
  for (int nt = 0; nt < 8; nt++)
#pragma unroll
    for (int e = 0; e < 4; e++) oa[nt][e] = 0.f;

  const int NT = L_SEQ / 64;
  for (int ot = 0; ot < NT; ot++) {
    int cur = ot & 1;
    unsigned long long mWa = mbA[ot];
    unsigned long long mWb = mbB[ot];
    cpwait0();
    __syncthreads();
    if (ot + 1 < NT) KV_ISSUE((ot + 1) * 64, cur ^ 1);
    unsigned kAddr = sbase + cur * 2 * KVSZ * 2 + (lrow * PSTR + lcol) * 2;
    unsigned vAddr = kAddr + KVSZ * 2;

    float sa[8][4];
#pragma unroll
    for (int nt = 0; nt < 8; nt++)
      sa[nt][0] = sa[nt][1] = sa[nt][2] = sa[nt][3] = 0.f;
#pragma unroll
    for (int ntp = 0; ntp < 4; ntp++) {
#pragma unroll
      for (int kg = 0; kg < 4; kg++) {
        unsigned b0, b1, b2, b3;
        LDSM4(b0, b1, b2, b3, kAddr + (ntp * 16 * PSTR + kg * 16) * 2);
        unsigned bfA[2] = {b0, b2}, bfB[2] = {b1, b3};
        MMA16(sa[2 * ntp], Qf[kg], bfA);
        MMA16(sa[2 * ntp + 1], Qf[kg], bfB);
      }
    }

    float mxA = -CUDART_INF_F, mxB = -CUDART_INF_F;
#pragma unroll
    for (int nt = 0; nt < 8; nt++) {
      int c0 = nt * 8 + 2 * thr;
      if ((mWa >> c0) & 1ull) sa[nt][0] = NEGL2;
      if ((mWa >> (c0 + 1)) & 1ull) sa[nt][1] = NEGL2;
      if ((mWb >> c0) & 1ull) sa[nt][2] = NEGL2;
      if ((mWb >> (c0 + 1)) & 1ull) sa[nt][3] = NEGL2;
      mxA = fmaxf(mxA, fmaxf(sa[nt][0], sa[nt][1]));
      mxB = fmaxf(mxB, fmaxf(sa[nt][2], sa[nt][3]));
    }
    mxA = fmaxf(mxA, __shfl_xor_sync(0xffffffffu, mxA, 1));
    mxA = fmaxf(mxA, __shfl_xor_sync(0xffffffffu, mxA, 2));
    mxB = fmaxf(mxB, __shfl_xor_sync(0xffffffffu, mxB, 1));
    mxB = fmaxf(mxB, __shfl_xor_sync(0xffffffffu, mxB, 2));

    float nmA = fmaxf(mA, mxA), nmB = fmaxf(mB, mxB);
    float cA = ex2f(mA - nmA), cB = ex2f(mB - nmB);
    float sumA = 0.f, sumB = 0.f;
    unsigned pf[4][4];
#pragma unroll
    for (int nt = 0; nt < 8; nt++) {
      float p0 = ex2f(sa[nt][0] - nmA);
      float p1 = ex2f(sa[nt][1] - nmA);
      float p2 = ex2f(sa[nt][2] - nmB);
      float p3 = ex2f(sa[nt][3] - nmB);
      sumA += p0 + p1;
      sumB += p2 + p3;
      int kg = nt >> 1;
      if ((nt & 1) == 0) {
        pf[kg][0] = pack2(p0, p1);
        pf[kg][1] = pack2(p2, p3);
      } else {
        pf[kg][2] = pack2(p0, p1);
        pf[kg][3] = pack2(p2, p3);
      }
    }
    sumA += __shfl_xor_sync(0xffffffffu, sumA, 1);
    sumA += __shfl_xor_sync(0xffffffffu, sumA, 2);
    sumB += __shfl_xor_sync(0xffffffffu, sumB, 1);
    sumB += __shfl_xor_sync(0xffffffffu, sumB, 2);
    lA = lA * cA + sumA;
    lB = lB * cB + sumB;
    mA = nmA;
    mB = nmB;

#pragma unroll
    for (int nt = 0; nt < 8; nt++) {
      oa[nt][0] *= cA;
      oa[nt][1] *= cA;
      oa[nt][2] *= cB;
      oa[nt][3] *= cB;
    }

#pragma unroll
    for (int ntp = 0; ntp < 4; ntp++) {
#pragma unroll
      for (int kg = 0; kg < 4; kg++) {
        unsigned b0, b1, b2, b3;
        LDSM4(b0, b1, b2, b3, vAddr + (ntp * 16 * PSTR + kg * 16) * 2);
        unsigned bfA[2] = {b0, b2}, bfB[2] = {b1, b3};
        MMA16(oa[2 * ntp], pf[kg], bfA);
        MMA16(oa[2 * ntp + 1], pf[kg], bfB);
      }
    }
  }

  float iA = 1.f / lA, iB = 1.f / lB;
  __half* outA = &Mha[(size_t)(b * L_SEQ + rA) * D_MODEL + h];
  __half* outB = &Mha[(size_t)(b * L_SEQ + rB) * D_MODEL + h];
#pragma unroll
  for (int nt = 0; nt < 8; nt++) {
    int d0 = nt * 8 + 2 * thr;
    outA[(d0 + 0) * 16] = __float2half_rn(oa[nt][0] * iA);
    outA[(d0 + 1) * 16] = __float2half_rn(oa[nt][1] * iA);
    outB[(d0 + 0) * 16] = __float2half_rn(oa[nt][2] * iB);
    outB[(d0 + 1) * 16] = __float2half_rn(oa[nt][3] * iB);
  }
}

// ---------------------------------------------------------------------------
extern "C" void kernel_launch(void* const* d_in, const int* in_sizes, int n_in,
                              void* d_out, int out_size) {
  const float* q = (const float*)d_in[0];
  const float* k = (const float*)d_in[1];
  const float* v = (const float*)d_in[2];
  const int* mask4 = (const int*)d_in[3];
  float* out = (float*)d_out;

  __half *Qh, *Kh, *Vt, *Mh, *X16, *W16;
  unsigned* Mb;
  cudaGetSymbolAddress((void**)&Qh, g_Qh);
  cudaGetSymbolAddress((void**)&Kh, g_Kh);
  cudaGetSymbolAddress((void**)&Vt, g_Vt);
  cudaGetSymbolAddress((void**)&Mh, g_Mha);
  cudaGetSymbolAddress((void**)&Mb, g_mbits);
  cudaGetSymbolAddress((void**)&X16, g_x16);
  cudaGetSymbolAddress((void**)&W16, g_w16);

  int nwords = B_SZ * L_SEQ * L_SEQ / 32;
  mask_bits_kernel<<<nwords / 256, 256>>>(mask4, Mb);

  dim3 cg1(M_TOT * D_MODEL / 4 / 256, 3);
  cvt16_in_kernel<<<cg1, 256>>>((const float4*)q, (const float4*)k,
                                (const float4*)v, (uint2*)X16);
  dim3 cg2(D_MODEL * D_MODEL / 4 / 256, 4);
  cvt16_w_kernel<<<cg2, 256>>>((const float4*)d_in[4], (const float4*)d_in[5],
                               (const float4*)d_in[6], (const float4*)d_in[7],
                               (uint2*)W16);

  int gsmem = (2 * AT + 2 * BT) * 2;  // 110592 bytes
  cudaFuncSetAttribute(gemm_qkv_kernel, cudaFuncAttributeMaxDynamicSharedMemorySize, gsmem);
  cudaFuncSetAttribute(gemm_out_kernel, cudaFuncAttributeMaxDynamicSharedMemorySize, gsmem);

  dim3 gq(D_MODEL / 256, M_TOT / 128, 3);  // (4, 32, 3)
  gemm_qkv_kernel<<<gq, 256, gsmem>>>(X16, W16);

  int asmem = (4 * KVSZ + 128 * PSTR) * 2;  // 55296
  cudaFuncSetAttribute(attn_mma_kernel,
                       cudaFuncAttributeMaxDynamicSharedMemorySize, asmem);
  dim3 ag(L_SEQ / 128, NH, B_SZ);
  attn_mma_kernel<<<ag, 256, asmem>>>(Qh, Kh, Vt, Mb, Mh);

  dim3 go(D_MODEL / 256, M_TOT / 128);  // (4, 32)
  gemm_out_kernel<<<go, 256, gsmem>>>(Mh, W16 + 3ull * D_MODEL * D_MODEL, out);
}

// round 11
// speedup vs baseline: 2.0587x; 1.1495x over previous
#include <cuda_runtime.h>
#include <cuda_fp16.h>
#include <math_constants.h>

#define B_SZ 2
#define L_SEQ 2048
#define D_MODEL 1024
#define NH 16
#define DK 64
#define M_TOT (B_SZ * L_SEQ)
#define NEGL2 (-1.44269504e10f)
#define QSCALE (0.125f * 1.442695040888963f)

// Scratch (device globals). All fp16.
__device__ __align__(16) __half g_Qh[B_SZ * NH * L_SEQ * DK];
__device__ __align__(16) __half g_Kh[B_SZ * NH * L_SEQ * DK];
__device__ __align__(16) __half g_Vt[B_SZ * NH * DK * L_SEQ];
__device__ __align__(16) __half g_Mha[M_TOT * D_MODEL];  // [m][h*64+d]
__device__ unsigned g_mbits[B_SZ * L_SEQ * L_SEQ / 32];
__device__ __align__(16) __half g_x16[3][M_TOT * D_MODEL];
__device__ __align__(16) __half g_w16[4][D_MODEL * D_MODEL];  // Wq/Wk/Wv row-perm, Wo col-perm

__device__ __forceinline__ void cpa16(unsigned d, const void* s) {
  asm volatile("cp.async.cg.shared.global [%0], [%1], 16;" :: "r"(d), "l"(s));
}
__device__ __forceinline__ void cpcommit() { asm volatile("cp.async.commit_group;"); }
__device__ __forceinline__ void cpwait0() { asm volatile("cp.async.wait_group 0;"); }
__device__ __forceinline__ float ex2f(float x) {
  float r;
  asm("ex2.approx.ftz.f32 %0, %1;" : "=f"(r) : "f"(x));
  return r;
}
__device__ __forceinline__ unsigned pack2(float a, float b) {
  __half2 h = __floats2half2_rn(a, b);
  return *(unsigned*)&h;
}
#define MMA16(c, a, b)                                                    \
  asm volatile(                                                           \
      "mma.sync.aligned.m16n8k16.row.col.f32.f16.f16.f32 "                \
      "{%0,%1,%2,%3}, {%4,%5,%6,%7}, {%8,%9}, {%0,%1,%2,%3};"             \
      : "+f"((c)[0]), "+f"((c)[1]), "+f"((c)[2]), "+f"((c)[3])            \
      : "r"((a)[0]), "r"((a)[1]), "r"((a)[2]), "r"((a)[3]), "r"((b)[0]),  \
        "r"((b)[1]))
#define LDSM4(r0, r1, r2, r3, addr)                                       \
  asm volatile(                                                           \
      "ldmatrix.sync.aligned.m8n8.x4.shared.b16 {%0,%1,%2,%3}, [%4];"     \
      : "=r"(r0), "=r"(r1), "=r"(r2), "=r"(r3) : "r"(addr))

// ---------------------------------------------------------------------------
__global__ __launch_bounds__(256) void mask_bits_kernel(
    const int* __restrict__ m4, unsigned* __restrict__ out) {
  int w = blockIdx.x * 256 + threadIdx.x;
  const int4* p = (const int4*)m4 + (size_t)w * 8;
  unsigned bits = 0;
#pragma unroll
  for (int j = 0; j < 8; j++) {
    int4 v = p[j];
    bits |= (unsigned)(v.x != 0) << (4 * j + 0);
    bits |= (unsigned)(v.y != 0) << (4 * j + 1);
    bits |= (unsigned)(v.z != 0) << (4 * j + 2);
    bits |= (unsigned)(v.w != 0) << (4 * j + 3);
  }
  out[w] = bits;
}

__global__ __launch_bounds__(256) void cvt16_in_kernel(
    const float4* __restrict__ q, const float4* __restrict__ k,
    const float4* __restrict__ v, uint2* __restrict__ out) {
  int y = blockIdx.y;
  const float4* in = (y == 0) ? q : (y == 1) ? k : v;
  int i = blockIdx.x * 256 + threadIdx.x;
  float4 f = in[i];
  __half2 a = __floats2half2_rn(f.x, f.y);
  __half2 b = __floats2half2_rn(f.z, f.w);
  out[(size_t)y * (M_TOT * D_MODEL / 4) + i] =
      make_uint2(*(unsigned*)&a, *(unsigned*)&b);
}

// Wq/Wk/Wv: fp32->fp16 with ROW permutation p = (n&15)*64 + (n>>4).
// One block per source row; coalesced read + coalesced write.
__global__ __launch_bounds__(256) void cvtw_qkv_kernel(
    const float4* __restrict__ w0, const float4* __restrict__ w1,
    const float4* __restrict__ w2, uint2* __restrict__ out) {
  int y = blockIdx.y;
  const float4* in = (y == 0) ? w0 : (y == 1) ? w1 : w2;
  int n = blockIdx.x;
  int p = (n & 15) * 64 + (n >> 4);
  int i = threadIdx.x;  // 256 threads, 256 float4 per row
  float4 f = in[(size_t)n * 256 + i];
  __half2 a = __floats2half2_rn(f.x, f.y);
  __half2 b = __floats2half2_rn(f.z, f.w);
  out[(size_t)y * (D_MODEL * D_MODEL / 4) + (size_t)p * 256 + i] =
      make_uint2(*(unsigned*)&a, *(unsigned*)&b);
}

// Wo: fp32->fp16 with COLUMN permutation W'[j,p] = W[j, (p&63)*16 + (p>>6)].
// One block per row; stage row in smem, permuted gather, coalesced write.
__global__ __launch_bounds__(256) void cvtw_o_kernel(
    const float4* __restrict__ w3, uint2* __restrict__ out) {
  __shared__ __half s[D_MODEL];
  int j = blockIdx.x;
  int i = threadIdx.x;
  float4 f = w3[(size_t)j * 256 + i];
  __half2* sp = (__half2*)&s[i * 4];
  sp[0] = __floats2half2_rn(f.x, f.y);
  sp[1] = __floats2half2_rn(f.z, f.w);
  __syncthreads();
  __half o[4];
#pragma unroll
  for (int e = 0; e < 4; e++) {
    int p = i * 4 + e;
    int n = ((p & 63) << 4) | (p >> 6);
    o[e] = s[n];
  }
  out[(size_t)j * 256 + i] = *(uint2*)o;
}

// ---------------------------------------------------------------------------
// FP16 GEMM, 128(M) x 256(N) CTA tile, KC=64, cp.async double-buffered.
// Weights are pre-permuted so output columns are head-major p = h*64+d.
// ---------------------------------------------------------------------------
#define GSTR 72
#define AT (128 * GSTR)
#define BT (256 * GSTR)

#define GEMM_PRE()                                                         \
  extern __shared__ __half gsm[];                                          \
  unsigned sA = (unsigned)__cvta_generic_to_shared(gsm);                   \
  unsigned sB = sA + 2 * AT * 2;                                           \
  int tid = threadIdx.x;                                                   \
  int m0 = blockIdx.y * 128;                                               \
  int n0 = blockIdx.x * 256;                                               \
  int wid = tid >> 5;                                                      \
  int lane = tid & 31;                                                     \
  int warp_m = (wid & 1) * 64;                                             \
  int warp_n = (wid >> 1) * 64;                                            \
  int grp = lane >> 2;                                                     \
  int thr = lane & 3;                                                      \
  int lrow = lane & 15;                                                    \
  int lcol = (lane >> 4) * 8;                                              \
  unsigned aAddr = sA + ((warp_m + lrow) * GSTR + lcol) * 2;               \
  unsigned bAddr = sB + ((warp_n + lrow) * GSTR + lcol) * 2;               \
  float acc[4][8][4];                                                      \
  _Pragma("unroll") for (int i = 0; i < 4; i++)                            \
  _Pragma("unroll") for (int j = 0; j < 8; j++)                            \
  _Pragma("unroll") for (int r = 0; r < 4; r++) acc[i][j][r] = 0.f;

#define GLOAD(k0, buf)                                                     \
  {                                                                        \
    _Pragma("unroll") for (int s = 0; s < 4; s++) {                        \
      int idx = tid + s * 256;                                             \
      int r = idx >> 3, ch = (idx & 7) * 8;                                \
      cpa16(sA + ((buf)*AT + r * GSTR + ch) * 2,                           \
            Ap + (size_t)r * D_MODEL + (k0) + ch);                         \
    }                                                                      \
    _Pragma("unroll") for (int s = 0; s < 8; s++) {                        \
      int idx = tid + s * 256;                                             \
      int r = idx >> 3, ch = (idx & 7) * 8;                                \
      cpa16(sB + ((buf)*BT + r * GSTR + ch) * 2,                           \
            Wp + (size_t)r * D_MODEL + (k0) + ch);                         \
    }                                                                      \
    cpcommit();                                                            \
  }

#define GEMM_MAIN()                                                        \
  GLOAD(0, 0);                                                             \
  for (int t = 0; t < D_MODEL / 64; t++) {                                 \
    int cur = t & 1;                                                       \
    cpwait0();                                                             \
    __syncthreads();                                                       \
    if (t + 1 < D_MODEL / 64) GLOAD((t + 1) * 64, cur ^ 1);                \
    unsigned aB = aAddr + cur * AT * 2;                                    \
    unsigned bB = bAddr + cur * BT * 2;                                    \
    _Pragma("unroll") for (int kk = 0; kk < 64; kk += 16) {                \
      unsigned af[4][4], bf[8][2];                                         \
      _Pragma("unroll") for (int mt = 0; mt < 4; mt++)                     \
        LDSM4(af[mt][0], af[mt][1], af[mt][2], af[mt][3],                  \
              aB + (mt * 16 * GSTR + kk) * 2);                             \
      _Pragma("unroll") for (int ntp = 0; ntp < 4; ntp++) {                \
        unsigned b0, b1, b2, b3;                                           \
        LDSM4(b0, b1, b2, b3, bB + (ntp * 16 * GSTR + kk) * 2);            \
        bf[2 * ntp][0] = b0;                                               \
        bf[2 * ntp][1] = b2;                                               \
        bf[2 * ntp + 1][0] = b1;                                           \
        bf[2 * ntp + 1][1] = b3;                                           \
      }                                                                    \
      _Pragma("unroll") for (int mt = 0; mt < 4; mt++)                     \
      _Pragma("unroll") for (int nt = 0; nt < 8; nt++)                     \
        MMA16(acc[mt][nt], af[mt], bf[nt]);                                \
    }                                                                      \
  }

__global__ __launch_bounds__(256, 1) void gemm_qkv_kernel(
    const __half* __restrict__ X, const __half* __restrict__ Wb) {
  int z = blockIdx.z;
  const __half* Ap = X + (size_t)z * M_TOT * D_MODEL + (size_t)blockIdx.y * 128 * D_MODEL;
  const __half* Wp = Wb + (size_t)z * D_MODEL * D_MODEL + (size_t)blockIdx.x * 256 * D_MODEL;
  GEMM_PRE();
  GEMM_MAIN();
  __half* C = (z == 0) ? g_Qh : (z == 1) ? g_Kh : g_Vt;
  float s = (z == 0) ? QSCALE : 1.0f;
#pragma unroll
  for (int mt = 0; mt < 4; mt++) {
#pragma unroll
    for (int nt = 0; nt < 8; nt++) {
      int row = m0 + warp_m + mt * 16 + grp;
      int p = n0 + warp_n + nt * 8 + thr * 2;
      int h = p >> 6, d = p & 63;
      float* c = acc[mt][nt];
      if (z <= 1) {
        // [b,h,i,d]: contiguous d runs -> __half2 stores
#pragma unroll
        for (int e = 0; e < 2; e++) {
          int r = row + e * 8;
          int b = r >> 11;
          int ii = r & (L_SEQ - 1);
          *(unsigned*)&C[((((size_t)b * NH + h) * L_SEQ) + ii) * DK + d] =
              pack2(c[2 * e] * s, c[2 * e + 1] * s);
        }
      } else {
        // V^T [b,h,d,i]: runs over i
#pragma unroll
        for (int e = 0; e < 4; e++) {
          int r = row + (e >> 1) * 8;
          int b = r >> 11;
          int ii = r & (L_SEQ - 1);
          C[((((size_t)b * NH + h) * DK) + d + (e & 1)) * L_SEQ + ii] =
              __float2half_rn(c[e]);
        }
      }
    }
  }
}

__global__ __launch_bounds__(256, 1) void gemm_out_kernel(
    const __half* __restrict__ A, const __half* __restrict__ W,
    float* __restrict__ C) {
  const __half* Ap = A + (size_t)blockIdx.y * 128 * D_MODEL;
  const __half* Wp = W + (size_t)blockIdx.x * 256 * D_MODEL;
  GEMM_PRE();
  GEMM_MAIN();
#pragma unroll
  for (int mt = 0; mt < 4; mt++) {
#pragma unroll
    for (int nt = 0; nt < 8; nt++) {
      int row = m0 + warp_m + mt * 16 + grp;
      int col = n0 + warp_n + nt * 8 + thr * 2;
      float* c = acc[mt][nt];
      *(float2*)&C[(size_t)row * D_MODEL + col] = make_float2(c[0], c[1]);
      *(float2*)&C[(size_t)(row + 8) * D_MODEL + col] = make_float2(c[2], c[3]);
    }
  }
}

// ---------------------------------------------------------------------------
// FP16 flash attention. Output written head-major: Mha[m][h*64+d].
// ---------------------------------------------------------------------------
#define PSTR 72
#define KVSZ (64 * PSTR)
__global__ __launch_bounds__(256) void attn_mma_kernel(
    const __half* __restrict__ Qh, const __half* __restrict__ Kh,
    const __half* __restrict__ Vt, const unsigned* __restrict__ mbits,
    __half* __restrict__ Mha) {
  extern __shared__ __half smh[];
  __half* Ps = smh + 4 * KVSZ;
  unsigned sbase = (unsigned)__cvta_generic_to_shared(smh);

  int tid = threadIdx.x;
  int w = tid >> 5;
  int lane = tid & 31;
  int grp = lane >> 2;
  int thr = lane & 3;
  int lrow = lane & 15;
  int lcol = (lane >> 4) * 8;
  int i0 = blockIdx.x * 128;
  int h = blockIdx.y;
  int b = blockIdx.z;
  int bh = b * NH + h;
  const __half* Qb = Qh + (size_t)bh * L_SEQ * DK;
  const __half* Kb = Kh + (size_t)bh * L_SEQ * DK;
  const __half* Vb = Vt + (size_t)bh * DK * L_SEQ;

#define KV_ISSUE(o0, buf)                                                  \
  {                                                                        \
    unsigned kbb = sbase + (buf)*2 * KVSZ * 2;                             \
    unsigned vbb = kbb + KVSZ * 2;                                         \
    _Pragma("unroll") for (int s = 0; s < 2; s++) {                        \
      int idx = tid + s * 256;                                             \
      int r = idx >> 3, ch = (idx & 7) * 8;                                \
      cpa16(kbb + (r * PSTR + ch) * 2, Kb + (size_t)((o0) + r) * DK + ch); \
      cpa16(vbb + (r * PSTR + ch) * 2, Vb + (size_t)r * L_SEQ + (o0) + ch); \
    }                                                                      \
    cpcommit();                                                            \
  }

  KV_ISSUE(0, 0);

#pragma unroll
  for (int it = 0; it < 4; it++) {
    int idx = tid + it * 256;
    int r = idx >> 3, ch = (idx & 7) * 8;
    *(uint4*)&Ps[r * PSTR + ch] = *(const uint4*)&Qb[(size_t)(i0 + r) * DK + ch];
  }
  __syncthreads();

  int rbase = w * 16;
  unsigned Qf[4][4];
#pragma unroll
  for (int kg = 0; kg < 4; kg++) {
    Qf[kg][0] = *(const unsigned*)&Ps[(rbase + grp) * PSTR + kg * 16 + 2 * thr];
    Qf[kg][1] = *(const unsigned*)&Ps[(rbase + grp + 8) * PSTR + kg * 16 + 2 * thr];
    Qf[kg][2] = *(const unsigned*)&Ps[(rbase + grp) * PSTR + kg * 16 + 2 * thr + 8];
    Qf[kg][3] = *(const unsigned*)&Ps[(rbase + grp + 8) * PSTR + kg * 16 + 2 * thr + 8];
  }
  __syncthreads();

  int rA = i0 + rbase + grp;
  int rB = rA + 8;
  const unsigned long long* mbA =
      (const unsigned long long*)mbits + (size_t)(b * L_SEQ + rA) * (L_SEQ / 64);
  const unsigned long long* mbB =
      (const unsigned long long*)mbits + (size_t)(b * L_SEQ + rB) * (L_SEQ / 64);

  float mA = -CUDART_INF_F, mB = -CUDART_INF_F;
  float lA = 0.f, lB = 0.f;
  float oa[8][4];
#pragma unroll
  for (int nt = 0; nt < 8; nt++)
#pragma unroll
    for (int e = 0; e < 4; e++) oa[nt][e] = 0.f;

  const int NT = L_SEQ / 64;
  for (int ot = 0; ot < NT; ot++) {
    int cur = ot & 1;
    unsigned long long mWa = mbA[ot];
    unsigned long long mWb = mbB[ot];
    cpwait0();
    __syncthreads();
    if (ot + 1 < NT) KV_ISSUE((ot + 1) * 64, cur ^ 1);
    unsigned kAddr = sbase + cur * 2 * KVSZ * 2 + (lrow * PSTR + lcol) * 2;
    unsigned vAddr = kAddr + KVSZ * 2;

    float sa[8][4];
#pragma unroll
    for (int nt = 0; nt < 8; nt++)
      sa[nt][0] = sa[nt][1] = sa[nt][2] = sa[nt][3] = 0.f;
#pragma unroll
    for (int ntp = 0; ntp < 4; ntp++) {
#pragma unroll
      for (int kg = 0; kg < 4; kg++) {
        unsigned b0, b1, b2, b3;
        LDSM4(b0, b1, b2, b3, kAddr + (ntp * 16 * PSTR + kg * 16) * 2);
        unsigned bfA[2] = {b0, b2}, bfB[2] = {b1, b3};
        MMA16(sa[2 * ntp], Qf[kg], bfA);
        MMA16(sa[2 * ntp + 1], Qf[kg], bfB);
      }
    }

    float mxA = -CUDART_INF_F, mxB = -CUDART_INF_F;
#pragma unroll
    for (int nt = 0; nt < 8; nt++) {
      int c0 = nt * 8 + 2 * thr;
      if ((mWa >> c0) & 1ull) sa[nt][0] = NEGL2;
      if ((mWa >> (c0 + 1)) & 1ull) sa[nt][1] = NEGL2;
      if ((mWb >> c0) & 1ull) sa[nt][2] = NEGL2;
      if ((mWb >> (c0 + 1)) & 1ull) sa[nt][3] = NEGL2;
      mxA = fmaxf(mxA, fmaxf(sa[nt][0], sa[nt][1]));
      mxB = fmaxf(mxB, fmaxf(sa[nt][2], sa[nt][3]));
    }
    mxA = fmaxf(mxA, __shfl_xor_sync(0xffffffffu, mxA, 1));
    mxA = fmaxf(mxA, __shfl_xor_sync(0xffffffffu, mxA, 2));
    mxB = fmaxf(mxB, __shfl_xor_sync(0xffffffffu, mxB, 1));
    mxB = fmaxf(mxB, __shfl_xor_sync(0xffffffffu, mxB, 2));

    float nmA = fmaxf(mA, mxA), nmB = fmaxf(mB, mxB);
    float cA = ex2f(mA - nmA), cB = ex2f(mB - nmB);
    float sumA = 0.f, sumB = 0.f;
    unsigned pf[4][4];
#pragma unroll
    for (int nt = 0; nt < 8; nt++) {
      float p0 = ex2f(sa[nt][0] - nmA);
      float p1 = ex2f(sa[nt][1] - nmA);
      float p2 = ex2f(sa[nt][2] - nmB);
      float p3 = ex2f(sa[nt][3] - nmB);
      sumA += p0 + p1;
      sumB += p2 + p3;
      int kg = nt >> 1;
      if ((nt & 1) == 0) {
        pf[kg][0] = pack2(p0, p1);
        pf[kg][1] = pack2(p2, p3);
      } else {
        pf[kg][2] = pack2(p0, p1);
        pf[kg][3] = pack2(p2, p3);
      }
    }
    sumA += __shfl_xor_sync(0xffffffffu, sumA, 1);
    sumA += __shfl_xor_sync(0xffffffffu, sumA, 2);
    sumB += __shfl_xor_sync(0xffffffffu, sumB, 1);
    sumB += __shfl_xor_sync(0xffffffffu, sumB, 2);
    lA = lA * cA + sumA;
    lB = lB * cB + sumB;
    mA = nmA;
    mB = nmB;

#pragma unroll
    for (int nt = 0; nt < 8; nt++) {
      oa[nt][0] *= cA;
      oa[nt][1] *= cA;
      oa[nt][2] *= cB;
      oa[nt][3] *= cB;
    }

#pragma unroll
    for (int ntp = 0; ntp < 4; ntp++) {
#pragma unroll
      for (int kg = 0; kg < 4; kg++) {
        unsigned b0, b1, b2, b3;
        LDSM4(b0, b1, b2, b3, vAddr + (ntp * 16 * PSTR + kg * 16) * 2);
        unsigned bfA[2] = {b0, b2}, bfB[2] = {b1, b3};
        MMA16(oa[2 * ntp], pf[kg], bfA);
        MMA16(oa[2 * ntp + 1], pf[kg], bfB);
      }
    }
  }

  // Head-major output: Mha[m][h*64+d] -> __half2 stores, quad-contiguous
  float iA = 1.f / lA, iB = 1.f / lB;
  __half* outA = &Mha[(size_t)(b * L_SEQ + rA) * D_MODEL + h * 64];
  __half* outB = &Mha[(size_t)(b * L_SEQ + rB) * D_MODEL + h * 64];
#pragma unroll
  for (int nt = 0; nt < 8; nt++) {
    int d0 = nt * 8 + 2 * thr;
    *(unsigned*)&outA[d0] = pack2(oa[nt][0] * iA, oa[nt][1] * iA);
    *(unsigned*)&outB[d0] = pack2(oa[nt][2] * iB, oa[nt][3] * iB);
  }
}

// ---------------------------------------------------------------------------
extern "C" void kernel_launch(void* const* d_in, const int* in_sizes, int n_in,
                              void* d_out, int out_size) {
  const float* q = (const float*)d_in[0];
  const float* k = (const float*)d_in[1];
  const float* v = (const float*)d_in[2];
  const int* mask4 = (const int*)d_in[3];
  float* out = (float*)d_out;

  __half *Qh, *Kh, *Vt, *Mh, *X16, *W16;
  unsigned* Mb;
  cudaGetSymbolAddress((void**)&Qh, g_Qh);
  cudaGetSymbolAddress((void**)&Kh, g_Kh);
  cudaGetSymbolAddress((void**)&Vt, g_Vt);
  cudaGetSymbolAddress((void**)&Mh, g_Mha);
  cudaGetSymbolAddress((void**)&Mb, g_mbits);
  cudaGetSymbolAddress((void**)&X16, g_x16);
  cudaGetSymbolAddress((void**)&W16, g_w16);

  int nwords = B_SZ * L_SEQ * L_SEQ / 32;
  mask_bits_kernel<<<nwords / 256, 256>>>(mask4, Mb);

  dim3 cg1(M_TOT * D_MODEL / 4 / 256, 3);
  cvt16_in_kernel<<<cg1, 256>>>((const float4*)q, (const float4*)k,
                                (const float4*)v, (uint2*)X16);
  dim3 cgw(D_MODEL, 3);
  cvtw_qkv_kernel<<<cgw, 256>>>((const float4*)d_in[4], (const float4*)d_in[5],
                                (const float4*)d_in[6], (uint2*)W16);
  cvtw_o_kernel<<<D_MODEL, 256>>>((const float4*)d_in[7],
                                  (uint2*)(W16 + 3ull * D_MODEL * D_MODEL));

  int gsmem = (2 * AT + 2 * BT) * 2;  // 110592 bytes
  cudaFuncSetAttribute(gemm_qkv_kernel, cudaFuncAttributeMaxDynamicSharedMemorySize, gsmem);
  cudaFuncSetAttribute(gemm_out_kernel, cudaFuncAttributeMaxDynamicSharedMemorySize, gsmem);

  dim3 gq(D_MODEL / 256, M_TOT / 128, 3);  // (4, 32, 3)
  gemm_qkv_kernel<<<gq, 256, gsmem>>>(X16, W16);

  int asmem = (4 * KVSZ + 128 * PSTR) * 2;  // 55296
  cudaFuncSetAttribute(attn_mma_kernel,
                       cudaFuncAttributeMaxDynamicSharedMemorySize, asmem);
  dim3 ag(L_SEQ / 128, NH, B_SZ);
  attn_mma_kernel<<<ag, 256, asmem>>>(Qh, Kh, Vt, Mb, Mh);

  dim3 go(D_MODEL / 256, M_TOT / 128);  // (4, 32)
  gemm_out_kernel<<<go, 256, gsmem>>>(Mh, W16 + 3ull * D_MODEL * D_MODEL, out);
}

// round 12
// speedup vs baseline: 2.3138x; 1.1239x over previous
#include <cuda_runtime.h>
#include <cuda_fp16.h>
#include <math_constants.h>

#define B_SZ 2
#define L_SEQ 2048
#define D_MODEL 1024
#define NH 16
#define DK 64
#define M_TOT (B_SZ * L_SEQ)
#define NEGL2 (-1.44269504e10f)
#define QSCALE (0.125f * 1.442695040888963f)

// Scratch (device globals). All fp16.
__device__ __align__(16) __half g_Qh[B_SZ * NH * L_SEQ * DK];  // [b,h,i,d]
__device__ __align__(16) __half g_Kh[B_SZ * NH * L_SEQ * DK];  // [b,h,o,d]
__device__ __align__(16) __half g_Vh[B_SZ * NH * L_SEQ * DK];  // [b,h,o,d]
__device__ __align__(16) __half g_Mha[M_TOT * D_MODEL];        // [m][h*64+d]
__device__ unsigned g_mbits[B_SZ * L_SEQ * L_SEQ / 32];
__device__ __align__(16) __half g_x16[3][M_TOT * D_MODEL];
__device__ __align__(16) __half g_w16[4][D_MODEL * D_MODEL];

__device__ __forceinline__ void cpa16(unsigned d, const void* s) {
  asm volatile("cp.async.cg.shared.global [%0], [%1], 16;" :: "r"(d), "l"(s));
}
__device__ __forceinline__ void cpcommit() { asm volatile("cp.async.commit_group;"); }
__device__ __forceinline__ void cpwait0() { asm volatile("cp.async.wait_group 0;"); }
__device__ __forceinline__ float ex2f(float x) {
  float r;
  asm("ex2.approx.ftz.f32 %0, %1;" : "=f"(r) : "f"(x));
  return r;
}
__device__ __forceinline__ unsigned pack2(float a, float b) {
  __half2 h = __floats2half2_rn(a, b);
  return *(unsigned*)&h;
}
#define MMA16(c, a, b)                                                    \
  asm volatile(                                                           \
      "mma.sync.aligned.m16n8k16.row.col.f32.f16.f16.f32 "                \
      "{%0,%1,%2,%3}, {%4,%5,%6,%7}, {%8,%9}, {%0,%1,%2,%3};"             \
      : "+f"((c)[0]), "+f"((c)[1]), "+f"((c)[2]), "+f"((c)[3])            \
      : "r"((a)[0]), "r"((a)[1]), "r"((a)[2]), "r"((a)[3]), "r"((b)[0]),  \
        "r"((b)[1]))
#define LDSM4(r0, r1, r2, r3, addr)                                       \
  asm volatile(                                                           \
      "ldmatrix.sync.aligned.m8n8.x4.shared.b16 {%0,%1,%2,%3}, [%4];"     \
      : "=r"(r0), "=r"(r1), "=r"(r2), "=r"(r3) : "r"(addr))
#define LDSM4T(r0, r1, r2, r3, addr)                                      \
  asm volatile(                                                           \
      "ldmatrix.sync.aligned.m8n8.x4.trans.shared.b16 {%0,%1,%2,%3}, [%4];" \
      : "=r"(r0), "=r"(r1), "=r"(r2), "=r"(r3) : "r"(addr))

// ---------------------------------------------------------------------------
__global__ __launch_bounds__(256) void mask_bits_kernel(
    const int* __restrict__ m4, unsigned* __restrict__ out) {
  int w = blockIdx.x * 256 + threadIdx.x;
  const int4* p = (const int4*)m4 + (size_t)w * 8;
  unsigned bits = 0;
#pragma unroll
  for (int j = 0; j < 8; j++) {
    int4 v = p[j];
    bits |= (unsigned)(v.x != 0) << (4 * j + 0);
    bits |= (unsigned)(v.y != 0) << (4 * j + 1);
    bits |= (unsigned)(v.z != 0) << (4 * j + 2);
    bits |= (unsigned)(v.w != 0) << (4 * j + 3);
  }
  out[w] = bits;
}

__global__ __launch_bounds__(256) void cvt16_in_kernel(
    const float4* __restrict__ q, const float4* __restrict__ k,
    const float4* __restrict__ v, uint2* __restrict__ out) {
  int y = blockIdx.y;
  const float4* in = (y == 0) ? q : (y == 1) ? k : v;
  int i = blockIdx.x * 256 + threadIdx.x;
  float4 f = in[i];
  __half2 a = __floats2half2_rn(f.x, f.y);
  __half2 b = __floats2half2_rn(f.z, f.w);
  out[(size_t)y * (M_TOT * D_MODEL / 4) + i] =
      make_uint2(*(unsigned*)&a, *(unsigned*)&b);
}

// Wq/Wk/Wv: fp32->fp16 with ROW permutation p = (n&15)*64 + (n>>4).
__global__ __launch_bounds__(256) void cvtw_qkv_kernel(
    const float4* __restrict__ w0, const float4* __restrict__ w1,
    const float4* __restrict__ w2, uint2* __restrict__ out) {
  int y = blockIdx.y;
  const float4* in = (y == 0) ? w0 : (y == 1) ? w1 : w2;
  int n = blockIdx.x;
  int p = (n & 15) * 64 + (n >> 4);
  int i = threadIdx.x;
  float4 f = in[(size_t)n * 256 + i];
  __half2 a = __floats2half2_rn(f.x, f.y);
  __half2 b = __floats2half2_rn(f.z, f.w);
  out[(size_t)y * (D_MODEL * D_MODEL / 4) + (size_t)p * 256 + i] =
      make_uint2(*(unsigned*)&a, *(unsigned*)&b);
}

// Wo: fp32->fp16 with COLUMN permutation W'[j,p] = W[j, (p&63)*16 + (p>>6)].
__global__ __launch_bounds__(256) void cvtw_o_kernel(
    const float4* __restrict__ w3, uint2* __restrict__ out) {
  __shared__ __half s[D_MODEL];
  int j = blockIdx.x;
  int i = threadIdx.x;
  float4 f = w3[(size_t)j * 256 + i];
  __half2* sp = (__half2*)&s[i * 4];
  sp[0] = __floats2half2_rn(f.x, f.y);
  sp[1] = __floats2half2_rn(f.z, f.w);
  __syncthreads();
  __half o[4];
#pragma unroll
  for (int e = 0; e < 4; e++) {
    int p = i * 4 + e;
    int n = ((p & 63) << 4) | (p >> 6);
    o[e] = s[n];
  }
  out[(size_t)j * 256 + i] = *(uint2*)o;
}

// ---------------------------------------------------------------------------
// FP16 GEMM, 128(M) x 256(N) CTA tile, KC=64, cp.async double-buffered.
// Weights pre-permuted -> output columns head-major p = h*64+d.
// ---------------------------------------------------------------------------
#define GSTR 72
#define AT (128 * GSTR)
#define BT (256 * GSTR)

#define GEMM_PRE()                                                         \
  extern __shared__ __half gsm[];                                          \
  unsigned sA = (unsigned)__cvta_generic_to_shared(gsm);                   \
  unsigned sB = sA + 2 * AT * 2;                                           \
  int tid = threadIdx.x;                                                   \
  int m0 = blockIdx.y * 128;                                               \
  int n0 = blockIdx.x * 256;                                               \
  int wid = tid >> 5;                                                      \
  int lane = tid & 31;                                                     \
  int warp_m = (wid & 1) * 64;                                             \
  int warp_n = (wid >> 1) * 64;                                            \
  int grp = lane >> 2;                                                     \
  int thr = lane & 3;                                                      \
  int lrow = lane & 15;                                                    \
  int lcol = (lane >> 4) * 8;                                              \
  unsigned aAddr = sA + ((warp_m + lrow) * GSTR + lcol) * 2;               \
  unsigned bAddr = sB + ((warp_n + lrow) * GSTR + lcol) * 2;               \
  float acc[4][8][4];                                                      \
  _Pragma("unroll") for (int i = 0; i < 4; i++)                            \
  _Pragma("unroll") for (int j = 0; j < 8; j++)                            \
  _Pragma("unroll") for (int r = 0; r < 4; r++) acc[i][j][r] = 0.f;

#define GLOAD(k0, buf)                                                     \
  {                                                                        \
    _Pragma("unroll") for (int s = 0; s < 4; s++) {                        \
      int idx = tid + s * 256;                                             \
      int r = idx >> 3, ch = (idx & 7) * 8;                                \
      cpa16(sA + ((buf)*AT + r * GSTR + ch) * 2,                           \
            Ap + (size_t)r * D_MODEL + (k0) + ch);                         \
    }                                                                      \
    _Pragma("unroll") for (int s = 0; s < 8; s++) {                        \
      int idx = tid + s * 256;                                             \
      int r = idx >> 3, ch = (idx & 7) * 8;                                \
      cpa16(sB + ((buf)*BT + r * GSTR + ch) * 2,                           \
            Wp + (size_t)r * D_MODEL + (k0) + ch);                         \
    }                                                                      \
    cpcommit();                                                            \
  }

#define GEMM_MAIN()                                                        \
  GLOAD(0, 0);                                                             \
  for (int t = 0; t < D_MODEL / 64; t++) {                                 \
    int cur = t & 1;                                                       \
    cpwait0();                                                             \
    __syncthreads();                                                       \
    if (t + 1 < D_MODEL / 64) GLOAD((t + 1) * 64, cur ^ 1);                \
    unsigned aB = aAddr + cur * AT * 2;                                    \
    unsigned bB = bAddr + cur * BT * 2;                                    \
    _Pragma("unroll") for (int kk = 0; kk < 64; kk += 16) {                \
      unsigned af[4][4], bf[8][2];                                         \
      _Pragma("unroll") for (int mt = 0; mt < 4; mt++)                     \
        LDSM4(af[mt][0], af[mt][1], af[mt][2], af[mt][3],                  \
              aB + (mt * 16 * GSTR + kk) * 2);                             \
      _Pragma("unroll") for (int ntp = 0; ntp < 4; ntp++) {                \
        unsigned b0, b1, b2, b3;                                           \
        LDSM4(b0, b1, b2, b3, bB + (ntp * 16 * GSTR + kk) * 2);            \
        bf[2 * ntp][0] = b0;                                               \
        bf[2 * ntp][1] = b2;                                               \
        bf[2 * ntp + 1][0] = b1;                                           \
        bf[2 * ntp + 1][1] = b3;                                           \
      }                                                                    \
      _Pragma("unroll") for (int mt = 0; mt < 4; mt++)                     \
      _Pragma("unroll") for (int nt = 0; nt < 8; nt++)                     \
        MMA16(acc[mt][nt], af[mt], bf[nt]);                                \
    }                                                                      \
  }

__global__ __launch_bounds__(256, 1) void gemm_qkv_kernel(
    const __half* __restrict__ X, const __half* __restrict__ Wb) {
  int z = blockIdx.z;
  const __half* Ap = X + (size_t)z * M_TOT * D_MODEL + (size_t)blockIdx.y * 128 * D_MODEL;
  const __half* Wp = Wb + (size_t)z * D_MODEL * D_MODEL + (size_t)blockIdx.x * 256 * D_MODEL;
  GEMM_PRE();
  GEMM_MAIN();
  __half* C = (z == 0) ? g_Qh : (z == 1) ? g_Kh : g_Vh;
  float s = (z == 0) ? QSCALE : 1.0f;
#pragma unroll
  for (int mt = 0; mt < 4; mt++) {
#pragma unroll
    for (int nt = 0; nt < 8; nt++) {
      int row = m0 + warp_m + mt * 16 + grp;
      int p = n0 + warp_n + nt * 8 + thr * 2;
      int h = p >> 6, d = p & 63;
      float* c = acc[mt][nt];
#pragma unroll
      for (int e = 0; e < 2; e++) {
        int r = row + e * 8;
        int b = r >> 11;
        int ii = r & (L_SEQ - 1);
        *(unsigned*)&C[((((size_t)b * NH + h) * L_SEQ) + ii) * DK + d] =
            pack2(c[2 * e] * s, c[2 * e + 1] * s);
      }
    }
  }
}

__global__ __launch_bounds__(256, 1) void gemm_out_kernel(
    const __half* __restrict__ A, const __half* __restrict__ W,
    float* __restrict__ C) {
  const __half* Ap = A + (size_t)blockIdx.y * 128 * D_MODEL;
  const __half* Wp = W + (size_t)blockIdx.x * 256 * D_MODEL;
  GEMM_PRE();
  GEMM_MAIN();
#pragma unroll
  for (int mt = 0; mt < 4; mt++) {
#pragma unroll
    for (int nt = 0; nt < 8; nt++) {
      int row = m0 + warp_m + mt * 16 + grp;
      int col = n0 + warp_n + nt * 8 + thr * 2;
      float* c = acc[mt][nt];
      *(float2*)&C[(size_t)row * D_MODEL + col] = make_float2(c[0], c[1]);
      *(float2*)&C[(size_t)(row + 8) * D_MODEL + col] = make_float2(c[2], c[3]);
    }
  }
}

// ---------------------------------------------------------------------------
// FP16 flash attention. V loaded [o][d] like K; PV B-fragments via
// ldmatrix.trans (so no V^T global layout needed). Output head-major.
// ---------------------------------------------------------------------------
#define PSTR 72
#define KVSZ (64 * PSTR)
__global__ __launch_bounds__(256, 2) void attn_mma_kernel(
    const __half* __restrict__ Qh, const __half* __restrict__ Kh,
    const __half* __restrict__ Vh, const unsigned* __restrict__ mbits,
    __half* __restrict__ Mha) {
  extern __shared__ __half smh[];
  __half* Ps = smh + 4 * KVSZ;
  unsigned sbase = (unsigned)__cvta_generic_to_shared(smh);

  int tid = threadIdx.x;
  int w = tid >> 5;
  int lane = tid & 31;
  int grp = lane >> 2;
  int thr = lane & 3;
  int lrow = lane & 15;
  int lcol = (lane >> 4) * 8;
  int i0 = blockIdx.x * 128;
  int h = blockIdx.y;
  int b = blockIdx.z;
  int bh = b * NH + h;
  const __half* Qb = Qh + (size_t)bh * L_SEQ * DK;
  const __half* Kb = Kh + (size_t)bh * L_SEQ * DK;
  const __half* Vb = Vh + (size_t)bh * L_SEQ * DK;

#define KV_ISSUE(o0, buf)                                                  \
  {                                                                        \
    unsigned kbb = sbase + (buf)*2 * KVSZ * 2;                             \
    unsigned vbb = kbb + KVSZ * 2;                                         \
    _Pragma("unroll") for (int s = 0; s < 2; s++) {                        \
      int idx = tid + s * 256;                                             \
      int r = idx >> 3, ch = (idx & 7) * 8;                                \
      cpa16(kbb + (r * PSTR + ch) * 2, Kb + (size_t)((o0) + r) * DK + ch); \
      cpa16(vbb + (r * PSTR + ch) * 2, Vb + (size_t)((o0) + r) * DK + ch); \
    }                                                                      \
    cpcommit();                                                            \
  }

  KV_ISSUE(0, 0);

#pragma unroll
  for (int it = 0; it < 4; it++) {
    int idx = tid + it * 256;
    int r = idx >> 3, ch = (idx & 7) * 8;
    *(uint4*)&Ps[r * PSTR + ch] = *(const uint4*)&Qb[(size_t)(i0 + r) * DK + ch];
  }
  __syncthreads();

  int rbase = w * 16;
  unsigned Qf[4][4];
#pragma unroll
  for (int kg = 0; kg < 4; kg++) {
    Qf[kg][0] = *(const unsigned*)&Ps[(rbase + grp) * PSTR + kg * 16 + 2 * thr];
    Qf[kg][1] = *(const unsigned*)&Ps[(rbase + grp + 8) * PSTR + kg * 16 + 2 * thr];
    Qf[kg][2] = *(const unsigned*)&Ps[(rbase + grp) * PSTR + kg * 16 + 2 * thr + 8];
    Qf[kg][3] = *(const unsigned*)&Ps[(rbase + grp + 8) * PSTR + kg * 16 + 2 * thr + 8];
  }
  __syncthreads();

  int rA = i0 + rbase + grp;
  int rB = rA + 8;
  const unsigned long long* mbA =
      (const unsigned long long*)mbits + (size_t)(b * L_SEQ + rA) * (L_SEQ / 64);
  const unsigned long long* mbB =
      (const unsigned long long*)mbits + (size_t)(b * L_SEQ + rB) * (L_SEQ / 64);

  float mA = -CUDART_INF_F, mB = -CUDART_INF_F;
  float lA = 0.f, lB = 0.f;
  float oa[8][4];
#pragma unroll
  for (int nt = 0; nt < 8; nt++)
#pragma unroll
    for (int e = 0; e < 4; e++) oa[nt][e] = 0.f;

  const int NT = L_SEQ / 64;
  for (int ot = 0; ot < NT; ot++) {
    int cur = ot & 1;
    unsigned long long mWa = mbA[ot];
    unsigned long long mWb = mbB[ot];
    cpwait0();
    __syncthreads();
    if (ot + 1 < NT) KV_ISSUE((ot + 1) * 64, cur ^ 1);
    unsigned kAddr = sbase + cur * 2 * KVSZ * 2 + (lrow * PSTR + lcol) * 2;
    unsigned vAddr = kAddr + KVSZ * 2;

    // S = Q K^T
    float sa[8][4];
#pragma unroll
    for (int nt = 0; nt < 8; nt++)
      sa[nt][0] = sa[nt][1] = sa[nt][2] = sa[nt][3] = 0.f;
#pragma unroll
    for (int ntp = 0; ntp < 4; ntp++) {
#pragma unroll
      for (int kg = 0; kg < 4; kg++) {
        unsigned b0, b1, b2, b3;
        LDSM4(b0, b1, b2, b3, kAddr + (ntp * 16 * PSTR + kg * 16) * 2);
        unsigned bfA[2] = {b0, b2}, bfB[2] = {b1, b3};
        MMA16(sa[2 * ntp], Qf[kg], bfA);
        MMA16(sa[2 * ntp + 1], Qf[kg], bfB);
      }
    }

    float mxA = -CUDART_INF_F, mxB = -CUDART_INF_F;
#pragma unroll
    for (int nt = 0; nt < 8; nt++) {
      int c0 = nt * 8 + 2 * thr;
      if ((mWa >> c0) & 1ull) sa[nt][0] = NEGL2;
      if ((mWa >> (c0 + 1)) & 1ull) sa[nt][1] = NEGL2;
      if ((mWb >> c0) & 1ull) sa[nt][2] = NEGL2;
      if ((mWb >> (c0 + 1)) & 1ull) sa[nt][3] = NEGL2;
      mxA = fmaxf(mxA, fmaxf(sa[nt][0], sa[nt][1]));
      mxB = fmaxf(mxB, fmaxf(sa[nt][2], sa[nt][3]));
    }
    mxA = fmaxf(mxA, __shfl_xor_sync(0xffffffffu, mxA, 1));
    mxA = fmaxf(mxA, __shfl_xor_sync(0xffffffffu, mxA, 2));
    mxB = fmaxf(mxB, __shfl_xor_sync(0xffffffffu, mxB, 1));
    mxB = fmaxf(mxB, __shfl_xor_sync(0xffffffffu, mxB, 2));

    float nmA = fmaxf(mA, mxA), nmB = fmaxf(mB, mxB);
    float cA = ex2f(mA - nmA), cB = ex2f(mB - nmB);
    float sumA = 0.f, sumB = 0.f;
    unsigned pf[4][4];
#pragma unroll
    for (int nt = 0; nt < 8; nt++) {
      float p0 = ex2f(sa[nt][0] - nmA);
      float p1 = ex2f(sa[nt][1] - nmA);
      float p2 = ex2f(sa[nt][2] - nmB);
      float p3 = ex2f(sa[nt][3] - nmB);
      sumA += p0 + p1;
      sumB += p2 + p3;
      int kg = nt >> 1;
      if ((nt & 1) == 0) {
        pf[kg][0] = pack2(p0, p1);
        pf[kg][1] = pack2(p2, p3);
      } else {
        pf[kg][2] = pack2(p0, p1);
        pf[kg][3] = pack2(p2, p3);
      }
    }
    sumA += __shfl_xor_sync(0xffffffffu, sumA, 1);
    sumA += __shfl_xor_sync(0xffffffffu, sumA, 2);
    sumB += __shfl_xor_sync(0xffffffffu, sumB, 1);
    sumB += __shfl_xor_sync(0xffffffffu, sumB, 2);
    lA = lA * cA + sumA;
    lB = lB * cB + sumB;
    mA = nmA;
    mB = nmB;

#pragma unroll
    for (int nt = 0; nt < 8; nt++) {
      oa[nt][0] *= cA;
      oa[nt][1] *= cA;
      oa[nt][2] *= cB;
      oa[nt][3] *= cB;
    }

    // O += P V, B-fragments via ldmatrix.trans from V[o][d] tile
#pragma unroll
    for (int ntp = 0; ntp < 4; ntp++) {
#pragma unroll
      for (int kg = 0; kg < 4; kg++) {
        unsigned b0, b1, b2, b3;
        LDSM4T(b0, b1, b2, b3, vAddr + (kg * 16 * PSTR + ntp * 16) * 2);
        unsigned bfA[2] = {b0, b1}, bfB[2] = {b2, b3};
        MMA16(oa[2 * ntp], pf[kg], bfA);
        MMA16(oa[2 * ntp + 1], pf[kg], bfB);
      }
    }
  }

  float iA = 1.f / lA, iB = 1.f / lB;
  __half* outA = &Mha[(size_t)(b * L_SEQ + rA) * D_MODEL + h * 64];
  __half* outB = &Mha[(size_t)(b * L_SEQ + rB) * D_MODEL + h * 64];
#pragma unroll
  for (int nt = 0; nt < 8; nt++) {
    int d0 = nt * 8 + 2 * thr;
    *(unsigned*)&outA[d0] = pack2(oa[nt][0] * iA, oa[nt][1] * iA);
    *(unsigned*)&outB[d0] = pack2(oa[nt][2] * iB, oa[nt][3] * iB);
  }
}

// ---------------------------------------------------------------------------
extern "C" void kernel_launch(void* const* d_in, const int* in_sizes, int n_in,
                              void* d_out, int out_size) {
  const float* q = (const float*)d_in[0];
  const float* k = (const float*)d_in[1];
  const float* v = (const float*)d_in[2];
  const int* mask4 = (const int*)d_in[3];
  float* out = (float*)d_out;

  __half *Qh, *Kh, *Vh, *Mh, *X16, *W16;
  unsigned* Mb;
  cudaGetSymbolAddress((void**)&Qh, g_Qh);
  cudaGetSymbolAddress((void**)&Kh, g_Kh);
  cudaGetSymbolAddress((void**)&Vh, g_Vh);
  cudaGetSymbolAddress((void**)&Mh, g_Mha);
  cudaGetSymbolAddress((void**)&Mb, g_mbits);
  cudaGetSymbolAddress((void**)&X16, g_x16);
  cudaGetSymbolAddress((void**)&W16, g_w16);

  int nwords = B_SZ * L_SEQ * L_SEQ / 32;
  mask_bits_kernel<<<nwords / 256, 256>>>(mask4, Mb);

  dim3 cg1(M_TOT * D_MODEL / 4 / 256, 3);
  cvt16_in_kernel<<<cg1, 256>>>((const float4*)q, (const float4*)k,
                                (const float4*)v, (uint2*)X16);
  dim3 cgw(D_MODEL, 3);
  cvtw_qkv_kernel<<<cgw, 256>>>((const float4*)d_in[4], (const float4*)d_in[5],
                                (const float4*)d_in[6], (uint2*)W16);
  cvtw_o_kernel<<<D_MODEL, 256>>>((const float4*)d_in[7],
                                  (uint2*)(W16 + 3ull * D_MODEL * D_MODEL));

  int gsmem = (2 * AT + 2 * BT) * 2;  // 110592 bytes
  cudaFuncSetAttribute(gemm_qkv_kernel, cudaFuncAttributeMaxDynamicSharedMemorySize, gsmem);
  cudaFuncSetAttribute(gemm_out_kernel, cudaFuncAttributeMaxDynamicSharedMemorySize, gsmem);

  dim3 gq(D_MODEL / 256, M_TOT / 128, 3);  // (4, 32, 3)
  gemm_qkv_kernel<<<gq, 256, gsmem>>>(X16, W16);

  int asmem = (4 * KVSZ + 128 * PSTR) * 2;  // 55296
  cudaFuncSetAttribute(attn_mma_kernel,
                       cudaFuncAttributeMaxDynamicSharedMemorySize, asmem);
  dim3 ag(L_SEQ / 128, NH, B_SZ);
  attn_mma_kernel<<<ag, 256, asmem>>>(Qh, Kh, Vh, Mb, Mh);

  dim3 go(D_MODEL / 256, M_TOT / 128);  // (4, 32)
  gemm_out_kernel<<<go, 256, gsmem>>>(Mh, W16 + 3ull * D_MODEL * D_MODEL, out);
}

// round 13
// speedup vs baseline: 2.3686x; 1.0237x over previous
#include <cuda_runtime.h>
#include <cuda_fp16.h>
#include <math_constants.h>

#define B_SZ 2
#define L_SEQ 2048
#define D_MODEL 1024
#define NH 16
#define DK 64
#define M_TOT (B_SZ * L_SEQ)
#define NEGL2 (-1.44269504e10f)
#define QSCALE (0.125f * 1.442695040888963f)

// Scratch (device globals). All fp16.
__device__ __align__(16) __half g_Qh[B_SZ * NH * L_SEQ * DK];  // [b,h,i,d]
__device__ __align__(16) __half g_Kh[B_SZ * NH * L_SEQ * DK];  // [b,h,o,d]
__device__ __align__(16) __half g_Vh[B_SZ * NH * L_SEQ * DK];  // [b,h,o,d]
__device__ __align__(16) __half g_Mha[M_TOT * D_MODEL];        // [m][h*64+d]
__device__ unsigned g_mbits[B_SZ * L_SEQ * L_SEQ / 32];
__device__ __align__(16) __half g_x16[3][M_TOT * D_MODEL];
__device__ __align__(16) __half g_w16[4][D_MODEL * D_MODEL];

__device__ __forceinline__ void cpa16(unsigned d, const void* s) {
  asm volatile("cp.async.cg.shared.global [%0], [%1], 16;" :: "r"(d), "l"(s));
}
__device__ __forceinline__ void cpcommit() { asm volatile("cp.async.commit_group;"); }
__device__ __forceinline__ void cpwait1() { asm volatile("cp.async.wait_group 1;"); }
__device__ __forceinline__ float ex2f(float x) {
  float r;
  asm("ex2.approx.ftz.f32 %0, %1;" : "=f"(r) : "f"(x));
  return r;
}
__device__ __forceinline__ unsigned pack2(float a, float b) {
  __half2 h = __floats2half2_rn(a, b);
  return *(unsigned*)&h;
}
#define MMA16(c, a, b)                                                    \
  asm volatile(                                                           \
      "mma.sync.aligned.m16n8k16.row.col.f32.f16.f16.f32 "                \
      "{%0,%1,%2,%3}, {%4,%5,%6,%7}, {%8,%9}, {%0,%1,%2,%3};"             \
      : "+f"((c)[0]), "+f"((c)[1]), "+f"((c)[2]), "+f"((c)[3])            \
      : "r"((a)[0]), "r"((a)[1]), "r"((a)[2]), "r"((a)[3]), "r"((b)[0]),  \
        "r"((b)[1]))
#define LDSM4(r0, r1, r2, r3, addr)                                       \
  asm volatile(                                                           \
      "ldmatrix.sync.aligned.m8n8.x4.shared.b16 {%0,%1,%2,%3}, [%4];"     \
      : "=r"(r0), "=r"(r1), "=r"(r2), "=r"(r3) : "r"(addr))
#define LDSM4T(r0, r1, r2, r3, addr)                                      \
  asm volatile(                                                           \
      "ldmatrix.sync.aligned.m8n8.x4.trans.shared.b16 {%0,%1,%2,%3}, [%4];" \
      : "=r"(r0), "=r"(r1), "=r"(r2), "=r"(r3) : "r"(addr))

// ---------------------------------------------------------------------------
// Fused prologue. Block ranges:
//  [0, 1024)            : mask bit-pack (1 warp-group per 8192 mask elems)
//  [1024, 13312)        : q/k/v fp32->fp16 (4096 blocks each)
//  [13312, 16384)       : Wq/Wk/Wv row-permuted cvt (1024 rows each)
//  [16384, 17408)       : Wo column-permuted cvt (1024 rows)
// ---------------------------------------------------------------------------
__global__ __launch_bounds__(256) void prologue_kernel(
    const int* __restrict__ m4, const float4* __restrict__ q,
    const float4* __restrict__ k, const float4* __restrict__ v,
    const float4* __restrict__ w0, const float4* __restrict__ w1,
    const float4* __restrict__ w2, const float4* __restrict__ w3) {
  int blk = blockIdx.x;
  if (blk < 1024) {
    int w = blk * 256 + threadIdx.x;
    const int4* p = (const int4*)m4 + (size_t)w * 8;
    unsigned bits = 0;
#pragma unroll
    for (int j = 0; j < 8; j++) {
      int4 x = p[j];
      bits |= (unsigned)(x.x != 0) << (4 * j + 0);
      bits |= (unsigned)(x.y != 0) << (4 * j + 1);
      bits |= (unsigned)(x.z != 0) << (4 * j + 2);
      bits |= (unsigned)(x.w != 0) << (4 * j + 3);
    }
    g_mbits[w] = bits;
  } else if (blk < 13312) {
    int rel = blk - 1024;
    int y = rel / 4096;
    const float4* in = (y == 0) ? q : (y == 1) ? k : v;
    int i = (rel - y * 4096) * 256 + threadIdx.x;
    float4 f = in[i];
    ((uint2*)g_x16)[(size_t)y * (M_TOT * D_MODEL / 4) + i] =
        make_uint2(pack2(f.x, f.y), pack2(f.z, f.w));
  } else if (blk < 16384) {
    int rel = blk - 13312;
    int y = rel >> 10;
    const float4* in = (y == 0) ? w0 : (y == 1) ? w1 : w2;
    int n = rel & 1023;
    int p = (n & 15) * 64 + (n >> 4);
    int i = threadIdx.x;
    float4 f = in[(size_t)n * 256 + i];
    ((uint2*)g_w16)[(size_t)y * (D_MODEL * D_MODEL / 4) + (size_t)p * 256 + i] =
        make_uint2(pack2(f.x, f.y), pack2(f.z, f.w));
  } else {
    __shared__ __half s[D_MODEL];
    int j = blk - 16384;
    int i = threadIdx.x;
    float4 f = w3[(size_t)j * 256 + i];
    __half2* sp = (__half2*)&s[i * 4];
    sp[0] = __floats2half2_rn(f.x, f.y);
    sp[1] = __floats2half2_rn(f.z, f.w);
    __syncthreads();
    __half o[4];
#pragma unroll
    for (int e = 0; e < 4; e++) {
      int p = i * 4 + e;
      int n = ((p & 63) << 4) | (p >> 6);
      o[e] = s[n];
    }
    ((uint2*)g_w16)[3ull * (D_MODEL * D_MODEL / 4) + (size_t)j * 256 + i] =
        *(uint2*)o;
  }
}

// ---------------------------------------------------------------------------
// FP16 GEMM, 128(M) x 256(N) CTA tile, KC=64, 3-stage cp.async pipeline.
// Weights pre-permuted -> output columns head-major p = h*64+d.
// ---------------------------------------------------------------------------
#define GSTR 72
#define AT (128 * GSTR)
#define BT (256 * GSTR)
#define NSTG 3

#define GEMM_PRE()                                                         \
  extern __shared__ __half gsm[];                                          \
  unsigned sA = (unsigned)__cvta_generic_to_shared(gsm);                   \
  unsigned sB = sA + NSTG * AT * 2;                                        \
  int tid = threadIdx.x;                                                   \
  int m0 = blockIdx.y * 128;                                               \
  int n0 = blockIdx.x * 256;                                               \
  int wid = tid >> 5;                                                      \
  int lane = tid & 31;                                                     \
  int warp_m = (wid & 1) * 64;                                             \
  int warp_n = (wid >> 1) * 64;                                            \
  int grp = lane >> 2;                                                     \
  int thr = lane & 3;                                                      \
  int lrow = lane & 15;                                                    \
  int lcol = (lane >> 4) * 8;                                              \
  unsigned aAddr = sA + ((warp_m + lrow) * GSTR + lcol) * 2;               \
  unsigned bAddr = sB + ((warp_n + lrow) * GSTR + lcol) * 2;               \
  float acc[4][8][4];                                                      \
  _Pragma("unroll") for (int i = 0; i < 4; i++)                            \
  _Pragma("unroll") for (int j = 0; j < 8; j++)                            \
  _Pragma("unroll") for (int r = 0; r < 4; r++) acc[i][j][r] = 0.f;

#define GLOAD(k0, buf)                                                     \
  {                                                                        \
    _Pragma("unroll") for (int s = 0; s < 4; s++) {                        \
      int idx = tid + s * 256;                                             \
      int r = idx >> 3, ch = (idx & 7) * 8;                                \
      cpa16(sA + ((buf)*AT + r * GSTR + ch) * 2,                           \
            Ap + (size_t)r * D_MODEL + (k0) + ch);                         \
    }                                                                      \
    _Pragma("unroll") for (int s = 0; s < 8; s++) {                        \
      int idx = tid + s * 256;                                             \
      int r = idx >> 3, ch = (idx & 7) * 8;                                \
      cpa16(sB + ((buf)*BT + r * GSTR + ch) * 2,                           \
            Wp + (size_t)r * D_MODEL + (k0) + ch);                         \
    }                                                                      \
    cpcommit();                                                            \
  }

#define GEMM_MAIN()                                                        \
  GLOAD(0, 0);                                                             \
  GLOAD(64, 1);                                                            \
  for (int t = 0; t < D_MODEL / 64; t++) {                                 \
    int cur = t % NSTG;                                                    \
    cpwait1();                                                             \
    __syncthreads();                                                       \
    if (t + 2 < D_MODEL / 64) GLOAD((t + 2) * 64, (t + 2) % NSTG);         \
    unsigned aB = aAddr + cur * AT * 2;                                    \
    unsigned bB = bAddr + cur * BT * 2;                                    \
    _Pragma("unroll") for (int kk = 0; kk < 64; kk += 16) {                \
      unsigned af[4][4], bf[8][2];                                         \
      _Pragma("unroll") for (int mt = 0; mt < 4; mt++)                     \
        LDSM4(af[mt][0], af[mt][1], af[mt][2], af[mt][3],                  \
              aB + (mt * 16 * GSTR + kk) * 2);                             \
      _Pragma("unroll") for (int ntp = 0; ntp < 4; ntp++) {                \
        unsigned b0, b1, b2, b3;                                           \
        LDSM4(b0, b1, b2, b3, bB + (ntp * 16 * GSTR + kk) * 2);            \
        bf[2 * ntp][0] = b0;                                               \
        bf[2 * ntp][1] = b2;                                               \
        bf[2 * ntp + 1][0] = b1;                                           \
        bf[2 * ntp + 1][1] = b3;                                           \
      }                                                                    \
      _Pragma("unroll") for (int mt = 0; mt < 4; mt++)                     \
      _Pragma("unroll") for (int nt = 0; nt < 8; nt++)                     \
        MMA16(acc[mt][nt], af[mt], bf[nt]);                                \
    }                                                                      \
  }

__global__ __launch_bounds__(256, 1) void gemm_qkv_kernel(
    const __half* __restrict__ X, const __half* __restrict__ Wb) {
  int z = blockIdx.z;
  const __half* Ap = X + (size_t)z * M_TOT * D_MODEL + (size_t)blockIdx.y * 128 * D_MODEL;
  const __half* Wp = Wb + (size_t)z * D_MODEL * D_MODEL + (size_t)blockIdx.x * 256 * D_MODEL;
  GEMM_PRE();
  GEMM_MAIN();
  __half* C = (z == 0) ? g_Qh : (z == 1) ? g_Kh : g_Vh;
  float s = (z == 0) ? QSCALE : 1.0f;
#pragma unroll
  for (int mt = 0; mt < 4; mt++) {
#pragma unroll
    for (int nt = 0; nt < 8; nt++) {
      int row = m0 + warp_m + mt * 16 + grp;
      int p = n0 + warp_n + nt * 8 + thr * 2;
      int h = p >> 6, d = p & 63;
      float* c = acc[mt][nt];
#pragma unroll
      for (int e = 0; e < 2; e++) {
        int r = row + e * 8;
        int b = r >> 11;
        int ii = r & (L_SEQ - 1);
        *(unsigned*)&C[((((size_t)b * NH + h) * L_SEQ) + ii) * DK + d] =
            pack2(c[2 * e] * s, c[2 * e + 1] * s);
      }
    }
  }
}

__global__ __launch_bounds__(256, 1) void gemm_out_kernel(
    const __half* __restrict__ A, const __half* __restrict__ W,
    float* __restrict__ C) {
  const __half* Ap = A + (size_t)blockIdx.y * 128 * D_MODEL;
  const __half* Wp = W + (size_t)blockIdx.x * 256 * D_MODEL;
  GEMM_PRE();
  GEMM_MAIN();
#pragma unroll
  for (int mt = 0; mt < 4; mt++) {
#pragma unroll
    for (int nt = 0; nt < 8; nt++) {
      int row = m0 + warp_m + mt * 16 + grp;
      int col = n0 + warp_n + nt * 8 + thr * 2;
      float* c = acc[mt][nt];
      *(float2*)&C[(size_t)row * D_MODEL + col] = make_float2(c[0], c[1]);
      *(float2*)&C[(size_t)(row + 8) * D_MODEL + col] = make_float2(c[2], c[3]);
    }
  }
}

// ---------------------------------------------------------------------------
// FP16 flash attention, 3-stage K/V cp.async pipeline.
// V loaded [o][d] like K; PV B-fragments via ldmatrix.trans.
// ---------------------------------------------------------------------------
#define PSTR 72
#define KVSZ (64 * PSTR)
__global__ __launch_bounds__(256, 2) void attn_mma_kernel(
    const __half* __restrict__ Qh, const __half* __restrict__ Kh,
    const __half* __restrict__ Vh, const unsigned* __restrict__ mbits,
    __half* __restrict__ Mha) {
  extern __shared__ __half smh[];
  __half* Ps = smh + 6 * KVSZ;
  unsigned sbase = (unsigned)__cvta_generic_to_shared(smh);

  int tid = threadIdx.x;
  int w = tid >> 5;
  int lane = tid & 31;
  int grp = lane >> 2;
  int thr = lane & 3;
  int lrow = lane & 15;
  int lcol = (lane >> 4) * 8;
  int i0 = blockIdx.x * 128;
  int h = blockIdx.y;
  int b = blockIdx.z;
  int bh = b * NH + h;
  const __half* Qb = Qh + (size_t)bh * L_SEQ * DK;
  const __half* Kb = Kh + (size_t)bh * L_SEQ * DK;
  const __half* Vb = Vh + (size_t)bh * L_SEQ * DK;

#define KV_ISSUE(o0, buf)                                                  \
  {                                                                        \
    unsigned kbb = sbase + (buf)*2 * KVSZ * 2;                             \
    unsigned vbb = kbb + KVSZ * 2;                                         \
    _Pragma("unroll") for (int s = 0; s < 2; s++) {                        \
      int idx = tid + s * 256;                                             \
      int r = idx >> 3, ch = (idx & 7) * 8;                                \
      cpa16(kbb + (r * PSTR + ch) * 2, Kb + (size_t)((o0) + r) * DK + ch); \
      cpa16(vbb + (r * PSTR + ch) * 2, Vb + (size_t)((o0) + r) * DK + ch); \
    }                                                                      \
    cpcommit();                                                            \
  }

  KV_ISSUE(0, 0);
  KV_ISSUE(64, 1);

#pragma unroll
  for (int it = 0; it < 4; it++) {
    int idx = tid + it * 256;
    int r = idx >> 3, ch = (idx & 7) * 8;
    *(uint4*)&Ps[r * PSTR + ch] = *(const uint4*)&Qb[(size_t)(i0 + r) * DK + ch];
  }
  __syncthreads();

  int rbase = w * 16;
  unsigned Qf[4][4];
#pragma unroll
  for (int kg = 0; kg < 4; kg++) {
    Qf[kg][0] = *(const unsigned*)&Ps[(rbase + grp) * PSTR + kg * 16 + 2 * thr];
    Qf[kg][1] = *(const unsigned*)&Ps[(rbase + grp + 8) * PSTR + kg * 16 + 2 * thr];
    Qf[kg][2] = *(const unsigned*)&Ps[(rbase + grp) * PSTR + kg * 16 + 2 * thr + 8];
    Qf[kg][3] = *(const unsigned*)&Ps[(rbase + grp + 8) * PSTR + kg * 16 + 2 * thr + 8];
  }

  int rA = i0 + rbase + grp;
  int rB = rA + 8;
  const unsigned long long* mbA =
      (const unsigned long long*)mbits + (size_t)(b * L_SEQ + rA) * (L_SEQ / 64);
  const unsigned long long* mbB =
      (const unsigned long long*)mbits + (size_t)(b * L_SEQ + rB) * (L_SEQ / 64);

  float mA = -CUDART_INF_F, mB = -CUDART_INF_F;
  float lA = 0.f, lB = 0.f;
  float oa[8][4];
#pragma unroll
  for (int nt = 0; nt < 8; nt++)
#pragma unroll
    for (int e = 0; e < 4; e++) oa[nt][e] = 0.f;

  const int NT = L_SEQ / 64;
  for (int ot = 0; ot < NT; ot++) {
    int cur = ot % 3;
    unsigned long long mWa = mbA[ot];
    unsigned long long mWb = mbB[ot];
    cpwait1();
    __syncthreads();
    if (ot + 2 < NT) KV_ISSUE((ot + 2) * 64, (ot + 2) % 3);
    unsigned kAddr = sbase + cur * 2 * KVSZ * 2 + (lrow * PSTR + lcol) * 2;
    unsigned vAddr = kAddr + KVSZ * 2;

    // S = Q K^T
    float sa[8][4];
#pragma unroll
    for (int nt = 0; nt < 8; nt++)
      sa[nt][0] = sa[nt][1] = sa[nt][2] = sa[nt][3] = 0.f;
#pragma unroll
    for (int ntp = 0; ntp < 4; ntp++) {
#pragma unroll
      for (int kg = 0; kg < 4; kg++) {
        unsigned b0, b1, b2, b3;
        LDSM4(b0, b1, b2, b3, kAddr + (ntp * 16 * PSTR + kg * 16) * 2);
        unsigned bfA[2] = {b0, b2}, bfB[2] = {b1, b3};
        MMA16(sa[2 * ntp], Qf[kg], bfA);
        MMA16(sa[2 * ntp + 1], Qf[kg], bfB);
      }
    }

    float mxA = -CUDART_INF_F, mxB = -CUDART_INF_F;
#pragma unroll
    for (int nt = 0; nt < 8; nt++) {
      int c0 = nt * 8 + 2 * thr;
      if ((mWa >> c0) & 1ull) sa[nt][0] = NEGL2;
      if ((mWa >> (c0 + 1)) & 1ull) sa[nt][1] = NEGL2;
      if ((mWb >> c0) & 1ull) sa[nt][2] = NEGL2;
      if ((mWb >> (c0 + 1)) & 1ull) sa[nt][3] = NEGL2;
      mxA = fmaxf(mxA, fmaxf(sa[nt][0], sa[nt][1]));
      mxB = fmaxf(mxB, fmaxf(sa[nt][2], sa[nt][3]));
    }
    mxA = fmaxf(mxA, __shfl_xor_sync(0xffffffffu, mxA, 1));
    mxA = fmaxf(mxA, __shfl_xor_sync(0xffffffffu, mxA, 2));
    mxB = fmaxf(mxB, __shfl_xor_sync(0xffffffffu, mxB, 1));
    mxB = fmaxf(mxB, __shfl_xor_sync(0xffffffffu, mxB, 2));

    float nmA = fmaxf(mA, mxA), nmB = fmaxf(mB, mxB);
    float cA = ex2f(mA - nmA), cB = ex2f(mB - nmB);
    float sumA = 0.f, sumB = 0.f;
    unsigned pf[4][4];
#pragma unroll
    for (int nt = 0; nt < 8; nt++) {
      float p0 = ex2f(sa[nt][0] - nmA);
      float p1 = ex2f(sa[nt][1] - nmA);
      float p2 = ex2f(sa[nt][2] - nmB);
      float p3 = ex2f(sa[nt][3] - nmB);
      sumA += p0 + p1;
      sumB += p2 + p3;
      int kg = nt >> 1;
      if ((nt & 1) == 0) {
        pf[kg][0] = pack2(p0, p1);
        pf[kg][1] = pack2(p2, p3);
      } else {
        pf[kg][2] = pack2(p0, p1);
        pf[kg][3] = pack2(p2, p3);
      }
    }
    sumA += __shfl_xor_sync(0xffffffffu, sumA, 1);
    sumA += __shfl_xor_sync(0xffffffffu, sumA, 2);
    sumB += __shfl_xor_sync(0xffffffffu, sumB, 1);
    sumB += __shfl_xor_sync(0xffffffffu, sumB, 2);
    lA = lA * cA + sumA;
    lB = lB * cB + sumB;
    mA = nmA;
    mB = nmB;

#pragma unroll
    for (int nt = 0; nt < 8; nt++) {
      oa[nt][0] *= cA;
      oa[nt][1] *= cA;
      oa[nt][2] *= cB;
      oa[nt][3] *= cB;
    }

    // O += P V, B-fragments via ldmatrix.trans from V[o][d] tile
#pragma unroll
    for (int ntp = 0; ntp < 4; ntp++) {
#pragma unroll
      for (int kg = 0; kg < 4; kg++) {
        unsigned b0, b1, b2, b3;
        LDSM4T(b0, b1, b2, b3, vAddr + (kg * 16 * PSTR + ntp * 16) * 2);
        unsigned bfA[2] = {b0, b1}, bfB[2] = {b2, b3};
        MMA16(oa[2 * ntp], pf[kg], bfA);
        MMA16(oa[2 * ntp + 1], pf[kg], bfB);
      }
    }
  }

  float iA = 1.f / lA, iB = 1.f / lB;
  __half* outA = &Mha[(size_t)(b * L_SEQ + rA) * D_MODEL + h * 64];
  __half* outB = &Mha[(size_t)(b * L_SEQ + rB) * D_MODEL + h * 64];
#pragma unroll
  for (int nt = 0; nt < 8; nt++) {
    int d0 = nt * 8 + 2 * thr;
    *(unsigned*)&outA[d0] = pack2(oa[nt][0] * iA, oa[nt][1] * iA);
    *(unsigned*)&outB[d0] = pack2(oa[nt][2] * iB, oa[nt][3] * iB);
  }
}

// ---------------------------------------------------------------------------
extern "C" void kernel_launch(void* const* d_in, const int* in_sizes, int n_in,
                              void* d_out, int out_size) {
  const int* mask4 = (const int*)d_in[3];
  float* out = (float*)d_out;

  __half *Qh, *Kh, *Vh, *Mh, *X16, *W16;
  unsigned* Mb;
  cudaGetSymbolAddress((void**)&Qh, g_Qh);
  cudaGetSymbolAddress((void**)&Kh, g_Kh);
  cudaGetSymbolAddress((void**)&Vh, g_Vh);
  cudaGetSymbolAddress((void**)&Mh, g_Mha);
  cudaGetSymbolAddress((void**)&Mb, g_mbits);
  cudaGetSymbolAddress((void**)&X16, g_x16);
  cudaGetSymbolAddress((void**)&W16, g_w16);

  prologue_kernel<<<17408, 256>>>(
      mask4, (const float4*)d_in[0], (const float4*)d_in[1],
      (const float4*)d_in[2], (const float4*)d_in[4], (const float4*)d_in[5],
      (const float4*)d_in[6], (const float4*)d_in[7]);

  int gsmem = NSTG * (AT + BT) * 2;  // 165888 bytes
  cudaFuncSetAttribute(gemm_qkv_kernel, cudaFuncAttributeMaxDynamicSharedMemorySize, gsmem);
  cudaFuncSetAttribute(gemm_out_kernel, cudaFuncAttributeMaxDynamicSharedMemorySize, gsmem);

  dim3 gq(D_MODEL / 256, M_TOT / 128, 3);  // (4, 32, 3)
  gemm_qkv_kernel<<<gq, 256, gsmem>>>(X16, W16);

  int asmem = (6 * KVSZ + 128 * PSTR) * 2;  // 73728
  cudaFuncSetAttribute(attn_mma_kernel,
                       cudaFuncAttributeMaxDynamicSharedMemorySize, asmem);
  dim3 ag(L_SEQ / 128, NH, B_SZ);
  attn_mma_kernel<<<ag, 256, asmem>>>(Qh, Kh, Vh, Mb, Mh);

  dim3 go(D_MODEL / 256, M_TOT / 128);  // (4, 32)
  gemm_out_kernel<<<go, 256, gsmem>>>(Mh, W16 + 3ull * D_MODEL * D_MODEL, out);
}

// round 14
// speedup vs baseline: 2.3986x; 1.0127x over previous
#include <cuda_runtime.h>
#include <cuda_fp16.h>
#include <math_constants.h>

#define B_SZ 2
#define L_SEQ 2048
#define D_MODEL 1024
#define NH 16
#define DK 64
#define M_TOT (B_SZ * L_SEQ)
#define NEGL2 (-1.44269504e10f)
#define QSCALE (0.125f * 1.442695040888963f)

// Scratch (device globals). All fp16.
__device__ __align__(16) __half g_Qh[B_SZ * NH * L_SEQ * DK];  // [b,h,i,d]
__device__ __align__(16) __half g_Kh[B_SZ * NH * L_SEQ * DK];  // [b,h,o,d]
__device__ __align__(16) __half g_Vh[B_SZ * NH * L_SEQ * DK];  // [b,h,o,d]
__device__ __align__(16) __half g_Mha[M_TOT * D_MODEL];        // [m][h*64+d]
__device__ unsigned g_mbits[B_SZ * L_SEQ * L_SEQ / 32];
__device__ __align__(16) __half g_x16[3][M_TOT * D_MODEL];
__device__ __align__(16) __half g_w16[4][D_MODEL * D_MODEL];

__device__ __forceinline__ void cpa16(unsigned d, const void* s) {
  asm volatile("cp.async.cg.shared.global [%0], [%1], 16;" :: "r"(d), "l"(s));
}
__device__ __forceinline__ void cpcommit() { asm volatile("cp.async.commit_group;"); }
__device__ __forceinline__ void cpwait1() { asm volatile("cp.async.wait_group 1;"); }
__device__ __forceinline__ float ex2f(float x) {
  float r;
  asm("ex2.approx.ftz.f32 %0, %1;" : "=f"(r) : "f"(x));
  return r;
}
__device__ __forceinline__ unsigned pack2(float a, float b) {
  __half2 h = __floats2half2_rn(a, b);
  return *(unsigned*)&h;
}
#define MMA16(c, a, b)                                                    \
  asm volatile(                                                           \
      "mma.sync.aligned.m16n8k16.row.col.f32.f16.f16.f32 "                \
      "{%0,%1,%2,%3}, {%4,%5,%6,%7}, {%8,%9}, {%0,%1,%2,%3};"             \
      : "+f"((c)[0]), "+f"((c)[1]), "+f"((c)[2]), "+f"((c)[3])            \
      : "r"((a)[0]), "r"((a)[1]), "r"((a)[2]), "r"((a)[3]), "r"((b)[0]),  \
        "r"((b)[1]))
#define LDSM4(r0, r1, r2, r3, addr)                                       \
  asm volatile(                                                           \
      "ldmatrix.sync.aligned.m8n8.x4.shared.b16 {%0,%1,%2,%3}, [%4];"     \
      : "=r"(r0), "=r"(r1), "=r"(r2), "=r"(r3) : "r"(addr))
#define LDSM4T(r0, r1, r2, r3, addr)                                      \
  asm volatile(                                                           \
      "ldmatrix.sync.aligned.m8n8.x4.trans.shared.b16 {%0,%1,%2,%3}, [%4];" \
      : "=r"(r0), "=r"(r1), "=r"(r2), "=r"(r3) : "r"(addr))

// ---------------------------------------------------------------------------
// Fused prologue (unchanged).
// ---------------------------------------------------------------------------
__global__ __launch_bounds__(256) void prologue_kernel(
    const int* __restrict__ m4, const float4* __restrict__ q,
    const float4* __restrict__ k, const float4* __restrict__ v,
    const float4* __restrict__ w0, const float4* __restrict__ w1,
    const float4* __restrict__ w2, const float4* __restrict__ w3) {
  int blk = blockIdx.x;
  if (blk < 1024) {
    int w = blk * 256 + threadIdx.x;
    const int4* p = (const int4*)m4 + (size_t)w * 8;
    unsigned bits = 0;
#pragma unroll
    for (int j = 0; j < 8; j++) {
      int4 x = p[j];
      bits |= (unsigned)(x.x != 0) << (4 * j + 0);
      bits |= (unsigned)(x.y != 0) << (4 * j + 1);
      bits |= (unsigned)(x.z != 0) << (4 * j + 2);
      bits |= (unsigned)(x.w != 0) << (4 * j + 3);
    }
    g_mbits[w] = bits;
  } else if (blk < 13312) {
    int rel = blk - 1024;
    int y = rel / 4096;
    const float4* in = (y == 0) ? q : (y == 1) ? k : v;
    int i = (rel - y * 4096) * 256 + threadIdx.x;
    float4 f = in[i];
    ((uint2*)g_x16)[(size_t)y * (M_TOT * D_MODEL / 4) + i] =
        make_uint2(pack2(f.x, f.y), pack2(f.z, f.w));
  } else if (blk < 16384) {
    int rel = blk - 13312;
    int y = rel >> 10;
    const float4* in = (y == 0) ? w0 : (y == 1) ? w1 : w2;
    int n = rel & 1023;
    int p = (n & 15) * 64 + (n >> 4);
    int i = threadIdx.x;
    float4 f = in[(size_t)n * 256 + i];
    ((uint2*)g_w16)[(size_t)y * (D_MODEL * D_MODEL / 4) + (size_t)p * 256 + i] =
        make_uint2(pack2(f.x, f.y), pack2(f.z, f.w));
  } else {
    __shared__ __half s[D_MODEL];
    int j = blk - 16384;
    int i = threadIdx.x;
    float4 f = w3[(size_t)j * 256 + i];
    __half2* sp = (__half2*)&s[i * 4];
    sp[0] = __floats2half2_rn(f.x, f.y);
    sp[1] = __floats2half2_rn(f.z, f.w);
    __syncthreads();
    __half o[4];
#pragma unroll
    for (int e = 0; e < 4; e++) {
      int p = i * 4 + e;
      int n = ((p & 63) << 4) | (p >> 6);
      o[e] = s[n];
    }
    ((uint2*)g_w16)[3ull * (D_MODEL * D_MODEL / 4) + (size_t)j * 256 + i] =
        *(uint2*)o;
  }
}

// ---------------------------------------------------------------------------
// FP16 GEMM: 128(M) x 256(N) CTA tile, 512 threads (16 warps, 4/SMSP),
// warp tile 32x64 (mt<2, nt<8). KC=64, 3-stage cp.async pipeline.
// ---------------------------------------------------------------------------
#define GSTR 72
#define AT (128 * GSTR)
#define BT (256 * GSTR)
#define NSTG 3

#define GEMM_PRE()                                                         \
  extern __shared__ __half gsm[];                                          \
  unsigned sA = (unsigned)__cvta_generic_to_shared(gsm);                   \
  unsigned sB = sA + NSTG * AT * 2;                                        \
  int tid = threadIdx.x;                                                   \
  int m0 = blockIdx.y * 128;                                               \
  int n0 = blockIdx.x * 256;                                               \
  int wid = tid >> 5;                                                      \
  int lane = tid & 31;                                                     \
  int warp_m = (wid & 3) * 32;                                             \
  int warp_n = (wid >> 2) * 64;                                            \
  int grp = lane >> 2;                                                     \
  int thr = lane & 3;                                                      \
  int lrow = lane & 15;                                                    \
  int lcol = (lane >> 4) * 8;                                              \
  unsigned aAddr = sA + ((warp_m + lrow) * GSTR + lcol) * 2;               \
  unsigned bAddr = sB + ((warp_n + lrow) * GSTR + lcol) * 2;               \
  float acc[2][8][4];                                                      \
  _Pragma("unroll") for (int i = 0; i < 2; i++)                            \
  _Pragma("unroll") for (int j = 0; j < 8; j++)                            \
  _Pragma("unroll") for (int r = 0; r < 4; r++) acc[i][j][r] = 0.f;

#define GLOAD(k0, buf)                                                     \
  {                                                                        \
    _Pragma("unroll") for (int s = 0; s < 2; s++) {                        \
      int idx = tid + s * 512;                                             \
      int r = idx >> 3, ch = (idx & 7) * 8;                                \
      cpa16(sA + ((buf)*AT + r * GSTR + ch) * 2,                           \
            Ap + (size_t)r * D_MODEL + (k0) + ch);                         \
    }                                                                      \
    _Pragma("unroll") for (int s = 0; s < 4; s++) {                        \
      int idx = tid + s * 512;                                             \
      int r = idx >> 3, ch = (idx & 7) * 8;                                \
      cpa16(sB + ((buf)*BT + r * GSTR + ch) * 2,                           \
            Wp + (size_t)r * D_MODEL + (k0) + ch);                         \
    }                                                                      \
    cpcommit();                                                            \
  }

#define GEMM_MAIN()                                                        \
  GLOAD(0, 0);                                                             \
  GLOAD(64, 1);                                                            \
  for (int t = 0; t < D_MODEL / 64; t++) {                                 \
    int cur = t % NSTG;                                                    \
    cpwait1();                                                             \
    __syncthreads();                                                       \
    if (t + 2 < D_MODEL / 64) GLOAD((t + 2) * 64, (t + 2) % NSTG);         \
    unsigned aB = aAddr + cur * AT * 2;                                    \
    unsigned bB = bAddr + cur * BT * 2;                                    \
    _Pragma("unroll") for (int kk = 0; kk < 64; kk += 16) {                \
      unsigned af[2][4], bf[8][2];                                         \
      {                                                                    \
        unsigned a0, a1, a2, a3;                                           \
        LDSM4(a0, a1, a2, a3, aB + (((lane & 31) < 16 ? 0 : 0) * 0 + kk) * 2); \
        (void)a0;                                                          \
        af[0][0] = a0; af[0][1] = a1; af[0][2] = a2; af[0][3] = a3;        \
      }                                                                    \
      {                                                                    \
        unsigned a0, a1, a2, a3;                                           \
        LDSM4(a0, a1, a2, a3, aB + (16 * GSTR + kk) * 2);                  \
        af[1][0] = a0; af[1][1] = a1; af[1][2] = a2; af[1][3] = a3;        \
      }                                                                    \
      _Pragma("unroll") for (int ntp = 0; ntp < 4; ntp++) {                \
        unsigned b0, b1, b2, b3;                                           \
        LDSM4(b0, b1, b2, b3, bB + (ntp * 16 * GSTR + kk) * 2);            \
        bf[2 * ntp][0] = b0;                                               \
        bf[2 * ntp][1] = b2;                                               \
        bf[2 * ntp + 1][0] = b1;                                           \
        bf[2 * ntp + 1][1] = b3;                                           \
      }                                                                    \
      _Pragma("unroll") for (int mt = 0; mt < 2; mt++)                     \
      _Pragma("unroll") for (int nt = 0; nt < 8; nt++)                     \
        MMA16(acc[mt][nt], af[mt], bf[nt]);                                \
    }                                                                      \
  }

__global__ __launch_bounds__(512, 1) void gemm_qkv_kernel(
    const __half* __restrict__ X, const __half* __restrict__ Wb) {
  int z = blockIdx.z;
  const __half* Ap = X + (size_t)z * M_TOT * D_MODEL + (size_t)blockIdx.y * 128 * D_MODEL;
  const __half* Wp = Wb + (size_t)z * D_MODEL * D_MODEL + (size_t)blockIdx.x * 256 * D_MODEL;
  GEMM_PRE();
  GEMM_MAIN();
  __half* C = (z == 0) ? g_Qh : (z == 1) ? g_Kh : g_Vh;
  float s = (z == 0) ? QSCALE : 1.0f;
#pragma unroll
  for (int mt = 0; mt < 2; mt++) {
#pragma unroll
    for (int nt = 0; nt < 8; nt++) {
      int row = m0 + warp_m + mt * 16 + grp;
      int p = n0 + warp_n + nt * 8 + thr * 2;
      int h = p >> 6, d = p & 63;
      float* c = acc[mt][nt];
#pragma unroll
      for (int e = 0; e < 2; e++) {
        int r = row + e * 8;
        int b = r >> 11;
        int ii = r & (L_SEQ - 1);
        *(unsigned*)&C[((((size_t)b * NH + h) * L_SEQ) + ii) * DK + d] =
            pack2(c[2 * e] * s, c[2 * e + 1] * s);
      }
    }
  }
}

__global__ __launch_bounds__(512, 1) void gemm_out_kernel(
    const __half* __restrict__ A, const __half* __restrict__ W,
    float* __restrict__ C) {
  const __half* Ap = A + (size_t)blockIdx.y * 128 * D_MODEL;
  const __half* Wp = W + (size_t)blockIdx.x * 256 * D_MODEL;
  GEMM_PRE();
  GEMM_MAIN();
#pragma unroll
  for (int mt = 0; mt < 2; mt++) {
#pragma unroll
    for (int nt = 0; nt < 8; nt++) {
      int row = m0 + warp_m + mt * 16 + grp;
      int col = n0 + warp_n + nt * 8 + thr * 2;
      float* c = acc[mt][nt];
      *(float2*)&C[(size_t)row * D_MODEL + col] = make_float2(c[0], c[1]);
      *(float2*)&C[(size_t)(row + 8) * D_MODEL + col] = make_float2(c[2], c[3]);
    }
  }
}

// ---------------------------------------------------------------------------
// FP16 flash attention (unchanged from round 13).
// ---------------------------------------------------------------------------
#define PSTR 72
#define KVSZ (64 * PSTR)
__global__ __launch_bounds__(256, 2) void attn_mma_kernel(
    const __half* __restrict__ Qh, const __half* __restrict__ Kh,
    const __half* __restrict__ Vh, const unsigned* __restrict__ mbits,
    __half* __restrict__ Mha) {
  extern __shared__ __half smh[];
  __half* Ps = smh + 6 * KVSZ;
  unsigned sbase = (unsigned)__cvta_generic_to_shared(smh);

  int tid = threadIdx.x;
  int w = tid >> 5;
  int lane = tid & 31;
  int grp = lane >> 2;
  int thr = lane & 3;
  int lrow = lane & 15;
  int lcol = (lane >> 4) * 8;
  int i0 = blockIdx.x * 128;
  int h = blockIdx.y;
  int b = blockIdx.z;
  int bh = b * NH + h;
  const __half* Qb = Qh + (size_t)bh * L_SEQ * DK;
  const __half* Kb = Kh + (size_t)bh * L_SEQ * DK;
  const __half* Vb = Vh + (size_t)bh * L_SEQ * DK;

#define KV_ISSUE(o0, buf)                                                  \
  {                                                                        \
    unsigned kbb = sbase + (buf)*2 * KVSZ * 2;                             \
    unsigned vbb = kbb + KVSZ * 2;                                         \
    _Pragma("unroll") for (int s = 0; s < 2; s++) {                        \
      int idx = tid + s * 256;                                             \
      int r = idx >> 3, ch = (idx & 7) * 8;                                \
      cpa16(kbb + (r * PSTR + ch) * 2, Kb + (size_t)((o0) + r) * DK + ch); \
      cpa16(vbb + (r * PSTR + ch) * 2, Vb + (size_t)((o0) + r) * DK + ch); \
    }                                                                      \
    cpcommit();                                                            \
  }

  KV_ISSUE(0, 0);
  KV_ISSUE(64, 1);

#pragma unroll
  for (int it = 0; it < 4; it++) {
    int idx = tid + it * 256;
    int r = idx >> 3, ch = (idx & 7) * 8;
    *(uint4*)&Ps[r * PSTR + ch] = *(const uint4*)&Qb[(size_t)(i0 + r) * DK + ch];
  }
  __syncthreads();

  int rbase = w * 16;
  unsigned Qf[4][4];
#pragma unroll
  for (int kg = 0; kg < 4; kg++) {
    Qf[kg][0] = *(const unsigned*)&Ps[(rbase + grp) * PSTR + kg * 16 + 2 * thr];
    Qf[kg][1] = *(const unsigned*)&Ps[(rbase + grp + 8) * PSTR + kg * 16 + 2 * thr];
    Qf[kg][2] = *(const unsigned*)&Ps[(rbase + grp) * PSTR + kg * 16 + 2 * thr + 8];
    Qf[kg][3] = *(const unsigned*)&Ps[(rbase + grp + 8) * PSTR + kg * 16 + 2 * thr + 8];
  }

  int rA = i0 + rbase + grp;
  int rB = rA + 8;
  const unsigned long long* mbA =
      (const unsigned long long*)mbits + (size_t)(b * L_SEQ + rA) * (L_SEQ / 64);
  const unsigned long long* mbB =
      (const unsigned long long*)mbits + (size_t)(b * L_SEQ + rB) * (L_SEQ / 64);

  float mA = -CUDART_INF_F, mB = -CUDART_INF_F;
  float lA = 0.f, lB = 0.f;
  float oa[8][4];
#pragma unroll
  for (int nt = 0; nt < 8; nt++)
#pragma unroll
    for (int e = 0; e < 4; e++) oa[nt][e] = 0.f;

  const int NT = L_SEQ / 64;
  for (int ot = 0; ot < NT; ot++) {
    int cur = ot % 3;
    unsigned long long mWa = mbA[ot];
    unsigned long long mWb = mbB[ot];
    cpwait1();
    __syncthreads();
    if (ot + 2 < NT) KV_ISSUE((ot + 2) * 64, (ot + 2) % 3);
    unsigned kAddr = sbase + cur * 2 * KVSZ * 2 + (lrow * PSTR + lcol) * 2;
    unsigned vAddr = kAddr + KVSZ * 2;

    float sa[8][4];
#pragma unroll
    for (int nt = 0; nt < 8; nt++)
      sa[nt][0] = sa[nt][1] = sa[nt][2] = sa[nt][3] = 0.f;
#pragma unroll
    for (int ntp = 0; ntp < 4; ntp++) {
#pragma unroll
      for (int kg = 0; kg < 4; kg++) {
        unsigned b0, b1, b2, b3;
        LDSM4(b0, b1, b2, b3, kAddr + (ntp * 16 * PSTR + kg * 16) * 2);
        unsigned bfA[2] = {b0, b2}, bfB[2] = {b1, b3};
        MMA16(sa[2 * ntp], Qf[kg], bfA);
        MMA16(sa[2 * ntp + 1], Qf[kg], bfB);
      }
    }

    float mxA = -CUDART_INF_F, mxB = -CUDART_INF_F;
#pragma unroll
    for (int nt = 0; nt < 8; nt++) {
      int c0 = nt * 8 + 2 * thr;
      if ((mWa >> c0) & 1ull) sa[nt][0] = NEGL2;
      if ((mWa >> (c0 + 1)) & 1ull) sa[nt][1] = NEGL2;
      if ((mWb >> c0) & 1ull) sa[nt][2] = NEGL2;
      if ((mWb >> (c0 + 1)) & 1ull) sa[nt][3] = NEGL2;
      mxA = fmaxf(mxA, fmaxf(sa[nt][0], sa[nt][1]));
      mxB = fmaxf(mxB, fmaxf(sa[nt][2], sa[nt][3]));
    }
    mxA = fmaxf(mxA, __shfl_xor_sync(0xffffffffu, mxA, 1));
    mxA = fmaxf(mxA, __shfl_xor_sync(0xffffffffu, mxA, 2));
    mxB = fmaxf(mxB, __shfl_xor_sync(0xffffffffu, mxB, 1));
    mxB = fmaxf(mxB, __shfl_xor_sync(0xffffffffu, mxB, 2));

    float nmA = fmaxf(mA, mxA), nmB = fmaxf(mB, mxB);
    float cA = ex2f(mA - nmA), cB = ex2f(mB - nmB);
    float sumA = 0.f, sumB = 0.f;
    unsigned pf[4][4];
#pragma unroll
    for (int nt = 0; nt < 8; nt++) {
      float p0 = ex2f(sa[nt][0] - nmA);
      float p1 = ex2f(sa[nt][1] - nmA);
      float p2 = ex2f(sa[nt][2] - nmB);
      float p3 = ex2f(sa[nt][3] - nmB);
      sumA += p0 + p1;
      sumB += p2 + p3;
      int kg = nt >> 1;
      if ((nt & 1) == 0) {
        pf[kg][0] = pack2(p0, p1);
        pf[kg][1] = pack2(p2, p3);
      } else {
        pf[kg][2] = pack2(p0, p1);
        pf[kg][3] = pack2(p2, p3);
      }
    }
    sumA += __shfl_xor_sync(0xffffffffu, sumA, 1);
    sumA += __shfl_xor_sync(0xffffffffu, sumA, 2);
    sumB += __shfl_xor_sync(0xffffffffu, sumB, 1);
    sumB += __shfl_xor_sync(0xffffffffu, sumB, 2);
    lA = lA * cA + sumA;
    lB = lB * cB + sumB;
    mA = nmA;
    mB = nmB;

#pragma unroll
    for (int nt = 0; nt < 8; nt++) {
      oa[nt][0] *= cA;
      oa[nt][1] *= cA;
      oa[nt][2] *= cB;
      oa[nt][3] *= cB;
    }

#pragma unroll
    for (int ntp = 0; ntp < 4; ntp++) {
#pragma unroll
      for (int kg = 0; kg < 4; kg++) {
        unsigned b0, b1, b2, b3;
        LDSM4T(b0, b1, b2, b3, vAddr + (kg * 16 * PSTR + ntp * 16) * 2);
        unsigned bfA[2] = {b0, b1}, bfB[2] = {b2, b3};
        MMA16(oa[2 * ntp], pf[kg], bfA);
        MMA16(oa[2 * ntp + 1], pf[kg], bfB);
      }
    }
  }

  float iA = 1.f / lA, iB = 1.f / lB;
  __half* outA = &Mha[(size_t)(b * L_SEQ + rA) * D_MODEL + h * 64];
  __half* outB = &Mha[(size_t)(b * L_SEQ + rB) * D_MODEL + h * 64];
#pragma unroll
  for (int nt = 0; nt < 8; nt++) {
    int d0 = nt * 8 + 2 * thr;
    *(unsigned*)&outA[d0] = pack2(oa[nt][0] * iA, oa[nt][1] * iA);
    *(unsigned*)&outB[d0] = pack2(oa[nt][2] * iB, oa[nt][3] * iB);
  }
}

// ---------------------------------------------------------------------------
extern "C" void kernel_launch(void* const* d_in, const int* in_sizes, int n_in,
                              void* d_out, int out_size) {
  const int* mask4 = (const int*)d_in[3];
  float* out = (float*)d_out;

  __half *Qh, *Kh, *Vh, *Mh, *X16, *W16;
  unsigned* Mb;
  cudaGetSymbolAddress((void**)&Qh, g_Qh);
  cudaGetSymbolAddress((void**)&Kh, g_Kh);
  cudaGetSymbolAddress((void**)&Vh, g_Vh);
  cudaGetSymbolAddress((void**)&Mh, g_Mha);
  cudaGetSymbolAddress((void**)&Mb, g_mbits);
  cudaGetSymbolAddress((void**)&X16, g_x16);
  cudaGetSymbolAddress((void**)&W16, g_w16);

  prologue_kernel<<<17408, 256>>>(
      mask4, (const float4*)d_in[0], (const float4*)d_in[1],
      (const float4*)d_in[2], (const float4*)d_in[4], (const float4*)d_in[5],
      (const float4*)d_in[6], (const float4*)d_in[7]);

  int gsmem = NSTG * (AT + BT) * 2;  // 165888 bytes
  cudaFuncSetAttribute(gemm_qkv_kernel, cudaFuncAttributeMaxDynamicSharedMemorySize, gsmem);
  cudaFuncSetAttribute(gemm_out_kernel, cudaFuncAttributeMaxDynamicSharedMemorySize, gsmem);

  dim3 gq(D_MODEL / 256, M_TOT / 128, 3);  // (4, 32, 3)
  gemm_qkv_kernel<<<gq, 512, gsmem>>>(X16, W16);

  int asmem = (6 * KVSZ + 128 * PSTR) * 2;  // 73728
  cudaFuncSetAttribute(attn_mma_kernel,
                       cudaFuncAttributeMaxDynamicSharedMemorySize, asmem);
  dim3 ag(L_SEQ / 128, NH, B_SZ);
  attn_mma_kernel<<<ag, 256, asmem>>>(Qh, Kh, Vh, Mb, Mh);

  dim3 go(D_MODEL / 256, M_TOT / 128);  // (4, 32)
  gemm_out_kernel<<<go, 512, gsmem>>>(Mh, W16 + 3ull * D_MODEL * D_MODEL, out);
}

// round 16
// speedup vs baseline: 2.4094x; 1.0045x over previous
#include <cuda_runtime.h>
#include <cuda_fp16.h>
#include <math_constants.h>

#define B_SZ 2
#define L_SEQ 2048
#define D_MODEL 1024
#define NH 16
#define DK 64
#define M_TOT (B_SZ * L_SEQ)
#define NEGL2 (-1.44269504e10f)
#define QSCALE (0.125f * 1.442695040888963f)

// Scratch (device globals). All fp16.
__device__ __align__(16) __half g_Qh[B_SZ * NH * L_SEQ * DK];  // [b,h,i,d]
__device__ __align__(16) __half g_Kh[B_SZ * NH * L_SEQ * DK];  // [b,h,o,d]
__device__ __align__(16) __half g_Vh[B_SZ * NH * L_SEQ * DK];  // [b,h,o,d]
__device__ __align__(16) __half g_Mha[M_TOT * D_MODEL];        // [m][h*64+d]
__device__ unsigned g_mbits[B_SZ * L_SEQ * L_SEQ / 32];
__device__ __align__(16) __half g_x16[3][M_TOT * D_MODEL];
__device__ __align__(16) __half g_w16[4][D_MODEL * D_MODEL];

__device__ __forceinline__ void cpa16(unsigned d, const void* s) {
  asm volatile("cp.async.cg.shared.global [%0], [%1], 16;" :: "r"(d), "l"(s));
}
__device__ __forceinline__ void cpcommit() { asm volatile("cp.async.commit_group;"); }
__device__ __forceinline__ void cpwait1() { asm volatile("cp.async.wait_group 1;"); }
__device__ __forceinline__ float ex2f(float x) {
  float r;
  asm("ex2.approx.ftz.f32 %0, %1;" : "=f"(r) : "f"(x));
  return r;
}
__device__ __forceinline__ unsigned pack2(float a, float b) {
  __half2 h = __floats2half2_rn(a, b);
  return *(unsigned*)&h;
}
#define MMA16(c, a, b)                                                    \
  asm volatile(                                                           \
      "mma.sync.aligned.m16n8k16.row.col.f32.f16.f16.f32 "                \
      "{%0,%1,%2,%3}, {%4,%5,%6,%7}, {%8,%9}, {%0,%1,%2,%3};"             \
      : "+f"((c)[0]), "+f"((c)[1]), "+f"((c)[2]), "+f"((c)[3])            \
      : "r"((a)[0]), "r"((a)[1]), "r"((a)[2]), "r"((a)[3]), "r"((b)[0]),  \
        "r"((b)[1]))
#define LDSM4(r0, r1, r2, r3, addr)                                       \
  asm volatile(                                                           \
      "ldmatrix.sync.aligned.m8n8.x4.shared.b16 {%0,%1,%2,%3}, [%4];"     \
      : "=r"(r0), "=r"(r1), "=r"(r2), "=r"(r3) : "r"(addr))
#define LDSM4T(r0, r1, r2, r3, addr)                                      \
  asm volatile(                                                           \
      "ldmatrix.sync.aligned.m8n8.x4.trans.shared.b16 {%0,%1,%2,%3}, [%4];" \
      : "=r"(r0), "=r"(r1), "=r"(r2), "=r"(r3) : "r"(addr))

// ---------------------------------------------------------------------------
// Fused prologue (unchanged).
// ---------------------------------------------------------------------------
__global__ __launch_bounds__(256) void prologue_kernel(
    const int* __restrict__ m4, const float4* __restrict__ q,
    const float4* __restrict__ k, const float4* __restrict__ v,
    const float4* __restrict__ w0, const float4* __restrict__ w1,
    const float4* __restrict__ w2, const float4* __restrict__ w3) {
  int blk = blockIdx.x;
  if (blk < 1024) {
    int w = blk * 256 + threadIdx.x;
    const int4* p = (const int4*)m4 + (size_t)w * 8;
    unsigned bits = 0;
#pragma unroll
    for (int j = 0; j < 8; j++) {
      int4 x = p[j];
      bits |= (unsigned)(x.x != 0) << (4 * j + 0);
      bits |= (unsigned)(x.y != 0) << (4 * j + 1);
      bits |= (unsigned)(x.z != 0) << (4 * j + 2);
      bits |= (unsigned)(x.w != 0) << (4 * j + 3);
    }
    g_mbits[w] = bits;
  } else if (blk < 13312) {
    int rel = blk - 1024;
    int y = rel / 4096;
    const float4* in = (y == 0) ? q : (y == 1) ? k : v;
    int i = (rel - y * 4096) * 256 + threadIdx.x;
    float4 f = in[i];
    ((uint2*)g_x16)[(size_t)y * (M_TOT * D_MODEL / 4) + i] =
        make_uint2(pack2(f.x, f.y), pack2(f.z, f.w));
  } else if (blk < 16384) {
    int rel = blk - 13312;
    int y = rel >> 10;
    const float4* in = (y == 0) ? w0 : (y == 1) ? w1 : w2;
    int n = rel & 1023;
    int p = (n & 15) * 64 + (n >> 4);
    int i = threadIdx.x;
    float4 f = in[(size_t)n * 256 + i];
    ((uint2*)g_w16)[(size_t)y * (D_MODEL * D_MODEL / 4) + (size_t)p * 256 + i] =
        make_uint2(pack2(f.x, f.y), pack2(f.z, f.w));
  } else {
    __shared__ __half s[D_MODEL];
    int j = blk - 16384;
    int i = threadIdx.x;
    float4 f = w3[(size_t)j * 256 + i];
    __half2* sp = (__half2*)&s[i * 4];
    sp[0] = __floats2half2_rn(f.x, f.y);
    sp[1] = __floats2half2_rn(f.z, f.w);
    __syncthreads();
    __half o[4];
#pragma unroll
    for (int e = 0; e < 4; e++) {
      int p = i * 4 + e;
      int n = ((p & 63) << 4) | (p >> 6);
      o[e] = s[n];
    }
    ((uint2*)g_w16)[3ull * (D_MODEL * D_MODEL / 4) + (size_t)j * 256 + i] =
        *(uint2*)o;
  }
}

// ---------------------------------------------------------------------------
// FP16 GEMM: 128(M) x 128(N) CTA tile, 256 threads (8 warps), warp tile
// 32x64 (mt<2, nt<8). KC=64, 3-stage cp.async pipeline, 2 CTAs/SM.
// ---------------------------------------------------------------------------
#define GSTR 72
#define AT (128 * GSTR)
#define NSTG 3

#define GEMM_PRE()                                                         \
  extern __shared__ __half gsm[];                                          \
  unsigned sA = (unsigned)__cvta_generic_to_shared(gsm);                   \
  unsigned sB = sA + NSTG * AT * 2;                                        \
  int tid = threadIdx.x;                                                   \
  int m0 = blockIdx.y * 128;                                               \
  int n0 = blockIdx.x * 128;                                               \
  int wid = tid >> 5;                                                      \
  int lane = tid & 31;                                                     \
  int warp_m = (wid & 3) * 32;                                             \
  int warp_n = (wid >> 2) * 64;                                            \
  int grp = lane >> 2;                                                     \
  int thr = lane & 3;                                                      \
  int lrow = lane & 15;                                                    \
  int lcol = (lane >> 4) * 8;                                              \
  unsigned aAddr = sA + ((warp_m + lrow) * GSTR + lcol) * 2;               \
  unsigned bAddr = sB + ((warp_n + lrow) * GSTR + lcol) * 2;               \
  float acc[2][8][4];                                                      \
  _Pragma("unroll") for (int i = 0; i < 2; i++)                            \
  _Pragma("unroll") for (int j = 0; j < 8; j++)                            \
  _Pragma("unroll") for (int r = 0; r < 4; r++) acc[i][j][r] = 0.f;

#define GLOAD(k0, buf)                                                     \
  {                                                                        \
    _Pragma("unroll") for (int s = 0; s < 4; s++) {                        \
      int idx = tid + s * 256;                                             \
      int r = idx >> 3, ch = (idx & 7) * 8;                                \
      cpa16(sA + ((buf)*AT + r * GSTR + ch) * 2,                           \
            Ap + (size_t)r * D_MODEL + (k0) + ch);                         \
      cpa16(sB + ((buf)*AT + r * GSTR + ch) * 2,                           \
            Wp + (size_t)r * D_MODEL + (k0) + ch);                         \
    }                                                                      \
    cpcommit();                                                            \
  }

#define GEMM_MAIN()                                                        \
  GLOAD(0, 0);                                                             \
  GLOAD(64, 1);                                                            \
  for (int t = 0; t < D_MODEL / 64; t++) {                                 \
    int cur = t % NSTG;                                                    \
    cpwait1();                                                             \
    __syncthreads();                                                       \
    if (t + 2 < D_MODEL / 64) GLOAD((t + 2) * 64, (t + 2) % NSTG);         \
    unsigned aB = aAddr + cur * AT * 2;                                    \
    unsigned bB = bAddr + cur * AT * 2;                                    \
    _Pragma("unroll") for (int kk = 0; kk < 64; kk += 16) {                \
      unsigned af[2][4], bf[8][2];                                         \
      _Pragma("unroll") for (int mt = 0; mt < 2; mt++)                     \
        LDSM4(af[mt][0], af[mt][1], af[mt][2], af[mt][3],                  \
              aB + (mt * 16 * GSTR + kk) * 2);                             \
      _Pragma("unroll") for (int ntp = 0; ntp < 4; ntp++) {                \
        unsigned b0, b1, b2, b3;                                           \
        LDSM4(b0, b1, b2, b3, bB + (ntp * 16 * GSTR + kk) * 2);            \
        bf[2 * ntp][0] = b0;                                               \
        bf[2 * ntp][1] = b2;                                               \
        bf[2 * ntp + 1][0] = b1;                                           \
        bf[2 * ntp + 1][1] = b3;                                           \
      }                                                                    \
      _Pragma("unroll") for (int mt = 0; mt < 2; mt++)                     \
      _Pragma("unroll") for (int nt = 0; nt < 8; nt++)                     \
        MMA16(acc[mt][nt], af[mt], bf[nt]);                                \
    }                                                                      \
  }

__global__ __launch_bounds__(256, 2) void gemm_qkv_kernel(
    const __half* __restrict__ X, const __half* __restrict__ Wb) {
  int z = blockIdx.z;
  const __half* Ap = X + (size_t)z * M_TOT * D_MODEL + (size_t)blockIdx.y * 128 * D_MODEL;
  const __half* Wp = Wb + (size_t)z * D_MODEL * D_MODEL + (size_t)blockIdx.x * 128 * D_MODEL;
  GEMM_PRE();
  GEMM_MAIN();
  __half* C = (z == 0) ? g_Qh : (z == 1) ? g_Kh : g_Vh;
  float s = (z == 0) ? QSCALE : 1.0f;
#pragma unroll
  for (int mt = 0; mt < 2; mt++) {
#pragma unroll
    for (int nt = 0; nt < 8; nt++) {
      int row = m0 + warp_m + mt * 16 + grp;
      int p = n0 + warp_n + nt * 8 + thr * 2;
      int h = p >> 6, d = p & 63;
      float* c = acc[mt][nt];
#pragma unroll
      for (int e = 0; e < 2; e++) {
        int r = row + e * 8;
        int b = r >> 11;
        int ii = r & (L_SEQ - 1);
        *(unsigned*)&C[((((size_t)b * NH + h) * L_SEQ) + ii) * DK + d] =
            pack2(c[2 * e] * s, c[2 * e + 1] * s);
      }
    }
  }
}

__global__ __launch_bounds__(256, 2) void gemm_out_kernel(
    const __half* __restrict__ A, const __half* __restrict__ W,
    float* __restrict__ C) {
  const __half* Ap = A + (size_t)blockIdx.y * 128 * D_MODEL;
  const __half* Wp = W + (size_t)blockIdx.x * 128 * D_MODEL;
  GEMM_PRE();
  GEMM_MAIN();
#pragma unroll
  for (int mt = 0; mt < 2; mt++) {
#pragma unroll
    for (int nt = 0; nt < 8; nt++) {
      int row = m0 + warp_m + mt * 16 + grp;
      int col = n0 + warp_n + nt * 8 + thr * 2;
      float* c = acc[mt][nt];
      *(float2*)&C[(size_t)row * D_MODEL + col] = make_float2(c[0], c[1]);
      *(float2*)&C[(size_t)(row + 8) * D_MODEL + col] = make_float2(c[2], c[3]);
    }
  }
}

// ---------------------------------------------------------------------------
// FP16 flash attention (unchanged).
// ---------------------------------------------------------------------------
#define PSTR 72
#define KVSZ (64 * PSTR)
__global__ __launch_bounds__(256, 2) void attn_mma_kernel(
    const __half* __restrict__ Qh, const __half* __restrict__ Kh,
    const __half* __restrict__ Vh, const unsigned* __restrict__ mbits,
    __half* __restrict__ Mha) {
  extern __shared__ __half smh[];
  __half* Ps = smh + 6 * KVSZ;
  unsigned sbase = (unsigned)__cvta_generic_to_shared(smh);

  int tid = threadIdx.x;
  int w = tid >> 5;
  int lane = tid & 31;
  int grp = lane >> 2;
  int thr = lane & 3;
  int lrow = lane & 15;
  int lcol = (lane >> 4) * 8;
  int i0 = blockIdx.x * 128;
  int h = blockIdx.y;
  int b = blockIdx.z;
  int bh = b * NH + h;
  const __half* Qb = Qh + (size_t)bh * L_SEQ * DK;
  const __half* Kb = Kh + (size_t)bh * L_SEQ * DK;
  const __half* Vb = Vh + (size_t)bh * L_SEQ * DK;

#define KV_ISSUE(o0, buf)                                                  \
  {                                                                        \
    unsigned kbb = sbase + (buf)*2 * KVSZ * 2;                             \
    unsigned vbb = kbb + KVSZ * 2;                                         \
    _Pragma("unroll") for (int s = 0; s < 2; s++) {                        \
      int idx = tid + s * 256;                                             \
      int r = idx >> 3, ch = (idx & 7) * 8;                                \
      cpa16(kbb + (r * PSTR + ch) * 2, Kb + (size_t)((o0) + r) * DK + ch); \
      cpa16(vbb + (r * PSTR + ch) * 2, Vb + (size_t)((o0) + r) * DK + ch); \
    }                                                                      \
    cpcommit();                                                            \
  }

  KV_ISSUE(0, 0);
  KV_ISSUE(64, 1);

#pragma unroll
  for (int it = 0; it < 4; it++) {
    int idx = tid + it * 256;
    int r = idx >> 3, ch = (idx & 7) * 8;
    *(uint4*)&Ps[r * PSTR + ch] = *(const uint4*)&Qb[(size_t)(i0 + r) * DK + ch];
  }
  __syncthreads();

  int rbase = w * 16;
  unsigned Qf[4][4];
#pragma unroll
  for (int kg = 0; kg < 4; kg++) {
    Qf[kg][0] = *(const unsigned*)&Ps[(rbase + grp) * PSTR + kg * 16 + 2 * thr];
    Qf[kg][1] = *(const unsigned*)&Ps[(rbase + grp + 8) * PSTR + kg * 16 + 2 * thr];
    Qf[kg][2] = *(const unsigned*)&Ps[(rbase + grp) * PSTR + kg * 16 + 2 * thr + 8];
    Qf[kg][3] = *(const unsigned*)&Ps[(rbase + grp + 8) * PSTR + kg * 16 + 2 * thr + 8];
  }

  int rA = i0 + rbase + grp;
  int rB = rA + 8;
  const unsigned long long* mbA =
      (const unsigned long long*)mbits + (size_t)(b * L_SEQ + rA) * (L_SEQ / 64);
  const unsigned long long* mbB =
      (const unsigned long long*)mbits + (size_t)(b * L_SEQ + rB) * (L_SEQ / 64);

  float mA = -CUDART_INF_F, mB = -CUDART_INF_F;
  float lA = 0.f, lB = 0.f;
  float oa[8][4];
#pragma unroll
  for (int nt = 0; nt < 8; nt++)
#pragma unroll
    for (int e = 0; e < 4; e++) oa[nt][e] = 0.f;

  const int NT = L_SEQ / 64;
  for (int ot = 0; ot < NT; ot++) {
    int cur = ot % 3;
    unsigned long long mWa = mbA[ot];
    unsigned long long mWb = mbB[ot];
    cpwait1();
    __syncthreads();
    if (ot + 2 < NT) KV_ISSUE((ot + 2) * 64, (ot + 2) % 3);
    unsigned kAddr = sbase + cur * 2 * KVSZ * 2 + (lrow * PSTR + lcol) * 2;
    unsigned vAddr = kAddr + KVSZ * 2;

    float sa[8][4];
#pragma unroll
    for (int nt = 0; nt < 8; nt++)
      sa[nt][0] = sa[nt][1] = sa[nt][2] = sa[nt][3] = 0.f;
#pragma unroll
    for (int ntp = 0; ntp < 4; ntp++) {
#pragma unroll
      for (int kg = 0; kg < 4; kg++) {
        unsigned b0, b1, b2, b3;
        LDSM4(b0, b1, b2, b3, kAddr + (ntp * 16 * PSTR + kg * 16) * 2);
        unsigned bfA[2] = {b0, b2}, bfB[2] = {b1, b3};
        MMA16(sa[2 * ntp], Qf[kg], bfA);
        MMA16(sa[2 * ntp + 1], Qf[kg], bfB);
      }
    }

    float mxA = -CUDART_INF_F, mxB = -CUDART_INF_F;
#pragma unroll
    for (int nt = 0; nt < 8; nt++) {
      int c0 = nt * 8 + 2 * thr;
      if ((mWa >> c0) & 1ull) sa[nt][0] = NEGL2;
      if ((mWa >> (c0 + 1)) & 1ull) sa[nt][1] = NEGL2;
      if ((mWb >> c0) & 1ull) sa[nt][2] = NEGL2;
      if ((mWb >> (c0 + 1)) & 1ull) sa[nt][3] = NEGL2;
      mxA = fmaxf(mxA, fmaxf(sa[nt][0], sa[nt][1]));
      mxB = fmaxf(mxB, fmaxf(sa[nt][2], sa[nt][3]));
    }
    mxA = fmaxf(mxA, __shfl_xor_sync(0xffffffffu, mxA, 1));
    mxA = fmaxf(mxA, __shfl_xor_sync(0xffffffffu, mxA, 2));
    mxB = fmaxf(mxB, __shfl_xor_sync(0xffffffffu, mxB, 1));
    mxB = fmaxf(mxB, __shfl_xor_sync(0xffffffffu, mxB, 2));

    float nmA = fmaxf(mA, mxA), nmB = fmaxf(mB, mxB);
    float cA = ex2f(mA - nmA), cB = ex2f(mB - nmB);
    float sumA = 0.f, sumB = 0.f;
    unsigned pf[4][4];
#pragma unroll
    for (int nt = 0; nt < 8; nt++) {
      float p0 = ex2f(sa[nt][0] - nmA);
      float p1 = ex2f(sa[nt][1] - nmA);
      float p2 = ex2f(sa[nt][2] - nmB);
      float p3 = ex2f(sa[nt][3] - nmB);
      sumA += p0 + p1;
      sumB += p2 + p3;
      int kg = nt >> 1;
      if ((nt & 1) == 0) {
        pf[kg][0] = pack2(p0, p1);
        pf[kg][1] = pack2(p2, p3);
      } else {
        pf[kg][2] = pack2(p0, p1);
        pf[kg][3] = pack2(p2, p3);
      }
    }
    sumA += __shfl_xor_sync(0xffffffffu, sumA, 1);
    sumA += __shfl_xor_sync(0xffffffffu, sumA, 2);
    sumB += __shfl_xor_sync(0xffffffffu, sumB, 1);
    sumB += __shfl_xor_sync(0xffffffffu, sumB, 2);
    lA = lA * cA + sumA;
    lB = lB * cB + sumB;
    mA = nmA;
    mB = nmB;

#pragma unroll
    for (int nt = 0; nt < 8; nt++) {
      oa[nt][0] *= cA;
      oa[nt][1] *= cA;
      oa[nt][2] *= cB;
      oa[nt][3] *= cB;
    }

#pragma unroll
    for (int ntp = 0; ntp < 4; ntp++) {
#pragma unroll
      for (int kg = 0; kg < 4; kg++) {
        unsigned b0, b1, b2, b3;
        LDSM4T(b0, b1, b2, b3, vAddr + (kg * 16 * PSTR + ntp * 16) * 2);
        unsigned bfA[2] = {b0, b1}, bfB[2] = {b2, b3};
        MMA16(oa[2 * ntp], pf[kg], bfA);
        MMA16(oa[2 * ntp + 1], pf[kg], bfB);
      }
    }
  }

  float iA = 1.f / lA, iB = 1.f / lB;
  __half* outA = &Mha[(size_t)(b * L_SEQ + rA) * D_MODEL + h * 64];
  __half* outB = &Mha[(size_t)(b * L_SEQ + rB) * D_MODEL + h * 64];
#pragma unroll
  for (int nt = 0; nt < 8; nt++) {
    int d0 = nt * 8 + 2 * thr;
    *(unsigned*)&outA[d0] = pack2(oa[nt][0] * iA, oa[nt][1] * iA);
    *(unsigned*)&outB[d0] = pack2(oa[nt][2] * iB, oa[nt][3] * iB);
  }
}

// ---------------------------------------------------------------------------
extern "C" void kernel_launch(void* const* d_in, const int* in_sizes, int n_in,
                              void* d_out, int out_size) {
  const int* mask4 = (const int*)d_in[3];
  float* out = (float*)d_out;

  __half *Qh, *Kh, *Vh, *Mh, *X16, *W16;
  unsigned* Mb;
  cudaGetSymbolAddress((void**)&Qh, g_Qh);
  cudaGetSymbolAddress((void**)&Kh, g_Kh);
  cudaGetSymbolAddress((void**)&Vh, g_Vh);
  cudaGetSymbolAddress((void**)&Mh, g_Mha);
  cudaGetSymbolAddress((void**)&Mb, g_mbits);
  cudaGetSymbolAddress((void**)&X16, g_x16);
  cudaGetSymbolAddress((void**)&W16, g_w16);

  prologue_kernel<<<17408, 256>>>(
      mask4, (const float4*)d_in[0], (const float4*)d_in[1],
      (const float4*)d_in[2], (const float4*)d_in[4], (const float4*)d_in[5],
      (const float4*)d_in[6], (const float4*)d_in[7]);

  int gsmem = NSTG * 2 * AT * 2;  // 110592 bytes
  cudaFuncSetAttribute(gemm_qkv_kernel, cudaFuncAttributeMaxDynamicSharedMemorySize, gsmem);
  cudaFuncSetAttribute(gemm_out_kernel, cudaFuncAttributeMaxDynamicSharedMemorySize, gsmem);

  dim3 gq(D_MODEL / 128, M_TOT / 128, 3);  // (8, 32, 3)
  gemm_qkv_kernel<<<gq, 256, gsmem>>>(X16, W16);

  int asmem = (6 * KVSZ + 128 * PSTR) * 2;  // 73728
  cudaFuncSetAttribute(attn_mma_kernel,
                       cudaFuncAttributeMaxDynamicSharedMemorySize, asmem);
  dim3 ag(L_SEQ / 128, NH, B_SZ);
  attn_mma_kernel<<<ag, 256, asmem>>>(Qh, Kh, Vh, Mb, Mh);

  dim3 go(D_MODEL / 128, M_TOT / 128);  // (8, 32)
  gemm_out_kernel<<<go, 256, gsmem>>>(Mh, W16 + 3ull * D_MODEL * D_MODEL, out);
}

// round 17
// speedup vs baseline: 2.4122x; 1.0011x over previous
#include <cuda_runtime.h>
#include <cuda_fp16.h>
#include <math_constants.h>

#define B_SZ 2
#define L_SEQ 2048
#define D_MODEL 1024
#define NH 16
#define DK 64
#define M_TOT (B_SZ * L_SEQ)
#define NEGL2 (-1.44269504e10f)
#define QSCALE (0.125f * 1.442695040888963f)

// Scratch (device globals). All fp16.
__device__ __align__(16) __half g_Qh[B_SZ * NH * L_SEQ * DK];  // [b,h,i,d]
__device__ __align__(16) __half g_Kh[B_SZ * NH * L_SEQ * DK];  // [b,h,o,d]
__device__ __align__(16) __half g_Vh[B_SZ * NH * L_SEQ * DK];  // [b,h,o,d]
__device__ __align__(16) __half g_Mha[M_TOT * D_MODEL];        // [m][h*64+d]
__device__ unsigned g_mbits[B_SZ * L_SEQ * L_SEQ / 32];
__device__ __align__(16) __half g_x16[3][M_TOT * D_MODEL];
__device__ __align__(16) __half g_w16[4][D_MODEL * D_MODEL];

__device__ __forceinline__ void cpa16(unsigned d, const void* s) {
  asm volatile("cp.async.cg.shared.global [%0], [%1], 16;" :: "r"(d), "l"(s));
}
__device__ __forceinline__ void cpcommit() { asm volatile("cp.async.commit_group;"); }
__device__ __forceinline__ void cpwait1() { asm volatile("cp.async.wait_group 1;"); }
__device__ __forceinline__ float ex2f(float x) {
  float r;
  asm("ex2.approx.ftz.f32 %0, %1;" : "=f"(r) : "f"(x));
  return r;
}
__device__ __forceinline__ unsigned pack2(float a, float b) {
  __half2 h = __floats2half2_rn(a, b);
  return *(unsigned*)&h;
}
#define MMA16(c, a, b)                                                    \
  asm volatile(                                                           \
      "mma.sync.aligned.m16n8k16.row.col.f32.f16.f16.f32 "                \
      "{%0,%1,%2,%3}, {%4,%5,%6,%7}, {%8,%9}, {%0,%1,%2,%3};"             \
      : "+f"((c)[0]), "+f"((c)[1]), "+f"((c)[2]), "+f"((c)[3])            \
      : "r"((a)[0]), "r"((a)[1]), "r"((a)[2]), "r"((a)[3]), "r"((b)[0]),  \
        "r"((b)[1]))
#define LDSM4(r0, r1, r2, r3, addr)                                       \
  asm volatile(                                                           \
      "ldmatrix.sync.aligned.m8n8.x4.shared.b16 {%0,%1,%2,%3}, [%4];"     \
      : "=r"(r0), "=r"(r1), "=r"(r2), "=r"(r3) : "r"(addr))
#define LDSM4T(r0, r1, r2, r3, addr)                                      \
  asm volatile(                                                           \
      "ldmatrix.sync.aligned.m8n8.x4.trans.shared.b16 {%0,%1,%2,%3}, [%4];" \
      : "=r"(r0), "=r"(r1), "=r"(r2), "=r"(r3) : "r"(addr))

// ---------------------------------------------------------------------------
// Fused prologue (unchanged).
// ---------------------------------------------------------------------------
__global__ __launch_bounds__(256) void prologue_kernel(
    const int* __restrict__ m4, const float4* __restrict__ q,
    const float4* __restrict__ k, const float4* __restrict__ v,
    const float4* __restrict__ w0, const float4* __restrict__ w1,
    const float4* __restrict__ w2, const float4* __restrict__ w3) {
  int blk = blockIdx.x;
  if (blk < 1024) {
    int w = blk * 256 + threadIdx.x;
    const int4* p = (const int4*)m4 + (size_t)w * 8;
    unsigned bits = 0;
#pragma unroll
    for (int j = 0; j < 8; j++) {
      int4 x = p[j];
      bits |= (unsigned)(x.x != 0) << (4 * j + 0);
      bits |= (unsigned)(x.y != 0) << (4 * j + 1);
      bits |= (unsigned)(x.z != 0) << (4 * j + 2);
      bits |= (unsigned)(x.w != 0) << (4 * j + 3);
    }
    g_mbits[w] = bits;
  } else if (blk < 13312) {
    int rel = blk - 1024;
    int y = rel / 4096;
    const float4* in = (y == 0) ? q : (y == 1) ? k : v;
    int i = (rel - y * 4096) * 256 + threadIdx.x;
    float4 f = in[i];
    ((uint2*)g_x16)[(size_t)y * (M_TOT * D_MODEL / 4) + i] =
        make_uint2(pack2(f.x, f.y), pack2(f.z, f.w));
  } else if (blk < 16384) {
    int rel = blk - 13312;
    int y = rel >> 10;
    const float4* in = (y == 0) ? w0 : (y == 1) ? w1 : w2;
    int n = rel & 1023;
    int p = (n & 15) * 64 + (n >> 4);
    int i = threadIdx.x;
    float4 f = in[(size_t)n * 256 + i];
    ((uint2*)g_w16)[(size_t)y * (D_MODEL * D_MODEL / 4) + (size_t)p * 256 + i] =
        make_uint2(pack2(f.x, f.y), pack2(f.z, f.w));
  } else {
    __shared__ __half s[D_MODEL];
    int j = blk - 16384;
    int i = threadIdx.x;
    float4 f = w3[(size_t)j * 256 + i];
    __half2* sp = (__half2*)&s[i * 4];
    sp[0] = __floats2half2_rn(f.x, f.y);
    sp[1] = __floats2half2_rn(f.z, f.w);
    __syncthreads();
    __half o[4];
#pragma unroll
    for (int e = 0; e < 4; e++) {
      int p = i * 4 + e;
      int n = ((p & 63) << 4) | (p >> 6);
      o[e] = s[n];
    }
    ((uint2*)g_w16)[3ull * (D_MODEL * D_MODEL / 4) + (size_t)j * 256 + i] =
        *(uint2*)o;
  }
}

// ---------------------------------------------------------------------------
// FP16 GEMM: 128(M) x 128(N) CTA tile, 256 threads (8 warps), warp tile
// 32x64 (mt<2, nt<8). KC=64, 3-stage cp.async pipeline, 2 CTAs/SM.
// ---------------------------------------------------------------------------
#define GSTR 72
#define AT (128 * GSTR)
#define NSTG 3

#define GEMM_PRE()                                                         \
  extern __shared__ __half gsm[];                                          \
  unsigned sA = (unsigned)__cvta_generic_to_shared(gsm);                   \
  unsigned sB = sA + NSTG * AT * 2;                                        \
  int tid = threadIdx.x;                                                   \
  int m0 = blockIdx.y * 128;                                               \
  int n0 = blockIdx.x * 128;                                               \
  int wid = tid >> 5;                                                      \
  int lane = tid & 31;                                                     \
  int warp_m = (wid & 3) * 32;                                             \
  int warp_n = (wid >> 2) * 64;                                            \
  int grp = lane >> 2;                                                     \
  int thr = lane & 3;                                                      \
  int lrow = lane & 15;                                                    \
  int lcol = (lane >> 4) * 8;                                              \
  unsigned aAddr = sA + ((warp_m + lrow) * GSTR + lcol) * 2;               \
  unsigned bAddr = sB + ((warp_n + lrow) * GSTR + lcol) * 2;               \
  float acc[2][8][4];                                                      \
  _Pragma("unroll") for (int i = 0; i < 2; i++)                            \
  _Pragma("unroll") for (int j = 0; j < 8; j++)                            \
  _Pragma("unroll") for (int r = 0; r < 4; r++) acc[i][j][r] = 0.f;

#define GLOAD(k0, buf)                                                     \
  {                                                                        \
    _Pragma("unroll") for (int s = 0; s < 4; s++) {                        \
      int idx = tid + s * 256;                                             \
      int r = idx >> 3, ch = (idx & 7) * 8;                                \
      cpa16(sA + ((buf)*AT + r * GSTR + ch) * 2,                           \
            Ap + (size_t)r * D_MODEL + (k0) + ch);                         \
      cpa16(sB + ((buf)*AT + r * GSTR + ch) * 2,                           \
            Wp + (size_t)r * D_MODEL + (k0) + ch);                         \
    }                                                                      \
    cpcommit();                                                            \
  }

#define GEMM_MAIN()                                                        \
  GLOAD(0, 0);                                                             \
  GLOAD(64, 1);                                                            \
  for (int t = 0; t < D_MODEL / 64; t++) {                                 \
    int cur = t % NSTG;                                                    \
    cpwait1();                                                             \
    __syncthreads();                                                       \
    if (t + 2 < D_MODEL / 64) GLOAD((t + 2) * 64, (t + 2) % NSTG);         \
    unsigned aB = aAddr + cur * AT * 2;                                    \
    unsigned bB = bAddr + cur * AT * 2;                                    \
    _Pragma("unroll") for (int kk = 0; kk < 64; kk += 16) {                \
      unsigned af[2][4], bf[8][2];                                         \
      _Pragma("unroll") for (int mt = 0; mt < 2; mt++)                     \
        LDSM4(af[mt][0], af[mt][1], af[mt][2], af[mt][3],                  \
              aB + (mt * 16 * GSTR + kk) * 2);                             \
      _Pragma("unroll") for (int ntp = 0; ntp < 4; ntp++) {                \
        unsigned b0, b1, b2, b3;                                           \
        LDSM4(b0, b1, b2, b3, bB + (ntp * 16 * GSTR + kk) * 2);            \
        bf[2 * ntp][0] = b0;                                               \
        bf[2 * ntp][1] = b2;                                               \
        bf[2 * ntp + 1][0] = b1;                                           \
        bf[2 * ntp + 1][1] = b3;                                           \
      }                                                                    \
      _Pragma("unroll") for (int mt = 0; mt < 2; mt++)                     \
      _Pragma("unroll") for (int nt = 0; nt < 8; nt++)                     \
        MMA16(acc[mt][nt], af[mt], bf[nt]);                                \
    }                                                                      \
  }

__global__ __launch_bounds__(256, 2) void gemm_qkv_kernel(
    const __half* __restrict__ X, const __half* __restrict__ Wb) {
  int z = blockIdx.z;
  const __half* Ap = X + (size_t)z * M_TOT * D_MODEL + (size_t)blockIdx.y * 128 * D_MODEL;
  const __half* Wp = Wb + (size_t)z * D_MODEL * D_MODEL + (size_t)blockIdx.x * 128 * D_MODEL;
  GEMM_PRE();
  GEMM_MAIN();
  __half* C = (z == 0) ? g_Qh : (z == 1) ? g_Kh : g_Vh;
  float s = (z == 0) ? QSCALE : 1.0f;
#pragma unroll
  for (int mt = 0; mt < 2; mt++) {
#pragma unroll
    for (int nt = 0; nt < 8; nt++) {
      int row = m0 + warp_m + mt * 16 + grp;
      int p = n0 + warp_n + nt * 8 + thr * 2;
      int h = p >> 6, d = p & 63;
      float* c = acc[mt][nt];
#pragma unroll
      for (int e = 0; e < 2; e++) {
        int r = row + e * 8;
        int b = r >> 11;
        int ii = r & (L_SEQ - 1);
        *(unsigned*)&C[((((size_t)b * NH + h) * L_SEQ) + ii) * DK + d] =
            pack2(c[2 * e] * s, c[2 * e + 1] * s);
      }
    }
  }
}

__global__ __launch_bounds__(256, 2) void gemm_out_kernel(
    const __half* __restrict__ A, const __half* __restrict__ W,
    float* __restrict__ C) {
  const __half* Ap = A + (size_t)blockIdx.y * 128 * D_MODEL;
  const __half* Wp = W + (size_t)blockIdx.x * 128 * D_MODEL;
  GEMM_PRE();
  GEMM_MAIN();
#pragma unroll
  for (int mt = 0; mt < 2; mt++) {
#pragma unroll
    for (int nt = 0; nt < 8; nt++) {
      int row = m0 + warp_m + mt * 16 + grp;
      int col = n0 + warp_n + nt * 8 + thr * 2;
      float* c = acc[mt][nt];
      *(float2*)&C[(size_t)row * D_MODEL + col] = make_float2(c[0], c[1]);
      *(float2*)&C[(size_t)(row + 8) * D_MODEL + col] = make_float2(c[2], c[3]);
    }
  }
}

// ---------------------------------------------------------------------------
// FP16 flash attention (unchanged).
// ---------------------------------------------------------------------------
#define PSTR 72
#define KVSZ (64 * PSTR)
__global__ __launch_bounds__(256, 2) void attn_mma_kernel(
    const __half* __restrict__ Qh, const __half* __restrict__ Kh,
    const __half* __restrict__ Vh, const unsigned* __restrict__ mbits,
    __half* __restrict__ Mha) {
  extern __shared__ __half smh[];
  __half* Ps = smh + 6 * KVSZ;
  unsigned sbase = (unsigned)__cvta_generic_to_shared(smh);

  int tid = threadIdx.x;
  int w = tid >> 5;
  int lane = tid & 31;
  int grp = lane >> 2;
  int thr = lane & 3;
  int lrow = lane & 15;
  int lcol = (lane >> 4) * 8;
  int i0 = blockIdx.x * 128;
  int h = blockIdx.y;
  int b = blockIdx.z;
  int bh = b * NH + h;
  const __half* Qb = Qh + (size_t)bh * L_SEQ * DK;
  const __half* Kb = Kh + (size_t)bh * L_SEQ * DK;
  const __half* Vb = Vh + (size_t)bh * L_SEQ * DK;

#define KV_ISSUE(o0, buf)                                                  \
  {                                                                        \
    unsigned kbb = sbase + (buf)*2 * KVSZ * 2;                             \
    unsigned vbb = kbb + KVSZ * 2;                                         \
    _Pragma("unroll") for (int s = 0; s < 2; s++) {                        \
      int idx = tid + s * 256;                                             \
      int r = idx >> 3, ch = (idx & 7) * 8;                                \
      cpa16(kbb + (r * PSTR + ch) * 2, Kb + (size_t)((o0) + r) * DK + ch); \
      cpa16(vbb + (r * PSTR + ch) * 2, Vb + (size_t)((o0) + r) * DK + ch); \
    }                                                                      \
    cpcommit();                                                            \
  }

  KV_ISSUE(0, 0);
  KV_ISSUE(64, 1);

#pragma unroll
  for (int it = 0; it < 4; it++) {
    int idx = tid + it * 256;
    int r = idx >> 3, ch = (idx & 7) * 8;
    *(uint4*)&Ps[r * PSTR + ch] = *(const uint4*)&Qb[(size_t)(i0 + r) * DK + ch];
  }
  __syncthreads();

  int rbase = w * 16;
  unsigned Qf[4][4];
#pragma unroll
  for (int kg = 0; kg < 4; kg++) {
    Qf[kg][0] = *(const unsigned*)&Ps[(rbase + grp) * PSTR + kg * 16 + 2 * thr];
    Qf[kg][1] = *(const unsigned*)&Ps[(rbase + grp + 8) * PSTR + kg * 16 + 2 * thr];
    Qf[kg][2] = *(const unsigned*)&Ps[(rbase + grp) * PSTR + kg * 16 + 2 * thr + 8];
    Qf[kg][3] = *(const unsigned*)&Ps[(rbase + grp + 8) * PSTR + kg * 16 + 2 * thr + 8];
  }

  int rA = i0 + rbase + grp;
  int rB = rA + 8;
  const unsigned long long* mbA =
      (const unsigned long long*)mbits + (size_t)(b * L_SEQ + rA) * (L_SEQ / 64);
  const unsigned long long* mbB =
      (const unsigned long long*)mbits + (size_t)(b * L_SEQ + rB) * (L_SEQ / 64);

  float mA = -CUDART_INF_F, mB = -CUDART_INF_F;
  float lA = 0.f, lB = 0.f;
  float oa[8][4];
#pragma unroll
  for (int nt = 0; nt < 8; nt++)
#pragma unroll
    for (int e = 0; e < 4; e++) oa[nt][e] = 0.f;

  const int NT = L_SEQ / 64;
  for (int ot = 0; ot < NT; ot++) {
    int cur = ot % 3;
    unsigned long long mWa = mbA[ot];
    unsigned long long mWb = mbB[ot];
    cpwait1();
    __syncthreads();
    if (ot + 2 < NT) KV_ISSUE((ot + 2) * 64, (ot + 2) % 3);
    unsigned kAddr = sbase + cur * 2 * KVSZ * 2 + (lrow * PSTR + lcol) * 2;
    unsigned vAddr = kAddr + KVSZ * 2;

    float sa[8][4];
#pragma unroll
    for (int nt = 0; nt < 8; nt++)
      sa[nt][0] = sa[nt][1] = sa[nt][2] = sa[nt][3] = 0.f;
#pragma unroll
    for (int ntp = 0; ntp < 4; ntp++) {
#pragma unroll
      for (int kg = 0; kg < 4; kg++) {
        unsigned b0, b1, b2, b3;
        LDSM4(b0, b1, b2, b3, kAddr + (ntp * 16 * PSTR + kg * 16) * 2);
        unsigned bfA[2] = {b0, b2}, bfB[2] = {b1, b3};
        MMA16(sa[2 * ntp], Qf[kg], bfA);
        MMA16(sa[2 * ntp + 1], Qf[kg], bfB);
      }
    }

    float mxA = -CUDART_INF_F, mxB = -CUDART_INF_F;
#pragma unroll
    for (int nt = 0; nt < 8; nt++) {
      int c0 = nt * 8 + 2 * thr;
      if ((mWa >> c0) & 1ull) sa[nt][0] = NEGL2;
      if ((mWa >> (c0 + 1)) & 1ull) sa[nt][1] = NEGL2;
      if ((mWb >> c0) & 1ull) sa[nt][2] = NEGL2;
      if ((mWb >> (c0 + 1)) & 1ull) sa[nt][3] = NEGL2;
      mxA = fmaxf(mxA, fmaxf(sa[nt][0], sa[nt][1]));
      mxB = fmaxf(mxB, fmaxf(sa[nt][2], sa[nt][3]));
    }
    mxA = fmaxf(mxA, __shfl_xor_sync(0xffffffffu, mxA, 1));
    mxA = fmaxf(mxA, __shfl_xor_sync(0xffffffffu, mxA, 2));
    mxB = fmaxf(mxB, __shfl_xor_sync(0xffffffffu, mxB, 1));
    mxB = fmaxf(mxB, __shfl_xor_sync(0xffffffffu, mxB, 2));

    float nmA = fmaxf(mA, mxA), nmB = fmaxf(mB, mxB);
    float cA = ex2f(mA - nmA), cB = ex2f(mB - nmB);
    float sumA = 0.f, sumB = 0.f;
    unsigned pf[4][4];
#pragma unroll
    for (int nt = 0; nt < 8; nt++) {
      float p0 = ex2f(sa[nt][0] - nmA);
      float p1 = ex2f(sa[nt][1] - nmA);
      float p2 = ex2f(sa[nt][2] - nmB);
      float p3 = ex2f(sa[nt][3] - nmB);
      sumA += p0 + p1;
      sumB += p2 + p3;
      int kg = nt >> 1;
      if ((nt & 1) == 0) {
        pf[kg][0] = pack2(p0, p1);
        pf[kg][1] = pack2(p2, p3);
      } else {
        pf[kg][2] = pack2(p0, p1);
        pf[kg][3] = pack2(p2, p3);
      }
    }
    sumA += __shfl_xor_sync(0xffffffffu, sumA, 1);
    sumA += __shfl_xor_sync(0xffffffffu, sumA, 2);
    sumB += __shfl_xor_sync(0xffffffffu, sumB, 1);
    sumB += __shfl_xor_sync(0xffffffffu, sumB, 2);
    lA = lA * cA + sumA;
    lB = lB * cB + sumB;
    mA = nmA;
    mB = nmB;

#pragma unroll
    for (int nt = 0; nt < 8; nt++) {
      oa[nt][0] *= cA;
      oa[nt][1] *= cA;
      oa[nt][2] *= cB;
      oa[nt][3] *= cB;
    }

#pragma unroll
    for (int ntp = 0; ntp < 4; ntp++) {
#pragma unroll
      for (int kg = 0; kg < 4; kg++) {
        unsigned b0, b1, b2, b3;
        LDSM4T(b0, b1, b2, b3, vAddr + (kg * 16 * PSTR + ntp * 16) * 2);
        unsigned bfA[2] = {b0, b1}, bfB[2] = {b2, b3};
        MMA16(oa[2 * ntp], pf[kg], bfA);
        MMA16(oa[2 * ntp + 1], pf[kg], bfB);
      }
    }
  }

  float iA = 1.f / lA, iB = 1.f / lB;
  __half* outA = &Mha[(size_t)(b * L_SEQ + rA) * D_MODEL + h * 64];
  __half* outB = &Mha[(size_t)(b * L_SEQ + rB) * D_MODEL + h * 64];
#pragma unroll
  for (int nt = 0; nt < 8; nt++) {
    int d0 = nt * 8 + 2 * thr;
    *(unsigned*)&outA[d0] = pack2(oa[nt][0] * iA, oa[nt][1] * iA);
    *(unsigned*)&outB[d0] = pack2(oa[nt][2] * iB, oa[nt][3] * iB);
  }
}

// ---------------------------------------------------------------------------
extern "C" void kernel_launch(void* const* d_in, const int* in_sizes, int n_in,
                              void* d_out, int out_size) {
  const int* mask4 = (const int*)d_in[3];
  float* out = (float*)d_out;

  __half *Qh, *Kh, *Vh, *Mh, *X16, *W16;
  unsigned* Mb;
  cudaGetSymbolAddress((void**)&Qh, g_Qh);
  cudaGetSymbolAddress((void**)&Kh, g_Kh);
  cudaGetSymbolAddress((void**)&Vh, g_Vh);
  cudaGetSymbolAddress((void**)&Mh, g_Mha);
  cudaGetSymbolAddress((void**)&Mb, g_mbits);
  cudaGetSymbolAddress((void**)&X16, g_x16);
  cudaGetSymbolAddress((void**)&W16, g_w16);

  prologue_kernel<<<17408, 256>>>(
      mask4, (const float4*)d_in[0], (const float4*)d_in[1],
      (const float4*)d_in[2], (const float4*)d_in[4], (const float4*)d_in[5],
      (const float4*)d_in[6], (const float4*)d_in[7]);

  int gsmem = NSTG * 2 * AT * 2;  // 110592 bytes
  cudaFuncSetAttribute(gemm_qkv_kernel, cudaFuncAttributeMaxDynamicSharedMemorySize, gsmem);
  cudaFuncSetAttribute(gemm_out_kernel, cudaFuncAttributeMaxDynamicSharedMemorySize, gsmem);

  dim3 gq(D_MODEL / 128, M_TOT / 128, 3);  // (8, 32, 3)
  gemm_qkv_kernel<<<gq, 256, gsmem>>>(X16, W16);

  int asmem = (6 * KVSZ + 128 * PSTR) * 2;  // 73728
  cudaFuncSetAttribute(attn_mma_kernel,
                       cudaFuncAttributeMaxDynamicSharedMemorySize, asmem);
  dim3 ag(L_SEQ / 128, NH, B_SZ);
  attn_mma_kernel<<<ag, 256, asmem>>>(Qh, Kh, Vh, Mb, Mh);

  dim3 go(D_MODEL / 128, M_TOT / 128);  // (8, 32)
  gemm_out_kernel<<<go, 256, gsmem>>>(Mh, W16 + 3ull * D_MODEL * D_MODEL, out);
}